// round 1
// baseline (speedup 1.0000x reference)
#include <cuda_runtime.h>
#include <cuda_bf16.h>
#include <math.h>

// Problem constants
#define BB 2
#define SS 2048
#define DD 2048
#define HH 16
#define DH 128
#define MM (BB*SS)          // 4096
#define TRIO (3*DD)         // 6144
#define EPS 1e-6f

// Scratch (device globals; no allocation allowed)
__device__ float g_qkv[(size_t)MM * TRIO];   // 100.7 MB: (m, [q|k|v]*H*DH)
__device__ float g_attn[(size_t)MM * DD];    // 33.6 MB: attention output, normed in place

// ---------------------------------------------------------------------------
// SGEMM: C[M,N] = A[M,K] @ W[N,K]^T + bias[N]   (both operands K-major, "NT")
// 128x128 tile, BK=8, 256 threads, 8x8 microtile
// ---------------------------------------------------------------------------
#define GT 128
#define GBK 8

__global__ __launch_bounds__(256) void sgemm_nt_bias(
    const float* __restrict__ A, const float* __restrict__ W,
    const float* __restrict__ bias, float* __restrict__ C,
    int M, int N, int K)
{
    __shared__ float As[GBK][GT];
    __shared__ float Bs[GBK][GT];

    const int bm0 = blockIdx.y * GT;
    const int bn0 = blockIdx.x * GT;
    const int tid = threadIdx.x;
    const int tx = tid & 15;        // 0..15 -> N microtile
    const int ty = tid >> 4;        // 0..15 -> M microtile
    const int lrow = tid >> 1;      // 0..127 load row
    const int lk   = (tid & 1) * 4; // 0 or 4

    const float* Ap = A + (size_t)(bm0 + lrow) * K + lk;
    const float* Wp = W + (size_t)(bn0 + lrow) * K + lk;

    float acc[8][8];
    #pragma unroll
    for (int i = 0; i < 8; i++)
        #pragma unroll
        for (int j = 0; j < 8; j++) acc[i][j] = 0.f;

    for (int k0 = 0; k0 < K; k0 += GBK) {
        float4 a4 = *(const float4*)(Ap + k0);
        float4 b4 = *(const float4*)(Wp + k0);
        As[lk+0][lrow] = a4.x; As[lk+1][lrow] = a4.y;
        As[lk+2][lrow] = a4.z; As[lk+3][lrow] = a4.w;
        Bs[lk+0][lrow] = b4.x; Bs[lk+1][lrow] = b4.y;
        Bs[lk+2][lrow] = b4.z; Bs[lk+3][lrow] = b4.w;
        __syncthreads();
        #pragma unroll
        for (int kk = 0; kk < GBK; kk++) {
            float a[8], b[8];
            #pragma unroll
            for (int i = 0; i < 8; i++) a[i] = As[kk][ty*8 + i];
            #pragma unroll
            for (int j = 0; j < 8; j++) b[j] = Bs[kk][tx*8 + j];
            #pragma unroll
            for (int i = 0; i < 8; i++)
                #pragma unroll
                for (int j = 0; j < 8; j++)
                    acc[i][j] = fmaf(a[i], b[j], acc[i][j]);
        }
        __syncthreads();
    }

    #pragma unroll
    for (int i = 0; i < 8; i++) {
        const size_t r = (size_t)(bm0 + ty*8 + i);
        #pragma unroll
        for (int j = 0; j < 8; j += 4) {
            const int c = bn0 + tx*8 + j;
            float4 o;
            o.x = acc[i][j+0] + bias[c+0];
            o.y = acc[i][j+1] + bias[c+1];
            o.z = acc[i][j+2] + bias[c+2];
            o.w = acc[i][j+3] + bias[c+3];
            *(float4*)(C + r * N + c) = o;
        }
    }
}

// ---------------------------------------------------------------------------
// RoPE + RMSNorm for q and k, in-place in g_qkv. One warp per (m, which, h).
// ---------------------------------------------------------------------------
__global__ __launch_bounds__(256) void rope_rms_qk(
    const float* __restrict__ rp, const float* __restrict__ qk_w)
{
    const int w = blockIdx.x * (blockDim.x >> 5) + (threadIdx.x >> 5);
    const int lane = threadIdx.x & 31;
    const int h = w % HH;
    const int t = w / HH;
    const int which = t & 1;          // 0=q, 1=k
    const int m = t >> 1;             // 0..4095
    const int s = m & (SS - 1);

    float* base = g_qkv + (size_t)m * TRIO + which * DD + h * DH;
    const float* ang = rp + s * (DH/2);

    float r[4];
    float ss = 0.f;
    #pragma unroll
    for (int u = 0; u < 2; u++) {
        const int p = lane + u * 32;
        const float a = ang[p];
        const float c = cosf(a), sn = sinf(a);
        const float x0 = base[2*p], x1 = base[2*p+1];
        const float r0 = x0 * c - x1 * sn;
        const float r1 = x0 * sn + x1 * c;
        r[2*u] = r0; r[2*u+1] = r1;
        ss += r0*r0 + r1*r1;
    }
    #pragma unroll
    for (int o = 16; o > 0; o >>= 1) ss += __shfl_xor_sync(0xffffffffu, ss, o);
    const float inv = rsqrtf(ss * (1.0f / DH) + EPS);
    #pragma unroll
    for (int u = 0; u < 2; u++) {
        const int p = lane + u * 32;
        base[2*p]   = r[2*u]   * inv * qk_w[2*p];
        base[2*p+1] = r[2*u+1] * inv * qk_w[2*p+1];
    }
}

// ---------------------------------------------------------------------------
// Causal flash attention (fp32). Tile 64(q) x 64(k), 256 threads.
// Smem: Qs[d][i] 32KB, Ks[d][j] 32KB, Vs[j][d] 32KB, Ps[i][j] 16.6KB
// ---------------------------------------------------------------------------
#define FBM 64
#define FBN 64
#define PSTR 65

__global__ __launch_bounds__(256) void flash_attn_causal()
{
    extern __shared__ float sm[];
    float* Qs = sm;                 // [128][64]
    float* Ks = sm + 128*64;        // [128][64]
    float* Vs = sm + 2*128*64;      // [64][128]
    float* Ps = sm + 3*128*64;      // [64][65]

    const int qm0 = blockIdx.x * FBM;
    const int h = blockIdx.y, b = blockIdx.z;
    const int tid = threadIdx.x;
    const int tx = tid & 15;        // cols
    const int ty = tid >> 4;        // rows

    const size_t headoff = (size_t)h * DH;

    // ---- load Q tile transposed: Qs[d][i] ----
    #pragma unroll
    for (int rep = 0; rep < 8; rep++) {
        const int idx = rep * 256 + tid;
        const int i = idx & 63;
        const int d = (idx >> 6) * 4;
        const float4 q4 = *(const float4*)(g_qkv +
            (size_t)(b*SS + qm0 + i) * TRIO + headoff + d);
        Qs[(d+0)*FBM + i] = q4.x; Qs[(d+1)*FBM + i] = q4.y;
        Qs[(d+2)*FBM + i] = q4.z; Qs[(d+3)*FBM + i] = q4.w;
    }

    float m_i[4], l_i[4], O[4][8];
    #pragma unroll
    for (int i = 0; i < 4; i++) {
        m_i[i] = -1e30f; l_i[i] = 0.f;
        #pragma unroll
        for (int u = 0; u < 8; u++) O[i][u] = 0.f;
    }

    const float scale = 0.08838834764831845f; // 1/sqrt(128)

    for (int kt = 0; kt <= (int)blockIdx.x; kt++) {
        const int kn0 = kt * FBN;
        __syncthreads();  // previous iteration done reading Ks/Vs/Ps
        // ---- load K tile transposed, V tile ----
        #pragma unroll
        for (int rep = 0; rep < 8; rep++) {
            const int idx = rep * 256 + tid;
            const int i = idx & 63;
            const int d = (idx >> 6) * 4;
            const float4 k4 = *(const float4*)(g_qkv +
                (size_t)(b*SS + kn0 + i) * TRIO + DD + headoff + d);
            Ks[(d+0)*FBN + i] = k4.x; Ks[(d+1)*FBN + i] = k4.y;
            Ks[(d+2)*FBN + i] = k4.z; Ks[(d+3)*FBN + i] = k4.w;
            const int j = idx >> 5;
            const int d2 = (idx & 31) * 4;
            const float4 v4 = *(const float4*)(g_qkv +
                (size_t)(b*SS + kn0 + j) * TRIO + 2*DD + headoff + d2);
            *(float4*)(Vs + j*DH + d2) = v4;
        }
        __syncthreads();

        // ---- S = Q K^T ----
        float sacc[4][4];
        #pragma unroll
        for (int i = 0; i < 4; i++)
            #pragma unroll
            for (int j = 0; j < 4; j++) sacc[i][j] = 0.f;

        #pragma unroll 8
        for (int d = 0; d < DH; d++) {
            const float4 q4 = *(const float4*)(Qs + d*FBM + ty*4);
            const float4 k4 = *(const float4*)(Ks + d*FBN + tx*4);
            const float qv[4] = {q4.x, q4.y, q4.z, q4.w};
            const float kv[4] = {k4.x, k4.y, k4.z, k4.w};
            #pragma unroll
            for (int i = 0; i < 4; i++)
                #pragma unroll
                for (int j = 0; j < 4; j++)
                    sacc[i][j] = fmaf(qv[i], kv[j], sacc[i][j]);
        }

        const bool need_mask = (kt == (int)blockIdx.x);
        #pragma unroll
        for (int i = 0; i < 4; i++)
            #pragma unroll
            for (int j = 0; j < 4; j++) {
                float sv = sacc[i][j] * scale;
                if (need_mask && (kn0 + tx*4 + j > qm0 + ty*4 + i)) sv = -1e30f;
                sacc[i][j] = sv;
            }

        // ---- online softmax ----
        float alpha[4];
        #pragma unroll
        for (int i = 0; i < 4; i++) {
            float rmax = fmaxf(fmaxf(sacc[i][0], sacc[i][1]),
                               fmaxf(sacc[i][2], sacc[i][3]));
            #pragma unroll
            for (int o = 8; o > 0; o >>= 1)
                rmax = fmaxf(rmax, __shfl_xor_sync(0xffffffffu, rmax, o));
            const float mnew = fmaxf(m_i[i], rmax);
            alpha[i] = expf(m_i[i] - mnew);
            float rsum = 0.f;
            #pragma unroll
            for (int j = 0; j < 4; j++) {
                const float p = expf(sacc[i][j] - mnew);
                sacc[i][j] = p;
                rsum += p;
            }
            #pragma unroll
            for (int o = 8; o > 0; o >>= 1)
                rsum += __shfl_xor_sync(0xffffffffu, rsum, o);
            l_i[i] = l_i[i] * alpha[i] + rsum;
            m_i[i] = mnew;
            #pragma unroll
            for (int u = 0; u < 8; u++) O[i][u] *= alpha[i];
            #pragma unroll
            for (int j = 0; j < 4; j++)
                Ps[(ty*4 + i) * PSTR + tx*4 + j] = sacc[i][j];
        }
        __syncthreads();

        // ---- O += P V ----
        #pragma unroll 4
        for (int j = 0; j < FBN; j++) {
            const float4 v0 = *(const float4*)(Vs + j*DH + tx*8);
            const float4 v1 = *(const float4*)(Vs + j*DH + tx*8 + 4);
            const float vv[8] = {v0.x, v0.y, v0.z, v0.w, v1.x, v1.y, v1.z, v1.w};
            #pragma unroll
            for (int i = 0; i < 4; i++) {
                const float p = Ps[(ty*4 + i) * PSTR + j];
                #pragma unroll
                for (int u = 0; u < 8; u++)
                    O[i][u] = fmaf(p, vv[u], O[i][u]);
            }
        }
    }

    // ---- epilogue: O /= l, write (b, s, h*DH + d) ----
    #pragma unroll
    for (int i = 0; i < 4; i++) {
        const float inv = 1.0f / l_i[i];
        float* dst = g_attn + (size_t)(b*SS + qm0 + ty*4 + i) * DD + headoff + tx*8;
        float4 o0, o1;
        o0.x = O[i][0]*inv; o0.y = O[i][1]*inv; o0.z = O[i][2]*inv; o0.w = O[i][3]*inv;
        o1.x = O[i][4]*inv; o1.y = O[i][5]*inv; o1.z = O[i][6]*inv; o1.w = O[i][7]*inv;
        *(float4*)dst = o0;
        *(float4*)(dst + 4) = o1;
    }
}

// ---------------------------------------------------------------------------
// RMSNorm over D=2048, in place. One 256-thread block per row.
// ---------------------------------------------------------------------------
__global__ __launch_bounds__(256) void rmsnorm_rows(const float* __restrict__ w)
{
    __shared__ float red[8];
    __shared__ float s_inv;
    float* p = g_attn + (size_t)blockIdx.x * DD;
    const int tid = threadIdx.x;

    float v[8];
    float ss = 0.f;
    #pragma unroll
    for (int k = 0; k < 8; k++) {
        const float x = p[tid + k*256];
        v[k] = x;
        ss += x * x;
    }
    #pragma unroll
    for (int o = 16; o > 0; o >>= 1) ss += __shfl_xor_sync(0xffffffffu, ss, o);
    if ((tid & 31) == 0) red[tid >> 5] = ss;
    __syncthreads();
    if (tid == 0) {
        float t = 0.f;
        #pragma unroll
        for (int i = 0; i < 8; i++) t += red[i];
        s_inv = rsqrtf(t * (1.0f / DD) + EPS);
    }
    __syncthreads();
    const float inv = s_inv;
    #pragma unroll
    for (int k = 0; k < 8; k++) {
        const int idx = tid + k*256;
        p[idx] = v[k] * inv * w[idx];
    }
}

// ---------------------------------------------------------------------------
extern "C" void kernel_launch(void* const* d_in, const int* in_sizes, int n_in,
                              void* d_out, int out_size)
{
    const float* x     = (const float*)d_in[0];
    const float* rp    = (const float*)d_in[1];
    const float* Win   = (const float*)d_in[2];
    const float* b_in  = (const float*)d_in[3];
    const float* Wout  = (const float*)d_in[4];
    const float* b_out = (const float*)d_in[5];
    const float* qk_w  = (const float*)d_in[6];
    const float* out_w = (const float*)d_in[7];
    float* out = (float*)d_out;

    float* qkv;  cudaGetSymbolAddress((void**)&qkv,  g_qkv);
    float* attn; cudaGetSymbolAddress((void**)&attn, g_attn);

    // 1) qkv = x @ Win^T + b_in     [4096, 6144]
    {
        dim3 grid(TRIO / GT, MM / GT);
        sgemm_nt_bias<<<grid, 256>>>(x, Win, b_in, qkv, MM, TRIO, DD);
    }
    // 2) RoPE + RMS on q,k (in place)
    {
        const int warps = MM * HH * 2;       // 131072
        rope_rms_qk<<<warps / 8, 256>>>(rp, qk_w);
    }
    // 3) causal flash attention -> g_attn
    {
        const int smem = (3 * 128 * 64 + 64 * PSTR) * (int)sizeof(float); // 114944 B
        cudaFuncSetAttribute(flash_attn_causal,
                             cudaFuncAttributeMaxDynamicSharedMemorySize, smem);
        dim3 grid(SS / FBM, HH, BB);
        flash_attn_causal<<<grid, 256, smem>>>();
    }
    // 4) RMSNorm over D (in place)
    rmsnorm_rows<<<MM, 256>>>(out_w);
    // 5) out = attn @ Wout^T + b_out
    {
        dim3 grid(DD / GT, MM / GT);
        sgemm_nt_bias<<<grid, 256>>>(attn, Wout, b_out, out, MM, DD, DD);
    }
}

// round 2
// speedup vs baseline: 1.7963x; 1.7963x over previous
#include <cuda_runtime.h>
#include <cuda_bf16.h>
#include <math.h>
#include <stdint.h>

// Problem constants
#define BB 2
#define SS 2048
#define DD 2048
#define HH 16
#define DH 128
#define MM (BB*SS)          // 4096
#define TRIO (3*DD)         // 6144
#define EPS 1e-6f

// Scratch (device globals; no allocation allowed)
__device__ float g_qkv[(size_t)MM * TRIO];   // 100.7 MB
__device__ float g_attn[(size_t)MM * DD];    // 33.6 MB

// ---------------------------------------------------------------------------
// TF32 tensor-core GEMM: C[M,N] = A[M,K] @ W[N,K]^T + bias[N]
// Both operands K-major ("NT"). 128x128x32 tile, 256 threads, double-buffered
// cp.async, mma.sync.m16n8k8.tf32. Warp tile 64x32 (4x4 mma frags).
// ---------------------------------------------------------------------------
#define TBM 128
#define TBN 128
#define TBK 32
#define TSTR 36   // smem row stride (floats): 36 ≡ 4 mod 32 -> conflict-free frag loads
#define TBUF (TBM*TSTR)

__device__ __forceinline__ uint32_t f2tf32(float f) {
    uint32_t r;
    asm("cvt.rna.tf32.f32 %0, %1;" : "=r"(r) : "f"(f));
    return r;
}
__device__ __forceinline__ void cpasync16(float* s, const float* g) {
    uint32_t sa = (uint32_t)__cvta_generic_to_shared(s);
    asm volatile("cp.async.cg.shared.global [%0], [%1], 16;" :: "r"(sa), "l"(g));
}
__device__ __forceinline__ void mma_tf32(float c[4], const uint32_t a[4], const uint32_t b[2]) {
    asm volatile(
        "mma.sync.aligned.m16n8k8.row.col.f32.tf32.tf32.f32 "
        "{%0,%1,%2,%3}, {%4,%5,%6,%7}, {%8,%9}, {%0,%1,%2,%3};"
        : "+f"(c[0]), "+f"(c[1]), "+f"(c[2]), "+f"(c[3])
        : "r"(a[0]), "r"(a[1]), "r"(a[2]), "r"(a[3]), "r"(b[0]), "r"(b[1]));
}

__global__ __launch_bounds__(256) void tf32_gemm_nt_bias(
    const float* __restrict__ A, const float* __restrict__ W,
    const float* __restrict__ bias, float* __restrict__ C,
    int M, int N, int K)
{
    extern __shared__ float smem[];
    float* As = smem;             // [2][TBUF]
    float* Bs = smem + 2*TBUF;    // [2][TBUF]

    const int tid = threadIdx.x;
    const int bm0 = blockIdx.y * TBM;
    const int bn0 = blockIdx.x * TBN;

    const int warp = tid >> 5, lane = tid & 31;
    const int wm0 = (warp >> 2) * 64;   // 0,64
    const int wn0 = (warp & 3) * 32;    // 0,32,64,96
    const int qr = lane >> 2;           // 0..7
    const int qc = lane & 3;            // 0..3

    // Load mapping: each thread cp.asyncs 4 float4 per matrix per tile.
    const int lrow = tid >> 1;          // 0..127
    const int lc0  = (tid & 1) * 16;    // float col within row: 0 or 16
    const float* Ag = A + (size_t)(bm0 + lrow) * K + lc0;
    const float* Wg = W + (size_t)(bn0 + lrow) * K + lc0;
    float* AsW = As + lrow * TSTR + lc0;
    float* BsW = Bs + lrow * TSTR + lc0;

    float acc[4][4][4];
    #pragma unroll
    for (int i = 0; i < 4; i++)
        #pragma unroll
        for (int j = 0; j < 4; j++)
            #pragma unroll
            for (int u = 0; u < 4; u++) acc[i][j][u] = 0.f;

    const int nk = K / TBK;

    // prologue: prefetch tile 0 into buffer 0
    #pragma unroll
    for (int j = 0; j < 4; j++) {
        cpasync16(AsW + j*4, Ag + j*4);
        cpasync16(BsW + j*4, Wg + j*4);
    }
    asm volatile("cp.async.commit_group;\n");

    for (int kt = 0; kt < nk; kt++) {
        if (kt + 1 < nk) {
            const int nb = (kt + 1) & 1;
            const int ko = (kt + 1) * TBK;
            #pragma unroll
            for (int j = 0; j < 4; j++) {
                cpasync16(AsW + nb*TBUF + j*4, Ag + ko + j*4);
                cpasync16(BsW + nb*TBUF + j*4, Wg + ko + j*4);
            }
            asm volatile("cp.async.commit_group;\n");
            asm volatile("cp.async.wait_group 1;\n");
        } else {
            asm volatile("cp.async.wait_group 0;\n");
        }
        __syncthreads();

        const float* Ab = As + (kt & 1) * TBUF;
        const float* Bb = Bs + (kt & 1) * TBUF;

        #pragma unroll
        for (int kk = 0; kk < 4; kk++) {
            const int k = kk * 8;
            uint32_t af[4][4], bf[4][2];
            #pragma unroll
            for (int im = 0; im < 4; im++) {
                const float* p = Ab + (wm0 + im*16 + qr) * TSTR + k + qc;
                af[im][0] = f2tf32(p[0]);
                af[im][1] = f2tf32(p[8*TSTR]);
                af[im][2] = f2tf32(p[4]);
                af[im][3] = f2tf32(p[8*TSTR + 4]);
            }
            #pragma unroll
            for (int in = 0; in < 4; in++) {
                const float* p = Bb + (wn0 + in*8 + qr) * TSTR + k + qc;
                bf[in][0] = f2tf32(p[0]);
                bf[in][1] = f2tf32(p[4]);
            }
            #pragma unroll
            for (int im = 0; im < 4; im++)
                #pragma unroll
                for (int in = 0; in < 4; in++)
                    mma_tf32(acc[im][in], af[im], bf[in]);
        }
        __syncthreads();
    }

    // epilogue: C = acc + bias
    #pragma unroll
    for (int im = 0; im < 4; im++) {
        #pragma unroll
        for (int in = 0; in < 4; in++) {
            const int r0 = bm0 + wm0 + im*16 + qr;
            const int c0 = bn0 + wn0 + in*8 + qc*2;
            const float2 b2 = *(const float2*)(bias + c0);
            float2 v;
            v.x = acc[im][in][0] + b2.x; v.y = acc[im][in][1] + b2.y;
            *(float2*)(C + (size_t)r0 * N + c0) = v;
            v.x = acc[im][in][2] + b2.x; v.y = acc[im][in][3] + b2.y;
            *(float2*)(C + (size_t)(r0 + 8) * N + c0) = v;
        }
    }
}

// ---------------------------------------------------------------------------
// RoPE + RMSNorm for q and k, in-place in g_qkv. One warp per (m, which, h).
// ---------------------------------------------------------------------------
__global__ __launch_bounds__(256) void rope_rms_qk(
    const float* __restrict__ rp, const float* __restrict__ qk_w)
{
    const int w = blockIdx.x * (blockDim.x >> 5) + (threadIdx.x >> 5);
    const int lane = threadIdx.x & 31;
    const int h = w % HH;
    const int t = w / HH;
    const int which = t & 1;          // 0=q, 1=k
    const int m = t >> 1;             // 0..4095
    const int s = m & (SS - 1);

    float* base = g_qkv + (size_t)m * TRIO + which * DD + h * DH;
    const float* ang = rp + s * (DH/2);

    float r[4];
    float ss = 0.f;
    #pragma unroll
    for (int u = 0; u < 2; u++) {
        const int p = lane + u * 32;
        const float a = ang[p];
        const float c = cosf(a), sn = sinf(a);
        const float x0 = base[2*p], x1 = base[2*p+1];
        const float r0 = x0 * c - x1 * sn;
        const float r1 = x0 * sn + x1 * c;
        r[2*u] = r0; r[2*u+1] = r1;
        ss += r0*r0 + r1*r1;
    }
    #pragma unroll
    for (int o = 16; o > 0; o >>= 1) ss += __shfl_xor_sync(0xffffffffu, ss, o);
    const float inv = rsqrtf(ss * (1.0f / DH) + EPS);
    #pragma unroll
    for (int u = 0; u < 2; u++) {
        const int p = lane + u * 32;
        base[2*p]   = r[2*u]   * inv * qk_w[2*p];
        base[2*p+1] = r[2*u+1] * inv * qk_w[2*p+1];
    }
}

// ---------------------------------------------------------------------------
// Causal flash attention (fp32). Tile 64(q) x 64(k), 256 threads.
// ---------------------------------------------------------------------------
#define FBM 64
#define FBN 64
#define PSTR 65

__global__ __launch_bounds__(256) void flash_attn_causal()
{
    extern __shared__ float sm[];
    float* Qs = sm;                 // [128][64]
    float* Ks = sm + 128*64;        // [128][64]
    float* Vs = sm + 2*128*64;      // [64][128]
    float* Ps = sm + 3*128*64;      // [64][65]

    const int qm0 = blockIdx.x * FBM;
    const int h = blockIdx.y, b = blockIdx.z;
    const int tid = threadIdx.x;
    const int tx = tid & 15;        // cols
    const int ty = tid >> 4;        // rows

    const size_t headoff = (size_t)h * DH;

    #pragma unroll
    for (int rep = 0; rep < 8; rep++) {
        const int idx = rep * 256 + tid;
        const int i = idx & 63;
        const int d = (idx >> 6) * 4;
        const float4 q4 = *(const float4*)(g_qkv +
            (size_t)(b*SS + qm0 + i) * TRIO + headoff + d);
        Qs[(d+0)*FBM + i] = q4.x; Qs[(d+1)*FBM + i] = q4.y;
        Qs[(d+2)*FBM + i] = q4.z; Qs[(d+3)*FBM + i] = q4.w;
    }

    float m_i[4], l_i[4], O[4][8];
    #pragma unroll
    for (int i = 0; i < 4; i++) {
        m_i[i] = -1e30f; l_i[i] = 0.f;
        #pragma unroll
        for (int u = 0; u < 8; u++) O[i][u] = 0.f;
    }

    const float scale = 0.08838834764831845f; // 1/sqrt(128)

    for (int kt = 0; kt <= (int)blockIdx.x; kt++) {
        const int kn0 = kt * FBN;
        __syncthreads();
        #pragma unroll
        for (int rep = 0; rep < 8; rep++) {
            const int idx = rep * 256 + tid;
            const int i = idx & 63;
            const int d = (idx >> 6) * 4;
            const float4 k4 = *(const float4*)(g_qkv +
                (size_t)(b*SS + kn0 + i) * TRIO + DD + headoff + d);
            Ks[(d+0)*FBN + i] = k4.x; Ks[(d+1)*FBN + i] = k4.y;
            Ks[(d+2)*FBN + i] = k4.z; Ks[(d+3)*FBN + i] = k4.w;
            const int j = idx >> 5;
            const int d2 = (idx & 31) * 4;
            const float4 v4 = *(const float4*)(g_qkv +
                (size_t)(b*SS + kn0 + j) * TRIO + 2*DD + headoff + d2);
            *(float4*)(Vs + j*DH + d2) = v4;
        }
        __syncthreads();

        float sacc[4][4];
        #pragma unroll
        for (int i = 0; i < 4; i++)
            #pragma unroll
            for (int j = 0; j < 4; j++) sacc[i][j] = 0.f;

        #pragma unroll 8
        for (int d = 0; d < DH; d++) {
            const float4 q4 = *(const float4*)(Qs + d*FBM + ty*4);
            const float4 k4 = *(const float4*)(Ks + d*FBN + tx*4);
            const float qv[4] = {q4.x, q4.y, q4.z, q4.w};
            const float kv[4] = {k4.x, k4.y, k4.z, k4.w};
            #pragma unroll
            for (int i = 0; i < 4; i++)
                #pragma unroll
                for (int j = 0; j < 4; j++)
                    sacc[i][j] = fmaf(qv[i], kv[j], sacc[i][j]);
        }

        const bool need_mask = (kt == (int)blockIdx.x);
        #pragma unroll
        for (int i = 0; i < 4; i++)
            #pragma unroll
            for (int j = 0; j < 4; j++) {
                float sv = sacc[i][j] * scale;
                if (need_mask && (kn0 + tx*4 + j > qm0 + ty*4 + i)) sv = -1e30f;
                sacc[i][j] = sv;
            }

        float alpha[4];
        #pragma unroll
        for (int i = 0; i < 4; i++) {
            float rmax = fmaxf(fmaxf(sacc[i][0], sacc[i][1]),
                               fmaxf(sacc[i][2], sacc[i][3]));
            #pragma unroll
            for (int o = 8; o > 0; o >>= 1)
                rmax = fmaxf(rmax, __shfl_xor_sync(0xffffffffu, rmax, o));
            const float mnew = fmaxf(m_i[i], rmax);
            alpha[i] = expf(m_i[i] - mnew);
            float rsum = 0.f;
            #pragma unroll
            for (int j = 0; j < 4; j++) {
                const float p = expf(sacc[i][j] - mnew);
                sacc[i][j] = p;
                rsum += p;
            }
            #pragma unroll
            for (int o = 8; o > 0; o >>= 1)
                rsum += __shfl_xor_sync(0xffffffffu, rsum, o);
            l_i[i] = l_i[i] * alpha[i] + rsum;
            m_i[i] = mnew;
            #pragma unroll
            for (int u = 0; u < 8; u++) O[i][u] *= alpha[i];
            #pragma unroll
            for (int j = 0; j < 4; j++)
                Ps[(ty*4 + i) * PSTR + tx*4 + j] = sacc[i][j];
        }
        __syncthreads();

        #pragma unroll 4
        for (int j = 0; j < FBN; j++) {
            const float4 v0 = *(const float4*)(Vs + j*DH + tx*8);
            const float4 v1 = *(const float4*)(Vs + j*DH + tx*8 + 4);
            const float vv[8] = {v0.x, v0.y, v0.z, v0.w, v1.x, v1.y, v1.z, v1.w};
            #pragma unroll
            for (int i = 0; i < 4; i++) {
                const float p = Ps[(ty*4 + i) * PSTR + j];
                #pragma unroll
                for (int u = 0; u < 8; u++)
                    O[i][u] = fmaf(p, vv[u], O[i][u]);
            }
        }
    }

    #pragma unroll
    for (int i = 0; i < 4; i++) {
        const float inv = 1.0f / l_i[i];
        float* dst = g_attn + (size_t)(b*SS + qm0 + ty*4 + i) * DD + headoff + tx*8;
        float4 o0, o1;
        o0.x = O[i][0]*inv; o0.y = O[i][1]*inv; o0.z = O[i][2]*inv; o0.w = O[i][3]*inv;
        o1.x = O[i][4]*inv; o1.y = O[i][5]*inv; o1.z = O[i][6]*inv; o1.w = O[i][7]*inv;
        *(float4*)dst = o0;
        *(float4*)(dst + 4) = o1;
    }
}

// ---------------------------------------------------------------------------
// RMSNorm over D=2048, in place. One 256-thread block per row.
// ---------------------------------------------------------------------------
__global__ __launch_bounds__(256) void rmsnorm_rows(const float* __restrict__ w)
{
    __shared__ float red[8];
    __shared__ float s_inv;
    float* p = g_attn + (size_t)blockIdx.x * DD;
    const int tid = threadIdx.x;

    float v[8];
    float ss = 0.f;
    #pragma unroll
    for (int k = 0; k < 8; k++) {
        const float x = p[tid + k*256];
        v[k] = x;
        ss += x * x;
    }
    #pragma unroll
    for (int o = 16; o > 0; o >>= 1) ss += __shfl_xor_sync(0xffffffffu, ss, o);
    if ((tid & 31) == 0) red[tid >> 5] = ss;
    __syncthreads();
    if (tid == 0) {
        float t = 0.f;
        #pragma unroll
        for (int i = 0; i < 8; i++) t += red[i];
        s_inv = rsqrtf(t * (1.0f / DD) + EPS);
    }
    __syncthreads();
    const float inv = s_inv;
    #pragma unroll
    for (int k = 0; k < 8; k++) {
        const int idx = tid + k*256;
        p[idx] = v[k] * inv * w[idx];
    }
}

// ---------------------------------------------------------------------------
extern "C" void kernel_launch(void* const* d_in, const int* in_sizes, int n_in,
                              void* d_out, int out_size)
{
    const float* x     = (const float*)d_in[0];
    const float* rp    = (const float*)d_in[1];
    const float* Win   = (const float*)d_in[2];
    const float* b_in  = (const float*)d_in[3];
    const float* Wout  = (const float*)d_in[4];
    const float* b_out = (const float*)d_in[5];
    const float* qk_w  = (const float*)d_in[6];
    const float* out_w = (const float*)d_in[7];
    float* out = (float*)d_out;

    float* qkv;  cudaGetSymbolAddress((void**)&qkv,  g_qkv);
    float* attn; cudaGetSymbolAddress((void**)&attn, g_attn);

    const int gemm_smem = 4 * TBUF * (int)sizeof(float);  // 73728 B
    cudaFuncSetAttribute(tf32_gemm_nt_bias,
                         cudaFuncAttributeMaxDynamicSharedMemorySize, gemm_smem);

    // 1) qkv = x @ Win^T + b_in     [4096, 6144]
    {
        dim3 grid(TRIO / TBN, MM / TBM);
        tf32_gemm_nt_bias<<<grid, 256, gemm_smem>>>(x, Win, b_in, qkv, MM, TRIO, DD);
    }
    // 2) RoPE + RMS on q,k (in place)
    {
        const int warps = MM * HH * 2;       // 131072
        rope_rms_qk<<<warps / 8, 256>>>(rp, qk_w);
    }
    // 3) causal flash attention -> g_attn
    {
        const int smem = (3 * 128 * 64 + 64 * PSTR) * (int)sizeof(float); // 114944 B
        cudaFuncSetAttribute(flash_attn_causal,
                             cudaFuncAttributeMaxDynamicSharedMemorySize, smem);
        dim3 grid(SS / FBM, HH, BB);
        flash_attn_causal<<<grid, 256, smem>>>();
    }
    // 4) RMSNorm over D (in place)
    rmsnorm_rows<<<MM, 256>>>(out_w);
    // 5) out = attn @ Wout^T + b_out
    {
        dim3 grid(DD / TBN, MM / TBM);
        tf32_gemm_nt_bias<<<grid, 256, gemm_smem>>>(attn, Wout, b_out, out, MM, DD, DD);
    }
}

// round 3
// speedup vs baseline: 2.1762x; 1.2115x over previous
#include <cuda_runtime.h>
#include <cuda_bf16.h>
#include <math.h>
#include <stdint.h>

// Problem constants
#define BB 2
#define SS 2048
#define DD 2048
#define HH 16
#define DH 128
#define MM (BB*SS)          // 4096
#define TRIO (3*DD)         // 6144
#define EPS 1e-6f

// Scratch (device globals; no allocation allowed)
__device__ float g_qkv[(size_t)MM * TRIO];   // 100.7 MB
__device__ float g_attn[(size_t)MM * DD];    // 33.6 MB

// ---------------------------------------------------------------------------
// Common tensor-core helpers
// ---------------------------------------------------------------------------
__device__ __forceinline__ uint32_t f2tf32(float f) {
    uint32_t r;
    asm("cvt.rna.tf32.f32 %0, %1;" : "=r"(r) : "f"(f));
    return r;
}
__device__ __forceinline__ void split_tf32(float x, uint32_t& hi, uint32_t& lo) {
    hi = f2tf32(x);
    lo = f2tf32(x - __uint_as_float(hi));
}
__device__ __forceinline__ void cpasync16(float* s, const float* g) {
    uint32_t sa = (uint32_t)__cvta_generic_to_shared(s);
    asm volatile("cp.async.cg.shared.global [%0], [%1], 16;" :: "r"(sa), "l"(g));
}
__device__ __forceinline__ void mma_tf32(float c[4], const uint32_t a[4], const uint32_t b[2]) {
    asm volatile(
        "mma.sync.aligned.m16n8k8.row.col.f32.tf32.tf32.f32 "
        "{%0,%1,%2,%3}, {%4,%5,%6,%7}, {%8,%9}, {%0,%1,%2,%3};"
        : "+f"(c[0]), "+f"(c[1]), "+f"(c[2]), "+f"(c[3])
        : "r"(a[0]), "r"(a[1]), "r"(a[2]), "r"(a[3]), "r"(b[0]), "r"(b[1]));
}

// ---------------------------------------------------------------------------
// TF32 tensor-core GEMM: C[M,N] = A[M,K] @ W[N,K]^T + bias[N]  (unchanged R2)
// ---------------------------------------------------------------------------
#define TBM 128
#define TBN 128
#define TBK 32
#define TSTR 36
#define TBUF (TBM*TSTR)

__global__ __launch_bounds__(256) void tf32_gemm_nt_bias(
    const float* __restrict__ A, const float* __restrict__ W,
    const float* __restrict__ bias, float* __restrict__ C,
    int M, int N, int K)
{
    extern __shared__ float smem[];
    float* As = smem;
    float* Bs = smem + 2*TBUF;

    const int tid = threadIdx.x;
    const int bm0 = blockIdx.y * TBM;
    const int bn0 = blockIdx.x * TBN;

    const int warp = tid >> 5, lane = tid & 31;
    const int wm0 = (warp >> 2) * 64;
    const int wn0 = (warp & 3) * 32;
    const int qr = lane >> 2;
    const int qc = lane & 3;

    const int lrow = tid >> 1;
    const int lc0  = (tid & 1) * 16;
    const float* Ag = A + (size_t)(bm0 + lrow) * K + lc0;
    const float* Wg = W + (size_t)(bn0 + lrow) * K + lc0;
    float* AsW = As + lrow * TSTR + lc0;
    float* BsW = Bs + lrow * TSTR + lc0;

    float acc[4][4][4];
    #pragma unroll
    for (int i = 0; i < 4; i++)
        #pragma unroll
        for (int j = 0; j < 4; j++)
            #pragma unroll
            for (int u = 0; u < 4; u++) acc[i][j][u] = 0.f;

    const int nk = K / TBK;

    #pragma unroll
    for (int j = 0; j < 4; j++) {
        cpasync16(AsW + j*4, Ag + j*4);
        cpasync16(BsW + j*4, Wg + j*4);
    }
    asm volatile("cp.async.commit_group;\n");

    for (int kt = 0; kt < nk; kt++) {
        if (kt + 1 < nk) {
            const int nb = (kt + 1) & 1;
            const int ko = (kt + 1) * TBK;
            #pragma unroll
            for (int j = 0; j < 4; j++) {
                cpasync16(AsW + nb*TBUF + j*4, Ag + ko + j*4);
                cpasync16(BsW + nb*TBUF + j*4, Wg + ko + j*4);
            }
            asm volatile("cp.async.commit_group;\n");
            asm volatile("cp.async.wait_group 1;\n");
        } else {
            asm volatile("cp.async.wait_group 0;\n");
        }
        __syncthreads();

        const float* Ab = As + (kt & 1) * TBUF;
        const float* Bb = Bs + (kt & 1) * TBUF;

        #pragma unroll
        for (int kk = 0; kk < 4; kk++) {
            const int k = kk * 8;
            uint32_t af[4][4], bf[4][2];
            #pragma unroll
            for (int im = 0; im < 4; im++) {
                const float* p = Ab + (wm0 + im*16 + qr) * TSTR + k + qc;
                af[im][0] = f2tf32(p[0]);
                af[im][1] = f2tf32(p[8*TSTR]);
                af[im][2] = f2tf32(p[4]);
                af[im][3] = f2tf32(p[8*TSTR + 4]);
            }
            #pragma unroll
            for (int in = 0; in < 4; in++) {
                const float* p = Bb + (wn0 + in*8 + qr) * TSTR + k + qc;
                bf[in][0] = f2tf32(p[0]);
                bf[in][1] = f2tf32(p[4]);
            }
            #pragma unroll
            for (int im = 0; im < 4; im++)
                #pragma unroll
                for (int in = 0; in < 4; in++)
                    mma_tf32(acc[im][in], af[im], bf[in]);
        }
        __syncthreads();
    }

    #pragma unroll
    for (int im = 0; im < 4; im++) {
        #pragma unroll
        for (int in = 0; in < 4; in++) {
            const int r0 = bm0 + wm0 + im*16 + qr;
            const int c0 = bn0 + wn0 + in*8 + qc*2;
            const float2 b2 = *(const float2*)(bias + c0);
            float2 v;
            v.x = acc[im][in][0] + b2.x; v.y = acc[im][in][1] + b2.y;
            *(float2*)(C + (size_t)r0 * N + c0) = v;
            v.x = acc[im][in][2] + b2.x; v.y = acc[im][in][3] + b2.y;
            *(float2*)(C + (size_t)(r0 + 8) * N + c0) = v;
        }
    }
}

// ---------------------------------------------------------------------------
// RoPE + RMSNorm for q and k, in-place in g_qkv. One warp per (m, which, h).
// ---------------------------------------------------------------------------
__global__ __launch_bounds__(256) void rope_rms_qk(
    const float* __restrict__ rp, const float* __restrict__ qk_w)
{
    const int w = blockIdx.x * (blockDim.x >> 5) + (threadIdx.x >> 5);
    const int lane = threadIdx.x & 31;
    const int h = w % HH;
    const int t = w / HH;
    const int which = t & 1;
    const int m = t >> 1;
    const int s = m & (SS - 1);

    float* base = g_qkv + (size_t)m * TRIO + which * DD + h * DH;
    const float* ang = rp + s * (DH/2);

    float r[4];
    float ss = 0.f;
    #pragma unroll
    for (int u = 0; u < 2; u++) {
        const int p = lane + u * 32;
        const float a = ang[p];
        const float c = cosf(a), sn = sinf(a);
        const float x0 = base[2*p], x1 = base[2*p+1];
        const float r0 = x0 * c - x1 * sn;
        const float r1 = x0 * sn + x1 * c;
        r[2*u] = r0; r[2*u+1] = r1;
        ss += r0*r0 + r1*r1;
    }
    #pragma unroll
    for (int o = 16; o > 0; o >>= 1) ss += __shfl_xor_sync(0xffffffffu, ss, o);
    const float inv = rsqrtf(ss * (1.0f / DH) + EPS);
    #pragma unroll
    for (int u = 0; u < 2; u++) {
        const int p = lane + u * 32;
        base[2*p]   = r[2*u]   * inv * qk_w[2*p];
        base[2*p+1] = r[2*u+1] * inv * qk_w[2*p+1];
    }
}

// ---------------------------------------------------------------------------
// Tensor-core causal flash attention, 3xTF32 (fp32-accurate).
// Block: 128 Q rows x (b,h). 8 warps, 16 rows each. K/V tiles: 64 keys.
// Smem: Qs[128][132] | Ks[2][64][132] | Vs[64][136] | Ps[128][68]  = 204.8 KB
// ---------------------------------------------------------------------------
#define FQ 128
#define FK 64
#define QSTR 132
#define KSTR 132
#define VSTR 136
#define PST2 68
#define OFF_K (FQ*QSTR)
#define OFF_V (OFF_K + 2*FK*KSTR)
#define OFF_P (OFF_V + FK*VSTR)
#define FA_SMEM ((OFF_P + FQ*PST2) * 4)

__global__ __launch_bounds__(256) void flash_attn_tc()
{
    extern __shared__ float sm[];
    float* Qs = sm;
    float* Ks = sm + OFF_K;
    float* Vs = sm + OFF_V;
    float* Ps = sm + OFF_P;

    const int qb = blockIdx.x;
    const int qm0 = qb * FQ;
    const int h = blockIdx.y, b = blockIdx.z;
    const int tid = threadIdx.x;
    const int warp = tid >> 5, lane = tid & 31;
    const int qr = lane >> 2, qc = lane & 3;
    const int wp = warp * 16;

    const float* qbase = g_qkv + (size_t)(b*SS) * TRIO + (size_t)h * DH;

    // prologue: Q tile + K tile 0
    #pragma unroll
    for (int rep = 0; rep < 16; rep++) {
        const int idx = rep*256 + tid;
        const int row = idx >> 5, c4 = (idx & 31) * 4;
        cpasync16(Qs + row*QSTR + c4, qbase + (size_t)(qm0 + row)*TRIO + c4);
    }
    #pragma unroll
    for (int rep = 0; rep < 8; rep++) {
        const int idx = rep*256 + tid;
        const int row = idx >> 5, c4 = (idx & 31) * 4;
        cpasync16(Ks + row*KSTR + c4, qbase + (size_t)row*TRIO + DD + c4);
    }
    asm volatile("cp.async.commit_group;\n");

    float m0 = -1e30f, m1 = -1e30f, l0 = 0.f, l1 = 0.f;
    float O[16][4];
    #pragma unroll
    for (int n = 0; n < 16; n++)
        #pragma unroll
        for (int u = 0; u < 4; u++) O[n][u] = 0.f;

    const float scale = 0.08838834764831845f; // 1/sqrt(128)
    const int nt = 2*qb + 2;

    for (int t = 0; t < nt; t++) {
        const int kn0 = t * FK;
        asm volatile("cp.async.wait_group 0;\n");
        __syncthreads();

        // issue V_t (single buffer; overlaps with S phase)
        #pragma unroll
        for (int rep = 0; rep < 8; rep++) {
            const int idx = rep*256 + tid;
            const int row = idx >> 5, c4 = (idx & 31) * 4;
            cpasync16(Vs + row*VSTR + c4,
                      qbase + (size_t)(kn0 + row)*TRIO + 2*DD + c4);
        }
        asm volatile("cp.async.commit_group;\n");
        // issue K_{t+1}
        if (t + 1 < nt) {
            float* kb = Ks + ((t+1)&1)*FK*KSTR;
            #pragma unroll
            for (int rep = 0; rep < 8; rep++) {
                const int idx = rep*256 + tid;
                const int row = idx >> 5, c4 = (idx & 31) * 4;
                cpasync16(kb + row*KSTR + c4,
                          qbase + (size_t)(kn0 + FK + row)*TRIO + DD + c4);
            }
            asm volatile("cp.async.commit_group;\n");
        }

        const bool active = (kn0 <= qm0 + wp + 15);
        if (active) {
            const float* Kb = Ks + (t&1)*FK*KSTR;
            float Sf[8][4];
            #pragma unroll
            for (int n = 0; n < 8; n++)
                #pragma unroll
                for (int u = 0; u < 4; u++) Sf[n][u] = 0.f;

            // S = Q K^T over d=128 (3xTF32)
            #pragma unroll 4
            for (int k16 = 0; k16 < 16; k16++) {
                const int kk = k16 * 8;
                uint32_t ah[4], al[4];
                {
                    const float* p = Qs + (wp + qr)*QSTR + kk + qc;
                    float a0 = p[0], a1 = p[8*QSTR], a2 = p[4], a3 = p[8*QSTR+4];
                    split_tf32(a0, ah[0], al[0]);
                    split_tf32(a1, ah[1], al[1]);
                    split_tf32(a2, ah[2], al[2]);
                    split_tf32(a3, ah[3], al[3]);
                }
                #pragma unroll
                for (int n = 0; n < 8; n++) {
                    const float* p = Kb + (n*8 + qr)*KSTR + kk + qc;
                    uint32_t bh[2], bl[2];
                    split_tf32(p[0], bh[0], bl[0]);
                    split_tf32(p[4], bh[1], bl[1]);
                    mma_tf32(Sf[n], ah, bh);
                    mma_tf32(Sf[n], al, bh);
                    mma_tf32(Sf[n], ah, bl);
                }
            }

            // causal mask (only near the diagonal)
            if (kn0 + FK - 1 > qm0 + wp) {
                const int row0 = qm0 + wp + qr;
                #pragma unroll
                for (int n = 0; n < 8; n++) {
                    const int c0 = kn0 + n*8 + 2*qc;
                    if (c0     > row0)     Sf[n][0] = -1e30f;
                    if (c0 + 1 > row0)     Sf[n][1] = -1e30f;
                    if (c0     > row0 + 8) Sf[n][2] = -1e30f;
                    if (c0 + 1 > row0 + 8) Sf[n][3] = -1e30f;
                }
            }

            // online softmax, per 16-row warp strip
            float mx0 = -1e30f, mx1 = -1e30f;
            #pragma unroll
            for (int n = 0; n < 8; n++) {
                mx0 = fmaxf(mx0, fmaxf(Sf[n][0], Sf[n][1]));
                mx1 = fmaxf(mx1, fmaxf(Sf[n][2], Sf[n][3]));
            }
            mx0 = fmaxf(mx0, __shfl_xor_sync(0xffffffffu, mx0, 1));
            mx0 = fmaxf(mx0, __shfl_xor_sync(0xffffffffu, mx0, 2));
            mx1 = fmaxf(mx1, __shfl_xor_sync(0xffffffffu, mx1, 1));
            mx1 = fmaxf(mx1, __shfl_xor_sync(0xffffffffu, mx1, 2));

            const float nm0 = fmaxf(m0, mx0), nm1 = fmaxf(m1, mx1);
            const float a0 = __expf((m0 - nm0)*scale);
            const float a1 = __expf((m1 - nm1)*scale);
            float rs0 = 0.f, rs1 = 0.f;
            #pragma unroll
            for (int n = 0; n < 8; n++) {
                const float p00 = __expf((Sf[n][0]-nm0)*scale);
                const float p01 = __expf((Sf[n][1]-nm0)*scale);
                const float p10 = __expf((Sf[n][2]-nm1)*scale);
                const float p11 = __expf((Sf[n][3]-nm1)*scale);
                rs0 += p00 + p01; rs1 += p10 + p11;
                *(float2*)(Ps + (wp+qr)*PST2 + n*8 + 2*qc)   = make_float2(p00, p01);
                *(float2*)(Ps + (wp+qr+8)*PST2 + n*8 + 2*qc) = make_float2(p10, p11);
            }
            rs0 += __shfl_xor_sync(0xffffffffu, rs0, 1);
            rs0 += __shfl_xor_sync(0xffffffffu, rs0, 2);
            rs1 += __shfl_xor_sync(0xffffffffu, rs1, 1);
            rs1 += __shfl_xor_sync(0xffffffffu, rs1, 2);
            l0 = l0*a0 + rs0; m0 = nm0;
            l1 = l1*a1 + rs1; m1 = nm1;
            #pragma unroll
            for (int n = 0; n < 16; n++) {
                O[n][0] *= a0; O[n][1] *= a0;
                O[n][2] *= a1; O[n][3] *= a1;
            }
        }

        // wait for V_t
        if (t + 1 < nt) asm volatile("cp.async.wait_group 1;\n");
        else            asm volatile("cp.async.wait_group 0;\n");
        __syncthreads();

        if (active) {
            // O += P V   (3xTF32)
            #pragma unroll 2
            for (int k = 0; k < 8; k++) {
                const int kk = k * 8;
                uint32_t ah[4], al[4];
                {
                    const float* p = Ps + (wp + qr)*PST2 + kk + qc;
                    float a0v = p[0], a1v = p[8*PST2], a2v = p[4], a3v = p[8*PST2+4];
                    split_tf32(a0v, ah[0], al[0]);
                    split_tf32(a1v, ah[1], al[1]);
                    split_tf32(a2v, ah[2], al[2]);
                    split_tf32(a3v, ah[3], al[3]);
                }
                #pragma unroll
                for (int n = 0; n < 16; n++) {
                    uint32_t bh[2], bl[2];
                    split_tf32(Vs[(kk + qc)*VSTR + n*8 + qr],     bh[0], bl[0]);
                    split_tf32(Vs[(kk + qc + 4)*VSTR + n*8 + qr], bh[1], bl[1]);
                    mma_tf32(O[n], ah, bh);
                    mma_tf32(O[n], al, bh);
                    mma_tf32(O[n], ah, bl);
                }
            }
        }
    }

    // epilogue
    const float il0 = 1.0f / l0, il1 = 1.0f / l1;
    const int r0 = b*SS + qm0 + wp + qr;
    #pragma unroll
    for (int n = 0; n < 16; n++) {
        const int c = h*DH + n*8 + 2*qc;
        *(float2*)(g_attn + (size_t)r0 * DD + c)       = make_float2(O[n][0]*il0, O[n][1]*il0);
        *(float2*)(g_attn + (size_t)(r0 + 8) * DD + c) = make_float2(O[n][2]*il1, O[n][3]*il1);
    }
}

// ---------------------------------------------------------------------------
// RMSNorm over D=2048, in place. One 256-thread block per row.
// ---------------------------------------------------------------------------
__global__ __launch_bounds__(256) void rmsnorm_rows(const float* __restrict__ w)
{
    __shared__ float red[8];
    __shared__ float s_inv;
    float* p = g_attn + (size_t)blockIdx.x * DD;
    const int tid = threadIdx.x;

    float v[8];
    float ss = 0.f;
    #pragma unroll
    for (int k = 0; k < 8; k++) {
        const float x = p[tid + k*256];
        v[k] = x;
        ss += x * x;
    }
    #pragma unroll
    for (int o = 16; o > 0; o >>= 1) ss += __shfl_xor_sync(0xffffffffu, ss, o);
    if ((tid & 31) == 0) red[tid >> 5] = ss;
    __syncthreads();
    if (tid == 0) {
        float t = 0.f;
        #pragma unroll
        for (int i = 0; i < 8; i++) t += red[i];
        s_inv = rsqrtf(t * (1.0f / DD) + EPS);
    }
    __syncthreads();
    const float inv = s_inv;
    #pragma unroll
    for (int k = 0; k < 8; k++) {
        const int idx = tid + k*256;
        p[idx] = v[k] * inv * w[idx];
    }
}

// ---------------------------------------------------------------------------
extern "C" void kernel_launch(void* const* d_in, const int* in_sizes, int n_in,
                              void* d_out, int out_size)
{
    const float* x     = (const float*)d_in[0];
    const float* rp    = (const float*)d_in[1];
    const float* Win   = (const float*)d_in[2];
    const float* b_in  = (const float*)d_in[3];
    const float* Wout  = (const float*)d_in[4];
    const float* b_out = (const float*)d_in[5];
    const float* qk_w  = (const float*)d_in[6];
    const float* out_w = (const float*)d_in[7];
    float* out = (float*)d_out;

    float* qkv;  cudaGetSymbolAddress((void**)&qkv,  g_qkv);
    float* attn; cudaGetSymbolAddress((void**)&attn, g_attn);

    const int gemm_smem = 4 * TBUF * (int)sizeof(float);  // 73728 B
    cudaFuncSetAttribute(tf32_gemm_nt_bias,
                         cudaFuncAttributeMaxDynamicSharedMemorySize, gemm_smem);
    cudaFuncSetAttribute(flash_attn_tc,
                         cudaFuncAttributeMaxDynamicSharedMemorySize, FA_SMEM);

    // 1) qkv = x @ Win^T + b_in     [4096, 6144]
    {
        dim3 grid(TRIO / TBN, MM / TBM);
        tf32_gemm_nt_bias<<<grid, 256, gemm_smem>>>(x, Win, b_in, qkv, MM, TRIO, DD);
    }
    // 2) RoPE + RMS on q,k (in place)
    {
        const int warps = MM * HH * 2;
        rope_rms_qk<<<warps / 8, 256>>>(rp, qk_w);
    }
    // 3) tensor-core causal flash attention -> g_attn
    {
        dim3 grid(SS / FQ, HH, BB);
        flash_attn_tc<<<grid, 256, FA_SMEM>>>();
    }
    // 4) RMSNorm over D (in place)
    rmsnorm_rows<<<MM, 256>>>(out_w);
    // 5) out = attn @ Wout^T + b_out
    {
        dim3 grid(DD / TBN, MM / TBM);
        tf32_gemm_nt_bias<<<grid, 256, gemm_smem>>>(attn, Wout, b_out, out, MM, DD, DD);
    }
}

// round 4
// speedup vs baseline: 2.6653x; 1.2248x over previous
#include <cuda_runtime.h>
#include <cuda_bf16.h>
#include <math.h>
#include <stdint.h>

// Problem constants
#define BB 2
#define SS 2048
#define DD 2048
#define HH 16
#define DH 128
#define MM (BB*SS)          // 4096
#define TRIO (3*DD)         // 6144
#define EPS 1e-6f

// Scratch (device globals; no allocation allowed)
__device__ float g_qkv[(size_t)MM * TRIO];   // 100.7 MB
__device__ float g_attn[(size_t)MM * DD];    // 33.6 MB

// ---------------------------------------------------------------------------
// Common tensor-core helpers
// ---------------------------------------------------------------------------
__device__ __forceinline__ uint32_t f2tf32(float f) {
    uint32_t r;
    asm("cvt.rna.tf32.f32 %0, %1;" : "=r"(r) : "f"(f));
    return r;
}
__device__ __forceinline__ void cpasync16(float* s, const float* g) {
    uint32_t sa = (uint32_t)__cvta_generic_to_shared(s);
    asm volatile("cp.async.cg.shared.global [%0], [%1], 16;" :: "r"(sa), "l"(g));
}
__device__ __forceinline__ void mma_tf32(float c[4], const uint32_t a[4], const uint32_t b[2]) {
    asm volatile(
        "mma.sync.aligned.m16n8k8.row.col.f32.tf32.tf32.f32 "
        "{%0,%1,%2,%3}, {%4,%5,%6,%7}, {%8,%9}, {%0,%1,%2,%3};"
        : "+f"(c[0]), "+f"(c[1]), "+f"(c[2]), "+f"(c[3])
        : "r"(a[0]), "r"(a[1]), "r"(a[2]), "r"(a[3]), "r"(b[0]), "r"(b[1]));
}
__device__ __forceinline__ void mma_bf16(float c[4], const uint32_t a[4], const uint32_t b[2]) {
    asm volatile(
        "mma.sync.aligned.m16n8k16.row.col.f32.bf16.bf16.f32 "
        "{%0,%1,%2,%3}, {%4,%5,%6,%7}, {%8,%9}, {%0,%1,%2,%3};"
        : "+f"(c[0]), "+f"(c[1]), "+f"(c[2]), "+f"(c[3])
        : "r"(a[0]), "r"(a[1]), "r"(a[2]), "r"(a[3]), "r"(b[0]), "r"(b[1]));
}
// split two floats into packed bf16x2 (hi) and packed bf16x2 residual (lo)
__device__ __forceinline__ void splitbf(float x0, float x1, uint32_t& hi, uint32_t& lo) {
    __nv_bfloat162 hp = __floats2bfloat162_rn(x0, x1);
    float r0 = x0 - __bfloat162float(hp.x);
    float r1 = x1 - __bfloat162float(hp.y);
    __nv_bfloat162 lp = __floats2bfloat162_rn(r0, r1);
    hi = *reinterpret_cast<uint32_t*>(&hp);
    lo = *reinterpret_cast<uint32_t*>(&lp);
}

// ---------------------------------------------------------------------------
// TF32 tensor-core GEMM: C[M,N] = A[M,K] @ W[N,K]^T + bias[N]  (unchanged)
// ---------------------------------------------------------------------------
#define TBM 128
#define TBN 128
#define TBK 32
#define TSTR 36
#define TBUF (TBM*TSTR)

__global__ __launch_bounds__(256) void tf32_gemm_nt_bias(
    const float* __restrict__ A, const float* __restrict__ W,
    const float* __restrict__ bias, float* __restrict__ C,
    int M, int N, int K)
{
    extern __shared__ float smem[];
    float* As = smem;
    float* Bs = smem + 2*TBUF;

    const int tid = threadIdx.x;
    const int bm0 = blockIdx.y * TBM;
    const int bn0 = blockIdx.x * TBN;

    const int warp = tid >> 5, lane = tid & 31;
    const int wm0 = (warp >> 2) * 64;
    const int wn0 = (warp & 3) * 32;
    const int qr = lane >> 2;
    const int qc = lane & 3;

    const int lrow = tid >> 1;
    const int lc0  = (tid & 1) * 16;
    const float* Ag = A + (size_t)(bm0 + lrow) * K + lc0;
    const float* Wg = W + (size_t)(bn0 + lrow) * K + lc0;
    float* AsW = As + lrow * TSTR + lc0;
    float* BsW = Bs + lrow * TSTR + lc0;

    float acc[4][4][4];
    #pragma unroll
    for (int i = 0; i < 4; i++)
        #pragma unroll
        for (int j = 0; j < 4; j++)
            #pragma unroll
            for (int u = 0; u < 4; u++) acc[i][j][u] = 0.f;

    const int nk = K / TBK;

    #pragma unroll
    for (int j = 0; j < 4; j++) {
        cpasync16(AsW + j*4, Ag + j*4);
        cpasync16(BsW + j*4, Wg + j*4);
    }
    asm volatile("cp.async.commit_group;\n");

    for (int kt = 0; kt < nk; kt++) {
        if (kt + 1 < nk) {
            const int nb = (kt + 1) & 1;
            const int ko = (kt + 1) * TBK;
            #pragma unroll
            for (int j = 0; j < 4; j++) {
                cpasync16(AsW + nb*TBUF + j*4, Ag + ko + j*4);
                cpasync16(BsW + nb*TBUF + j*4, Wg + ko + j*4);
            }
            asm volatile("cp.async.commit_group;\n");
            asm volatile("cp.async.wait_group 1;\n");
        } else {
            asm volatile("cp.async.wait_group 0;\n");
        }
        __syncthreads();

        const float* Ab = As + (kt & 1) * TBUF;
        const float* Bb = Bs + (kt & 1) * TBUF;

        #pragma unroll
        for (int kk = 0; kk < 4; kk++) {
            const int k = kk * 8;
            uint32_t af[4][4], bf[4][2];
            #pragma unroll
            for (int im = 0; im < 4; im++) {
                const float* p = Ab + (wm0 + im*16 + qr) * TSTR + k + qc;
                af[im][0] = f2tf32(p[0]);
                af[im][1] = f2tf32(p[8*TSTR]);
                af[im][2] = f2tf32(p[4]);
                af[im][3] = f2tf32(p[8*TSTR + 4]);
            }
            #pragma unroll
            for (int in = 0; in < 4; in++) {
                const float* p = Bb + (wn0 + in*8 + qr) * TSTR + k + qc;
                bf[in][0] = f2tf32(p[0]);
                bf[in][1] = f2tf32(p[4]);
            }
            #pragma unroll
            for (int im = 0; im < 4; im++)
                #pragma unroll
                for (int in = 0; in < 4; in++)
                    mma_tf32(acc[im][in], af[im], bf[in]);
        }
        __syncthreads();
    }

    #pragma unroll
    for (int im = 0; im < 4; im++) {
        #pragma unroll
        for (int in = 0; in < 4; in++) {
            const int r0 = bm0 + wm0 + im*16 + qr;
            const int c0 = bn0 + wn0 + in*8 + qc*2;
            const float2 b2 = *(const float2*)(bias + c0);
            float2 v;
            v.x = acc[im][in][0] + b2.x; v.y = acc[im][in][1] + b2.y;
            *(float2*)(C + (size_t)r0 * N + c0) = v;
            v.x = acc[im][in][2] + b2.x; v.y = acc[im][in][3] + b2.y;
            *(float2*)(C + (size_t)(r0 + 8) * N + c0) = v;
        }
    }
}

// ---------------------------------------------------------------------------
// RoPE + RMSNorm for q and k, in-place in g_qkv. One warp per (m, which, h).
// ---------------------------------------------------------------------------
__global__ __launch_bounds__(256) void rope_rms_qk(
    const float* __restrict__ rp, const float* __restrict__ qk_w)
{
    const int w = blockIdx.x * (blockDim.x >> 5) + (threadIdx.x >> 5);
    const int lane = threadIdx.x & 31;
    const int h = w % HH;
    const int t = w / HH;
    const int which = t & 1;
    const int m = t >> 1;
    const int s = m & (SS - 1);

    float* base = g_qkv + (size_t)m * TRIO + which * DD + h * DH;
    const float* ang = rp + s * (DH/2);

    float r[4];
    float ss = 0.f;
    #pragma unroll
    for (int u = 0; u < 2; u++) {
        const int p = lane + u * 32;
        const float a = ang[p];
        const float c = cosf(a), sn = sinf(a);
        const float x0 = base[2*p], x1 = base[2*p+1];
        const float r0 = x0 * c - x1 * sn;
        const float r1 = x0 * sn + x1 * c;
        r[2*u] = r0; r[2*u+1] = r1;
        ss += r0*r0 + r1*r1;
    }
    #pragma unroll
    for (int o = 16; o > 0; o >>= 1) ss += __shfl_xor_sync(0xffffffffu, ss, o);
    const float inv = rsqrtf(ss * (1.0f / DH) + EPS);
    #pragma unroll
    for (int u = 0; u < 2; u++) {
        const int p = lane + u * 32;
        base[2*p]   = r[2*u]   * inv * qk_w[2*p];
        base[2*p+1] = r[2*u+1] * inv * qk_w[2*p+1];
    }
}

// ---------------------------------------------------------------------------
// bf16 3-product tensor-core causal flash attention (near-fp32 accurate).
// 512 threads, 16 warps; warp pair (wp2) owns a 16-row strip, halves split
// the n range. Operands pre-split into packed bf16x2 hi/lo smem once.
// ---------------------------------------------------------------------------
#define FQ 128
#define FK 64
// u32-unit smem offsets
#define OQH 0
#define OQL (OQH + 128*68)          // 8704
#define OKH (OQL + 128*68)          // 17408
#define OKL (OKH + 64*68)           // 21760
#define OVH (OKL + 64*68)           // 26112
#define OVL (OVH + 128*36)          // 30720
#define OPH (OVL + 128*36)          // 35328
#define OPL (OPH + 128*36)          // 39936
#define ORAW (OPL + 128*36)         // 44544  (floats, 64x132)
#define ORED (ORAW + 64*132)        // 52992  (floats, 512: [max 2x128][sum 2x128])
#define FA2_SMEM ((ORED + 512) * 4) // 214016 B

__global__ __launch_bounds__(512, 1) void flash_attn_bf16x3()
{
    extern __shared__ uint32_t smu[];
    float* smf = reinterpret_cast<float*>(smu);

    const int qb = (int)(gridDim.x - 1 - blockIdx.x);   // heavy blocks first
    const int qm0 = qb * FQ;
    const int h = blockIdx.y, b = blockIdx.z;
    const int tid = threadIdx.x;
    const int warp = tid >> 5, lane = tid & 31;
    const int qr = lane >> 2, qc = lane & 3;
    const int wp2 = warp >> 1, half = warp & 1;
    const int wrow = wp2 * 16;

    const float* qbase = g_qkv + (size_t)(b*SS) * TRIO + (size_t)h * DH;

    // ---- issue cp.async for K_0 into RAW ----
    #pragma unroll
    for (int rep = 0; rep < 4; rep++) {
        const int idx = rep*512 + tid;
        const int row = idx >> 5, c4 = (idx & 31) * 4;
        cpasync16(smf + ORAW + row*132 + c4,
                  qbase + (size_t)row*TRIO + DD + c4);
    }
    asm volatile("cp.async.commit_group;\n");

    // ---- load + split Q (once; reused for all tiles) ----
    #pragma unroll
    for (int rep = 0; rep < 8; rep++) {
        const int idx = rep*512 + tid;
        const int row = idx >> 5, g = idx & 31;
        const float4 v = *(const float4*)(qbase + (size_t)(qm0 + row)*TRIO + 4*g);
        uint32_t h0, l0, h1, l1;
        splitbf(v.x, v.y, h0, l0);
        splitbf(v.z, v.w, h1, l1);
        smu[OQH + row*68 + 2*g]     = h0;
        smu[OQH + row*68 + 2*g + 1] = h1;
        smu[OQL + row*68 + 2*g]     = l0;
        smu[OQL + row*68 + 2*g + 1] = l1;
    }

    float m0 = -1e30f, m1 = -1e30f, l0s = 0.f, l1s = 0.f;
    float O[8][4];
    #pragma unroll
    for (int n = 0; n < 8; n++)
        #pragma unroll
        for (int u = 0; u < 4; u++) O[n][u] = 0.f;

    const float scale = 0.08838834764831845f; // 1/sqrt(128)
    const int nt = 2*qb + 2;

    for (int t = 0; t < nt; t++) {
        const int kn0 = t * FK;

        // ---- K_t raw ready ----
        asm volatile("cp.async.wait_group 0;\n");
        __syncthreads();

        // ---- cooperative K split: RAW[j][d] -> KH/KL[j][d2] ----
        #pragma unroll
        for (int rep = 0; rep < 8; rep++) {
            const int idx = rep*512 + tid;
            const int j = idx >> 6, d2 = idx & 63;
            const float2 v = *(const float2*)(smf + ORAW + j*132 + 2*d2);
            uint32_t hi, lo;
            splitbf(v.x, v.y, hi, lo);
            smu[OKH + j*68 + d2] = hi;
            smu[OKL + j*68 + d2] = lo;
        }
        __syncthreads();

        // ---- issue cp.async for V_t into RAW (overlaps S phase) ----
        #pragma unroll
        for (int rep = 0; rep < 4; rep++) {
            const int idx = rep*512 + tid;
            const int row = idx >> 5, c4 = (idx & 31) * 4;
            cpasync16(smf + ORAW + row*132 + c4,
                      qbase + (size_t)(kn0 + row)*TRIO + 2*DD + c4);
        }
        asm volatile("cp.async.commit_group;\n");

        const bool active = (kn0 <= qm0 + wrow + 15);
        if (active) {
            // ---- S = Q K^T (bf16 3-product), this warp: 4 n-frags ----
            float Sf[4][4];
            #pragma unroll
            for (int n = 0; n < 4; n++)
                #pragma unroll
                for (int u = 0; u < 4; u++) Sf[n][u] = 0.f;

            #pragma unroll
            for (int ch = 0; ch < 8; ch++) {
                uint32_t ah[4], al[4];
                {
                    const uint32_t* p = smu + OQH + (wrow + qr)*68 + ch*8 + qc;
                    ah[0] = p[0]; ah[1] = p[8*68]; ah[2] = p[4]; ah[3] = p[8*68 + 4];
                    const uint32_t* q = smu + OQL + (wrow + qr)*68 + ch*8 + qc;
                    al[0] = q[0]; al[1] = q[8*68]; al[2] = q[4]; al[3] = q[8*68 + 4];
                }
                #pragma unroll
                for (int nf = 0; nf < 4; nf++) {
                    const int gn = half*4 + nf;
                    const uint32_t* kh = smu + OKH + (gn*8 + qr)*68 + ch*8 + qc;
                    const uint32_t* kl = smu + OKL + (gn*8 + qr)*68 + ch*8 + qc;
                    uint32_t bh[2] = {kh[0], kh[4]};
                    uint32_t bl[2] = {kl[0], kl[4]};
                    mma_bf16(Sf[nf], ah, bh);
                    mma_bf16(Sf[nf], al, bh);
                    mma_bf16(Sf[nf], ah, bl);
                }
            }

            // ---- causal mask ----
            if (kn0 + FK - 1 > qm0 + wrow) {
                const int r0g = qm0 + wrow + qr;
                #pragma unroll
                for (int nf = 0; nf < 4; nf++) {
                    const int c0 = kn0 + (half*4 + nf)*8 + 2*qc;
                    if (c0     > r0g)     Sf[nf][0] = -1e30f;
                    if (c0 + 1 > r0g)     Sf[nf][1] = -1e30f;
                    if (c0     > r0g + 8) Sf[nf][2] = -1e30f;
                    if (c0 + 1 > r0g + 8) Sf[nf][3] = -1e30f;
                }
            }

            // ---- online softmax (cross-half via smem + pair barrier) ----
            float mx0 = -1e30f, mx1 = -1e30f;
            #pragma unroll
            for (int nf = 0; nf < 4; nf++) {
                mx0 = fmaxf(mx0, fmaxf(Sf[nf][0], Sf[nf][1]));
                mx1 = fmaxf(mx1, fmaxf(Sf[nf][2], Sf[nf][3]));
            }
            mx0 = fmaxf(mx0, __shfl_xor_sync(0xffffffffu, mx0, 1));
            mx0 = fmaxf(mx0, __shfl_xor_sync(0xffffffffu, mx0, 2));
            mx1 = fmaxf(mx1, __shfl_xor_sync(0xffffffffu, mx1, 1));
            mx1 = fmaxf(mx1, __shfl_xor_sync(0xffffffffu, mx1, 2));
            if (qc == 0) {
                smf[ORED + half*128 + wrow + qr]     = mx0;
                smf[ORED + half*128 + wrow + qr + 8] = mx1;
            }
            asm volatile("bar.sync %0, %1;" :: "r"(wp2 + 1), "r"(64) : "memory");
            {
                const float o0 = smf[ORED + (1 - half)*128 + wrow + qr];
                const float o1 = smf[ORED + (1 - half)*128 + wrow + qr + 8];
                mx0 = fmaxf(mx0, o0);
                mx1 = fmaxf(mx1, o1);
            }
            const float nm0 = fmaxf(m0, mx0), nm1 = fmaxf(m1, mx1);
            const float a0 = __expf((m0 - nm0) * scale);
            const float a1 = __expf((m1 - nm1) * scale);
            float rs0 = 0.f, rs1 = 0.f;
            #pragma unroll
            for (int nf = 0; nf < 4; nf++) {
                const float p00 = __expf((Sf[nf][0] - nm0) * scale);
                const float p01 = __expf((Sf[nf][1] - nm0) * scale);
                const float p10 = __expf((Sf[nf][2] - nm1) * scale);
                const float p11 = __expf((Sf[nf][3] - nm1) * scale);
                rs0 += p00 + p01; rs1 += p10 + p11;
                uint32_t hi, lo;
                splitbf(p00, p01, hi, lo);
                smu[OPH + (wrow + qr)*36 + (half*4 + nf)*4 + qc] = hi;
                smu[OPL + (wrow + qr)*36 + (half*4 + nf)*4 + qc] = lo;
                splitbf(p10, p11, hi, lo);
                smu[OPH + (wrow + qr + 8)*36 + (half*4 + nf)*4 + qc] = hi;
                smu[OPL + (wrow + qr + 8)*36 + (half*4 + nf)*4 + qc] = lo;
            }
            rs0 += __shfl_xor_sync(0xffffffffu, rs0, 1);
            rs0 += __shfl_xor_sync(0xffffffffu, rs0, 2);
            rs1 += __shfl_xor_sync(0xffffffffu, rs1, 1);
            rs1 += __shfl_xor_sync(0xffffffffu, rs1, 2);
            if (qc == 0) {
                smf[ORED + 256 + half*128 + wrow + qr]     = rs0;
                smf[ORED + 256 + half*128 + wrow + qr + 8] = rs1;
            }
            asm volatile("bar.sync %0, %1;" :: "r"(wp2 + 1), "r"(64) : "memory");
            {
                const float o0 = smf[ORED + 256 + (1 - half)*128 + wrow + qr];
                const float o1 = smf[ORED + 256 + (1 - half)*128 + wrow + qr + 8];
                rs0 += o0; rs1 += o1;
            }
            l0s = l0s*a0 + rs0; m0 = nm0;
            l1s = l1s*a1 + rs1; m1 = nm1;
            #pragma unroll
            for (int n = 0; n < 8; n++) {
                O[n][0] *= a0; O[n][1] *= a0;
                O[n][2] *= a1; O[n][3] *= a1;
            }
        }

        // ---- V_t raw ready ----
        asm volatile("cp.async.wait_group 0;\n");
        __syncthreads();

        // ---- cooperative V split+transpose: RAW[j][d] -> VH/VL[d][j2] ----
        #pragma unroll
        for (int rep = 0; rep < 8; rep++) {
            const int idx = rep*512 + tid;
            const int d = idx & 127, j2 = idx >> 7;
            const float x0 = smf[ORAW + (2*j2)*132 + d];
            const float x1 = smf[ORAW + (2*j2 + 1)*132 + d];
            uint32_t hi, lo;
            splitbf(x0, x1, hi, lo);
            smu[OVH + d*36 + j2] = hi;
            smu[OVL + d*36 + j2] = lo;
        }
        __syncthreads();

        // ---- issue cp.async for K_{t+1} (overlaps PV phase) ----
        if (t + 1 < nt) {
            #pragma unroll
            for (int rep = 0; rep < 4; rep++) {
                const int idx = rep*512 + tid;
                const int row = idx >> 5, c4 = (idx & 31) * 4;
                cpasync16(smf + ORAW + row*132 + c4,
                          qbase + (size_t)(kn0 + FK + row)*TRIO + DD + c4);
            }
            asm volatile("cp.async.commit_group;\n");
        }

        if (active) {
            // ---- O += P V (bf16 3-product), this warp: 8 n-frags (d half) ----
            #pragma unroll
            for (int ch = 0; ch < 4; ch++) {
                uint32_t ah[4], al[4];
                {
                    const uint32_t* p = smu + OPH + (wrow + qr)*36 + ch*8 + qc;
                    ah[0] = p[0]; ah[1] = p[8*36]; ah[2] = p[4]; ah[3] = p[8*36 + 4];
                    const uint32_t* q = smu + OPL + (wrow + qr)*36 + ch*8 + qc;
                    al[0] = q[0]; al[1] = q[8*36]; al[2] = q[4]; al[3] = q[8*36 + 4];
                }
                #pragma unroll
                for (int nf = 0; nf < 8; nf++) {
                    const int gn = half*8 + nf;
                    const uint32_t* vh = smu + OVH + (gn*8 + qr)*36 + ch*8 + qc;
                    const uint32_t* vl = smu + OVL + (gn*8 + qr)*36 + ch*8 + qc;
                    uint32_t bh[2] = {vh[0], vh[4]};
                    uint32_t bl[2] = {vl[0], vl[4]};
                    mma_bf16(O[nf], ah, bh);
                    mma_bf16(O[nf], al, bh);
                    mma_bf16(O[nf], ah, bl);
                }
            }
        }
    }

    // ---- epilogue ----
    const float il0 = 1.0f / l0s, il1 = 1.0f / l1s;
    const int r0 = b*SS + qm0 + wrow + qr;
    #pragma unroll
    for (int nf = 0; nf < 8; nf++) {
        const int c = h*DH + (half*8 + nf)*8 + 2*qc;
        *(float2*)(g_attn + (size_t)r0 * DD + c) =
            make_float2(O[nf][0]*il0, O[nf][1]*il0);
        *(float2*)(g_attn + (size_t)(r0 + 8) * DD + c) =
            make_float2(O[nf][2]*il1, O[nf][3]*il1);
    }
}

// ---------------------------------------------------------------------------
// RMSNorm over D=2048, in place. One 256-thread block per row.
// ---------------------------------------------------------------------------
__global__ __launch_bounds__(256) void rmsnorm_rows(const float* __restrict__ w)
{
    __shared__ float red[8];
    __shared__ float s_inv;
    float* p = g_attn + (size_t)blockIdx.x * DD;
    const int tid = threadIdx.x;

    float v[8];
    float ss = 0.f;
    #pragma unroll
    for (int k = 0; k < 8; k++) {
        const float x = p[tid + k*256];
        v[k] = x;
        ss += x * x;
    }
    #pragma unroll
    for (int o = 16; o > 0; o >>= 1) ss += __shfl_xor_sync(0xffffffffu, ss, o);
    if ((tid & 31) == 0) red[tid >> 5] = ss;
    __syncthreads();
    if (tid == 0) {
        float t = 0.f;
        #pragma unroll
        for (int i = 0; i < 8; i++) t += red[i];
        s_inv = rsqrtf(t * (1.0f / DD) + EPS);
    }
    __syncthreads();
    const float inv = s_inv;
    #pragma unroll
    for (int k = 0; k < 8; k++) {
        const int idx = tid + k*256;
        p[idx] = v[k] * inv * w[idx];
    }
}

// ---------------------------------------------------------------------------
extern "C" void kernel_launch(void* const* d_in, const int* in_sizes, int n_in,
                              void* d_out, int out_size)
{
    const float* x     = (const float*)d_in[0];
    const float* rp    = (const float*)d_in[1];
    const float* Win   = (const float*)d_in[2];
    const float* b_in  = (const float*)d_in[3];
    const float* Wout  = (const float*)d_in[4];
    const float* b_out = (const float*)d_in[5];
    const float* qk_w  = (const float*)d_in[6];
    const float* out_w = (const float*)d_in[7];
    float* out = (float*)d_out;

    float* qkv;  cudaGetSymbolAddress((void**)&qkv,  g_qkv);
    float* attn; cudaGetSymbolAddress((void**)&attn, g_attn);

    const int gemm_smem = 4 * TBUF * (int)sizeof(float);  // 73728 B
    cudaFuncSetAttribute(tf32_gemm_nt_bias,
                         cudaFuncAttributeMaxDynamicSharedMemorySize, gemm_smem);
    cudaFuncSetAttribute(flash_attn_bf16x3,
                         cudaFuncAttributeMaxDynamicSharedMemorySize, FA2_SMEM);

    // 1) qkv = x @ Win^T + b_in     [4096, 6144]
    {
        dim3 grid(TRIO / TBN, MM / TBM);
        tf32_gemm_nt_bias<<<grid, 256, gemm_smem>>>(x, Win, b_in, qkv, MM, TRIO, DD);
    }
    // 2) RoPE + RMS on q,k (in place)
    {
        const int warps = MM * HH * 2;
        rope_rms_qk<<<warps / 8, 256>>>(rp, qk_w);
    }
    // 3) bf16x3 tensor-core causal flash attention -> g_attn
    {
        dim3 grid(SS / FQ, HH, BB);
        flash_attn_bf16x3<<<grid, 512, FA2_SMEM>>>();
    }
    // 4) RMSNorm over D (in place)
    rmsnorm_rows<<<MM, 256>>>(out_w);
    // 5) out = attn @ Wout^T + b_out
    {
        dim3 grid(DD / TBN, MM / TBM);
        tf32_gemm_nt_bias<<<grid, 256, gemm_smem>>>(attn, Wout, b_out, out, MM, DD, DD);
    }
}

// round 7
// speedup vs baseline: 2.7826x; 1.0440x over previous
#include <cuda_runtime.h>
#include <cuda_bf16.h>
#include <math.h>
#include <stdint.h>

// Problem constants
#define BB 2
#define SS 2048
#define DD 2048
#define HH 16
#define DH 128
#define MM (BB*SS)          // 4096
#define TRIO (3*DD)         // 6144
#define EPS 1e-6f

// Scratch (device globals; no allocation allowed)
__device__ float g_qkv[(size_t)MM * TRIO];   // 100.7 MB
__device__ float g_attn[(size_t)MM * DD];    // 33.6 MB
// Pre-split bf16x2 planes (hi/lo), packed 2 elems per u32.
// q/k: [b][h][s][64]   v (transposed): [b][h][d][1024]
__device__ uint32_t g_qh[(size_t)BB*HH*SS*64];
__device__ uint32_t g_ql[(size_t)BB*HH*SS*64];
__device__ uint32_t g_kh[(size_t)BB*HH*SS*64];
__device__ uint32_t g_kl[(size_t)BB*HH*SS*64];
__device__ uint32_t g_vh[(size_t)BB*HH*DH*(SS/2)];
__device__ uint32_t g_vl[(size_t)BB*HH*DH*(SS/2)];

// ---------------------------------------------------------------------------
// Helpers
// ---------------------------------------------------------------------------
__device__ __forceinline__ uint32_t f2tf32(float f) {
    uint32_t r;
    asm("cvt.rna.tf32.f32 %0, %1;" : "=r"(r) : "f"(f));
    return r;
}
__device__ __forceinline__ void cpasync16(float* s, const float* g) {
    uint32_t sa = (uint32_t)__cvta_generic_to_shared(s);
    asm volatile("cp.async.cg.shared.global [%0], [%1], 16;" :: "r"(sa), "l"(g));
}
__device__ __forceinline__ void cpasync16u(uint32_t* s, const uint32_t* g) {
    uint32_t sa = (uint32_t)__cvta_generic_to_shared(s);
    asm volatile("cp.async.cg.shared.global [%0], [%1], 16;" :: "r"(sa), "l"(g));
}
__device__ __forceinline__ void mma_tf32(float c[4], const uint32_t a[4], const uint32_t b[2]) {
    asm volatile(
        "mma.sync.aligned.m16n8k8.row.col.f32.tf32.tf32.f32 "
        "{%0,%1,%2,%3}, {%4,%5,%6,%7}, {%8,%9}, {%0,%1,%2,%3};"
        : "+f"(c[0]), "+f"(c[1]), "+f"(c[2]), "+f"(c[3])
        : "r"(a[0]), "r"(a[1]), "r"(a[2]), "r"(a[3]), "r"(b[0]), "r"(b[1]));
}
__device__ __forceinline__ void mma_bf16(float c[4], const uint32_t a[4], const uint32_t b[2]) {
    asm volatile(
        "mma.sync.aligned.m16n8k16.row.col.f32.bf16.bf16.f32 "
        "{%0,%1,%2,%3}, {%4,%5,%6,%7}, {%8,%9}, {%0,%1,%2,%3};"
        : "+f"(c[0]), "+f"(c[1]), "+f"(c[2]), "+f"(c[3])
        : "r"(a[0]), "r"(a[1]), "r"(a[2]), "r"(a[3]), "r"(b[0]), "r"(b[1]));
}
// split two floats into packed bf16x2 (hi) and packed bf16x2 residual (lo)
__device__ __forceinline__ void splitbf(float x0, float x1, uint32_t& hi, uint32_t& lo) {
    __nv_bfloat162 hp = __floats2bfloat162_rn(x0, x1);
    float r0 = x0 - __bfloat162float(hp.x);
    float r1 = x1 - __bfloat162float(hp.y);
    __nv_bfloat162 lp = __floats2bfloat162_rn(r0, r1);
    hi = *reinterpret_cast<uint32_t*>(&hp);
    lo = *reinterpret_cast<uint32_t*>(&lp);
}
// 16B-granule XOR swizzle address (u32 units): row r, u32-col p, row length rowu
__device__ __forceinline__ int xsw(int r, int p, int rowu) {
    return r*rowu + ((((p >> 2) ^ (r & 7)) << 2) | (p & 3));
}

// ---------------------------------------------------------------------------
// TF32 tensor-core GEMM: C[M,N] = A[M,K] @ W[N,K]^T + bias[N]  (unchanged)
// ---------------------------------------------------------------------------
#define TBM 128
#define TBN 128
#define TBK 32
#define TSTR 36
#define TBUF (TBM*TSTR)

__global__ __launch_bounds__(256) void tf32_gemm_nt_bias(
    const float* __restrict__ A, const float* __restrict__ W,
    const float* __restrict__ bias, float* __restrict__ C,
    int M, int N, int K)
{
    extern __shared__ float smem[];
    float* As = smem;
    float* Bs = smem + 2*TBUF;

    const int tid = threadIdx.x;
    const int bm0 = blockIdx.y * TBM;
    const int bn0 = blockIdx.x * TBN;

    const int warp = tid >> 5, lane = tid & 31;
    const int wm0 = (warp >> 2) * 64;
    const int wn0 = (warp & 3) * 32;
    const int qr = lane >> 2;
    const int qc = lane & 3;

    const int lrow = tid >> 1;
    const int lc0  = (tid & 1) * 16;
    const float* Ag = A + (size_t)(bm0 + lrow) * K + lc0;
    const float* Wg = W + (size_t)(bn0 + lrow) * K + lc0;
    float* AsW = As + lrow * TSTR + lc0;
    float* BsW = Bs + lrow * TSTR + lc0;

    float acc[4][4][4];
    #pragma unroll
    for (int i = 0; i < 4; i++)
        #pragma unroll
        for (int j = 0; j < 4; j++)
            #pragma unroll
            for (int u = 0; u < 4; u++) acc[i][j][u] = 0.f;

    const int nk = K / TBK;

    #pragma unroll
    for (int j = 0; j < 4; j++) {
        cpasync16(AsW + j*4, Ag + j*4);
        cpasync16(BsW + j*4, Wg + j*4);
    }
    asm volatile("cp.async.commit_group;\n");

    for (int kt = 0; kt < nk; kt++) {
        if (kt + 1 < nk) {
            const int nb = (kt + 1) & 1;
            const int ko = (kt + 1) * TBK;
            #pragma unroll
            for (int j = 0; j < 4; j++) {
                cpasync16(AsW + nb*TBUF + j*4, Ag + ko + j*4);
                cpasync16(BsW + nb*TBUF + j*4, Wg + ko + j*4);
            }
            asm volatile("cp.async.commit_group;\n");
            asm volatile("cp.async.wait_group 1;\n");
        } else {
            asm volatile("cp.async.wait_group 0;\n");
        }
        __syncthreads();

        const float* Ab = As + (kt & 1) * TBUF;
        const float* Bb = Bs + (kt & 1) * TBUF;

        #pragma unroll
        for (int kk = 0; kk < 4; kk++) {
            const int k = kk * 8;
            uint32_t af[4][4], bf[4][2];
            #pragma unroll
            for (int im = 0; im < 4; im++) {
                const float* p = Ab + (wm0 + im*16 + qr) * TSTR + k + qc;
                af[im][0] = f2tf32(p[0]);
                af[im][1] = f2tf32(p[8*TSTR]);
                af[im][2] = f2tf32(p[4]);
                af[im][3] = f2tf32(p[8*TSTR + 4]);
            }
            #pragma unroll
            for (int in = 0; in < 4; in++) {
                const float* p = Bb + (wn0 + in*8 + qr) * TSTR + k + qc;
                bf[in][0] = f2tf32(p[0]);
                bf[in][1] = f2tf32(p[4]);
            }
            #pragma unroll
            for (int im = 0; im < 4; im++)
                #pragma unroll
                for (int in = 0; in < 4; in++)
                    mma_tf32(acc[im][in], af[im], bf[in]);
        }
        __syncthreads();
    }

    #pragma unroll
    for (int im = 0; im < 4; im++) {
        #pragma unroll
        for (int in = 0; in < 4; in++) {
            const int r0 = bm0 + wm0 + im*16 + qr;
            const int c0 = bn0 + wn0 + in*8 + qc*2;
            const float2 b2 = *(const float2*)(bias + c0);
            float2 v;
            v.x = acc[im][in][0] + b2.x; v.y = acc[im][in][1] + b2.y;
            *(float2*)(C + (size_t)r0 * N + c0) = v;
            v.x = acc[im][in][2] + b2.x; v.y = acc[im][in][3] + b2.y;
            *(float2*)(C + (size_t)(r0 + 8) * N + c0) = v;
        }
    }
}

// ---------------------------------------------------------------------------
// RoPE + RMSNorm for q,k; writes pre-split bf16 hi/lo planes.
// One warp per (m, which, h).
// ---------------------------------------------------------------------------
__global__ __launch_bounds__(256) void rope_rms_split(
    const float* __restrict__ rp, const float* __restrict__ qk_w)
{
    const int w = blockIdx.x * 8 + (threadIdx.x >> 5);
    const int lane = threadIdx.x & 31;
    const int h = w % HH;
    const int t = w / HH;
    const int which = t & 1;          // 0=q, 1=k
    const int m = t >> 1;             // 0..4095
    const int s = m & (SS - 1);
    const int b = m >> 11;            // m / SS

    const float* base = g_qkv + (size_t)m * TRIO + which * DD + h * DH;
    const float* ang = rp + s * (DH/2);

    float r[4];
    float ss = 0.f;
    #pragma unroll
    for (int u = 0; u < 2; u++) {
        const int p = lane + u * 32;
        const float a = ang[p];
        const float c = cosf(a), sn = sinf(a);
        const float x0 = base[2*p], x1 = base[2*p+1];
        const float r0 = x0 * c - x1 * sn;
        const float r1 = x0 * sn + x1 * c;
        r[2*u] = r0; r[2*u+1] = r1;
        ss += r0*r0 + r1*r1;
    }
    #pragma unroll
    for (int o = 16; o > 0; o >>= 1) ss += __shfl_xor_sync(0xffffffffu, ss, o);
    const float inv = rsqrtf(ss * (1.0f / DH) + EPS);

    const float o0 = r[0] * inv * qk_w[2*lane];
    const float o1 = r[1] * inv * qk_w[2*lane + 1];
    const float o2 = r[2] * inv * qk_w[2*(lane+32)];
    const float o3 = r[3] * inv * qk_w[2*(lane+32) + 1];
    uint32_t h0, l0, h1, l1;
    splitbf(o0, o1, h0, l0);
    splitbf(o2, o3, h1, l1);

    const size_t pb = ((size_t)(b*HH + h)*SS + s) * 64;
    uint32_t* ph = which ? g_kh : g_qh;
    uint32_t* pl = which ? g_kl : g_ql;
    ph[pb + lane]      = h0;
    ph[pb + lane + 32] = h1;
    pl[pb + lane]      = l0;
    pl[pb + lane + 32] = l1;
}

// ---------------------------------------------------------------------------
// V split + transpose: g_qkv v -> g_vh/g_vl [b][h][d][s2]. Block per
// (s-chunk of 128, h, b); 256 threads; smem 128x129 fp32.
// ---------------------------------------------------------------------------
__global__ __launch_bounds__(256) void v_split_t()
{
    extern __shared__ float vt[];     // [128][129]
    const int sc = blockIdx.x, h = blockIdx.y, b = blockIdx.z;
    const int tid = threadIdx.x;

    #pragma unroll
    for (int rep = 0; rep < 16; rep++) {
        const int idx = rep*256 + tid;
        const int r = idx >> 5, c4 = (idx & 31) * 4;
        const float4 v = *(const float4*)(g_qkv +
            (size_t)(b*SS + sc*128 + r)*TRIO + 2*DD + h*DH + c4);
        vt[r*129 + c4 + 0] = v.x; vt[r*129 + c4 + 1] = v.y;
        vt[r*129 + c4 + 2] = v.z; vt[r*129 + c4 + 3] = v.w;
    }
    __syncthreads();

    #pragma unroll
    for (int rep = 0; rep < 32; rep++) {
        const int idx = rep*256 + tid;
        const int d = idx >> 6, j2 = idx & 63;
        const float x0 = vt[(2*j2)*129 + d];
        const float x1 = vt[(2*j2 + 1)*129 + d];
        uint32_t hi, lo;
        splitbf(x0, x1, hi, lo);
        const size_t o = ((size_t)(b*HH + h)*DH + d)*(SS/2) + sc*64 + j2;
        g_vh[o] = hi;
        g_vl[o] = lo;
    }
}

// ---------------------------------------------------------------------------
// Flash attention v2: mma.sync bf16 3-product, static-shift softmax,
// pre-split operands, XOR-swizzled smem, 2 blocks/SM.
// FQ=64 q rows, FK=64 keys/tile, 256 threads (8 warps = 4 strips x 2 halves).
// ---------------------------------------------------------------------------
#define AQH 0
#define AQL 4096
#define AKH 8192
#define AKL 12288
#define AVH 16384
#define AVL 20480
#define APH 24576
#define APL 26624
#define ALRED 28672
#define ASZ ((28672 + 128) * 4)     // 115200 B
#define SHIFTC 11.32f

__global__ __launch_bounds__(256, 2) void flash_attn_v2()
{
    extern __shared__ uint32_t smu[];
    float* smf = reinterpret_cast<float*>(smu);

    const int qb = (int)(gridDim.x - 1 - blockIdx.x);   // heavy blocks first
    const int qm0 = qb * 64;
    const int h = blockIdx.y, b = blockIdx.z;
    const int tid = threadIdx.x;
    const int warp = tid >> 5, lane = tid & 31;
    const int qr = lane >> 2, qc = lane & 3;
    const int half = warp & 1;
    const int wrow = (warp >> 1) * 16;

    const size_t qkbase = (size_t)(b*HH + h) * SS * 64;        // u32
    const size_t vbase  = (size_t)(b*HH + h) * DH * (SS/2);    // u32
    const float scale = 0.08838834764831845f;                  // 1/sqrt(128)

    // ---- prologue: Q planes (this block's 64 rows) + K_0 planes ----
    #pragma unroll
    for (int rep = 0; rep < 4; rep++) {
        const int idx = rep*256 + tid;           // 0..1023
        const int r = idx >> 4, g = idx & 15;
        const int dst = r*64 + ((g ^ (r & 7)) << 2);
        const size_t qsrc = qkbase + (size_t)(qm0 + r)*64 + g*4;
        const size_t ksrc = qkbase + (size_t)r*64 + g*4;
        cpasync16u(smu + AQH + dst, g_qh + qsrc);
        cpasync16u(smu + AQL + dst, g_ql + qsrc);
        cpasync16u(smu + AKH + dst, g_kh + ksrc);
        cpasync16u(smu + AKL + dst, g_kl + ksrc);
    }
    asm volatile("cp.async.commit_group;\n");
    asm volatile("cp.async.wait_group 0;\n");
    __syncthreads();

    float lsum0 = 0.f, lsum1 = 0.f;
    float O[8][4];
    #pragma unroll
    for (int n = 0; n < 8; n++)
        #pragma unroll
        for (int u = 0; u < 4; u++) O[n][u] = 0.f;

    const int nt = qb + 1;

    for (int t = 0; t < nt; t++) {
        const int kn0 = t * 64;
        if (t > 0) __syncthreads();   // PV t-1 done: V/P buffers free

        // ---- issue V_t planes ----
        #pragma unroll
        for (int rep = 0; rep < 4; rep++) {
            const int idx = rep*256 + tid;       // 0..1023
            const int d = idx >> 3, g = idx & 7;
            const int dst = d*32 + ((g ^ (d & 7)) << 2);
            const size_t src = vbase + (size_t)d*(SS/2) + (kn0 >> 1) + g*4;
            cpasync16u(smu + AVH + dst, g_vh + src);
            cpasync16u(smu + AVL + dst, g_vl + src);
        }
        asm volatile("cp.async.commit_group;\n");

        // ---- K_t ready (V_t still in flight) ----
        asm volatile("cp.async.wait_group 1;\n");
        __syncthreads();

        // ---- S = Q K^T (bf16 3-product): warp covers 4 n-frags (its half) ----
        float Sf[4][4];
        #pragma unroll
        for (int n = 0; n < 4; n++)
            #pragma unroll
            for (int u = 0; u < 4; u++) Sf[n][u] = 0.f;

        #pragma unroll
        for (int ch = 0; ch < 8; ch++) {
            const int p0 = ch*8 + qc, p1 = p0 + 4;
            const int r0 = wrow + qr, r1 = r0 + 8;
            uint32_t ah[4], al[4];
            ah[0] = smu[AQH + xsw(r0, p0, 64)];
            ah[1] = smu[AQH + xsw(r1, p0, 64)];
            ah[2] = smu[AQH + xsw(r0, p1, 64)];
            ah[3] = smu[AQH + xsw(r1, p1, 64)];
            al[0] = smu[AQL + xsw(r0, p0, 64)];
            al[1] = smu[AQL + xsw(r1, p0, 64)];
            al[2] = smu[AQL + xsw(r0, p1, 64)];
            al[3] = smu[AQL + xsw(r1, p1, 64)];
            #pragma unroll
            for (int nf = 0; nf < 4; nf++) {
                const int kr = (half*4 + nf)*8 + qr;
                uint32_t bh[2] = { smu[AKH + xsw(kr, p0, 64)],
                                   smu[AKH + xsw(kr, p1, 64)] };
                uint32_t bl[2] = { smu[AKL + xsw(kr, p0, 64)],
                                   smu[AKL + xsw(kr, p1, 64)] };
                mma_bf16(Sf[nf], ah, bh);
                mma_bf16(Sf[nf], al, bh);
                mma_bf16(Sf[nf], ah, bl);
            }
        }

        // ---- static-shift softmax: p = exp(s*scale - SHIFT), mask diag tile ----
        const bool maskt = (t == nt - 1);
        const int row0 = qm0 + wrow + qr, row1 = row0 + 8;
        #pragma unroll
        for (int nf = 0; nf < 4; nf++) {
            const int key0 = kn0 + (half*4 + nf)*8 + 2*qc;
            float p00 = __expf(fmaf(Sf[nf][0], scale, -SHIFTC));
            float p01 = __expf(fmaf(Sf[nf][1], scale, -SHIFTC));
            float p10 = __expf(fmaf(Sf[nf][2], scale, -SHIFTC));
            float p11 = __expf(fmaf(Sf[nf][3], scale, -SHIFTC));
            if (maskt) {
                if (key0     > row0) p00 = 0.f;
                if (key0 + 1 > row0) p01 = 0.f;
                if (key0     > row1) p10 = 0.f;
                if (key0 + 1 > row1) p11 = 0.f;
            }
            lsum0 += p00 + p01;
            lsum1 += p10 + p11;
            const int pp = (half*4 + nf)*4 + qc;   // pair column 0..31
            uint32_t hi, lo;
            splitbf(p00, p01, hi, lo);
            smu[APH + xsw(wrow + qr, pp, 32)] = hi;
            smu[APL + xsw(wrow + qr, pp, 32)] = lo;
            splitbf(p10, p11, hi, lo);
            smu[APH + xsw(wrow + qr + 8, pp, 32)] = hi;
            smu[APL + xsw(wrow + qr + 8, pp, 32)] = lo;
        }

        // ---- V_t ready; P visible after sync ----
        asm volatile("cp.async.wait_group 0;\n");
        __syncthreads();

        // ---- issue K_{t+1} planes (K buffer free: S done block-wide) ----
        if (t + 1 < nt) {
            #pragma unroll
            for (int rep = 0; rep < 4; rep++) {
                const int idx = rep*256 + tid;
                const int r = idx >> 4, g = idx & 15;
                const int dst = r*64 + ((g ^ (r & 7)) << 2);
                const size_t src = qkbase + (size_t)(kn0 + 64 + r)*64 + g*4;
                cpasync16u(smu + AKH + dst, g_kh + src);
                cpasync16u(smu + AKL + dst, g_kl + src);
            }
            asm volatile("cp.async.commit_group;\n");
        }

        // ---- O += P V (bf16 3-product): warp covers 8 d-frags (its half) ----
        // 64 keys = 32 P-pairs = 4 chunks of K=16  (ch < 4 — R6 bug was ch < 2)
        #pragma unroll
        for (int ch = 0; ch < 4; ch++) {
            const int p0 = ch*8 + qc, p1 = p0 + 4;
            const int r0 = wrow + qr, r1 = r0 + 8;
            uint32_t ah[4], al[4];
            ah[0] = smu[APH + xsw(r0, p0, 32)];
            ah[1] = smu[APH + xsw(r1, p0, 32)];
            ah[2] = smu[APH + xsw(r0, p1, 32)];
            ah[3] = smu[APH + xsw(r1, p1, 32)];
            al[0] = smu[APL + xsw(r0, p0, 32)];
            al[1] = smu[APL + xsw(r1, p0, 32)];
            al[2] = smu[APL + xsw(r0, p1, 32)];
            al[3] = smu[APL + xsw(r1, p1, 32)];
            #pragma unroll
            for (int nf = 0; nf < 8; nf++) {
                const int dr = (half*8 + nf)*8 + qr;
                uint32_t bh[2] = { smu[AVH + xsw(dr, p0, 32)],
                                   smu[AVH + xsw(dr, p1, 32)] };
                uint32_t bl[2] = { smu[AVL + xsw(dr, p0, 32)],
                                   smu[AVL + xsw(dr, p1, 32)] };
                mma_bf16(O[nf], ah, bh);
                mma_bf16(O[nf], al, bh);
                mma_bf16(O[nf], ah, bl);
            }
        }
    }

    // ---- epilogue: reduce l across quads and halves, write O/l ----
    lsum0 += __shfl_xor_sync(0xffffffffu, lsum0, 1);
    lsum0 += __shfl_xor_sync(0xffffffffu, lsum0, 2);
    lsum1 += __shfl_xor_sync(0xffffffffu, lsum1, 1);
    lsum1 += __shfl_xor_sync(0xffffffffu, lsum1, 2);
    __syncthreads();                 // PV done everywhere; safe to reuse smem
    if (qc == 0) {
        smf[ALRED + half*64 + wrow + qr]     = lsum0;
        smf[ALRED + half*64 + wrow + qr + 8] = lsum1;
    }
    __syncthreads();
    const float il0 = 1.0f / (smf[ALRED + wrow + qr] + smf[ALRED + 64 + wrow + qr]);
    const float il1 = 1.0f / (smf[ALRED + wrow + qr + 8] + smf[ALRED + 64 + wrow + qr + 8]);

    const size_t gr0 = (size_t)(b*SS + qm0 + wrow + qr);
    #pragma unroll
    for (int nf = 0; nf < 8; nf++) {
        const int col = h*DH + (half*8 + nf)*8 + 2*qc;
        *(float2*)(g_attn + gr0 * DD + col) =
            make_float2(O[nf][0]*il0, O[nf][1]*il0);
        *(float2*)(g_attn + (gr0 + 8) * DD + col) =
            make_float2(O[nf][2]*il1, O[nf][3]*il1);
    }
}

// ---------------------------------------------------------------------------
// RMSNorm over D=2048, in place. One 256-thread block per row.
// ---------------------------------------------------------------------------
__global__ __launch_bounds__(256) void rmsnorm_rows(const float* __restrict__ w)
{
    __shared__ float red[8];
    __shared__ float s_inv;
    float* p = g_attn + (size_t)blockIdx.x * DD;
    const int tid = threadIdx.x;

    float v[8];
    float ss = 0.f;
    #pragma unroll
    for (int k = 0; k < 8; k++) {
        const float x = p[tid + k*256];
        v[k] = x;
        ss += x * x;
    }
    #pragma unroll
    for (int o = 16; o > 0; o >>= 1) ss += __shfl_xor_sync(0xffffffffu, ss, o);
    if ((tid & 31) == 0) red[tid >> 5] = ss;
    __syncthreads();
    if (tid == 0) {
        float t = 0.f;
        #pragma unroll
        for (int i = 0; i < 8; i++) t += red[i];
        s_inv = rsqrtf(t * (1.0f / DD) + EPS);
    }
    __syncthreads();
    const float inv = s_inv;
    #pragma unroll
    for (int k = 0; k < 8; k++) {
        const int idx = tid + k*256;
        p[idx] = v[k] * inv * w[idx];
    }
}

// ---------------------------------------------------------------------------
extern "C" void kernel_launch(void* const* d_in, const int* in_sizes, int n_in,
                              void* d_out, int out_size)
{
    const float* x     = (const float*)d_in[0];
    const float* rp    = (const float*)d_in[1];
    const float* Win   = (const float*)d_in[2];
    const float* b_in  = (const float*)d_in[3];
    const float* Wout  = (const float*)d_in[4];
    const float* b_out = (const float*)d_in[5];
    const float* qk_w  = (const float*)d_in[6];
    const float* out_w = (const float*)d_in[7];
    float* out = (float*)d_out;

    float* qkv;  cudaGetSymbolAddress((void**)&qkv,  g_qkv);
    float* attn; cudaGetSymbolAddress((void**)&attn, g_attn);

    const int gemm_smem = 4 * TBUF * (int)sizeof(float);  // 73728 B
    cudaFuncSetAttribute(tf32_gemm_nt_bias,
                         cudaFuncAttributeMaxDynamicSharedMemorySize, gemm_smem);
    const int vsp_smem = 128 * 129 * (int)sizeof(float);  // 66048 B
    cudaFuncSetAttribute(v_split_t,
                         cudaFuncAttributeMaxDynamicSharedMemorySize, vsp_smem);
    cudaFuncSetAttribute(flash_attn_v2,
                         cudaFuncAttributeMaxDynamicSharedMemorySize, ASZ);

    // 1) qkv = x @ Win^T + b_in     [4096, 6144]
    {
        dim3 grid(TRIO / TBN, MM / TBM);
        tf32_gemm_nt_bias<<<grid, 256, gemm_smem>>>(x, Win, b_in, qkv, MM, TRIO, DD);
    }
    // 2a) RoPE + RMS on q,k -> split planes
    {
        const int warps = MM * HH * 2;
        rope_rms_split<<<warps / 8, 256>>>(rp, qk_w);
    }
    // 2b) v -> transposed split planes
    {
        dim3 grid(SS / 128, HH, BB);
        v_split_t<<<grid, 256, vsp_smem>>>();
    }
    // 3) flash attention -> g_attn
    {
        dim3 grid(SS / 64, HH, BB);
        flash_attn_v2<<<grid, 256, ASZ>>>();
    }
    // 4) RMSNorm over D (in place)
    rmsnorm_rows<<<MM, 256>>>(out_w);
    // 5) out = attn @ Wout^T + b_out
    {
        dim3 grid(DD / TBN, MM / TBM);
        tf32_gemm_nt_bias<<<grid, 256, gemm_smem>>>(attn, Wout, b_out, out, MM, DD, DD);
    }
}

// round 8
// speedup vs baseline: 3.0034x; 1.0794x over previous
#include <cuda_runtime.h>
#include <cuda_bf16.h>
#include <math.h>
#include <stdint.h>

// Problem constants
#define BB 2
#define SS 2048
#define DD 2048
#define HH 16
#define DH 128
#define MM (BB*SS)          // 4096
#define TRIO (3*DD)         // 6144
#define EPS 1e-6f

// Scratch (device globals; no allocation allowed)
__device__ float g_qkv[(size_t)MM * TRIO];   // 100.7 MB
__device__ float g_attn[(size_t)MM * DD];    // 33.6 MB
// Pre-split bf16x2 planes (hi/lo), packed 2 elems per u32.
__device__ uint32_t g_qh[(size_t)BB*HH*SS*64];
__device__ uint32_t g_ql[(size_t)BB*HH*SS*64];
__device__ uint32_t g_kh[(size_t)BB*HH*SS*64];
__device__ uint32_t g_kl[(size_t)BB*HH*SS*64];
__device__ uint32_t g_vh[(size_t)BB*HH*DH*(SS/2)];
__device__ uint32_t g_vl[(size_t)BB*HH*DH*(SS/2)];
// GEMM operand planes
__device__ uint32_t g_xh[(size_t)MM*(DD/2)];      // x
__device__ uint32_t g_xl[(size_t)MM*(DD/2)];
__device__ uint32_t g_wih[(size_t)TRIO*(DD/2)];   // Win
__device__ uint32_t g_wil[(size_t)TRIO*(DD/2)];
__device__ uint32_t g_woh[(size_t)DD*(DD/2)];     // Wout
__device__ uint32_t g_wol[(size_t)DD*(DD/2)];
__device__ uint32_t g_ah[(size_t)MM*(DD/2)];      // rmsnormed attn
__device__ uint32_t g_al[(size_t)MM*(DD/2)];

// ---------------------------------------------------------------------------
// Helpers
// ---------------------------------------------------------------------------
__device__ __forceinline__ void cpasync16u(uint32_t* s, const uint32_t* g) {
    uint32_t sa = (uint32_t)__cvta_generic_to_shared(s);
    asm volatile("cp.async.cg.shared.global [%0], [%1], 16;" :: "r"(sa), "l"(g));
}
__device__ __forceinline__ void mma_bf16(float c[4], const uint32_t a[4], const uint32_t b[2]) {
    asm volatile(
        "mma.sync.aligned.m16n8k16.row.col.f32.bf16.bf16.f32 "
        "{%0,%1,%2,%3}, {%4,%5,%6,%7}, {%8,%9}, {%0,%1,%2,%3};"
        : "+f"(c[0]), "+f"(c[1]), "+f"(c[2]), "+f"(c[3])
        : "r"(a[0]), "r"(a[1]), "r"(a[2]), "r"(a[3]), "r"(b[0]), "r"(b[1]));
}
// split two floats into packed bf16x2 (hi) and packed bf16x2 residual (lo)
__device__ __forceinline__ void splitbf(float x0, float x1, uint32_t& hi, uint32_t& lo) {
    __nv_bfloat162 hp = __floats2bfloat162_rn(x0, x1);
    float r0 = x0 - __bfloat162float(hp.x);
    float r1 = x1 - __bfloat162float(hp.y);
    __nv_bfloat162 lp = __floats2bfloat162_rn(r0, r1);
    hi = *reinterpret_cast<uint32_t*>(&hp);
    lo = *reinterpret_cast<uint32_t*>(&lp);
}
// 16B-granule XOR swizzle (u32 units), row length 64 u32 (attention tiles)
__device__ __forceinline__ int xsw(int r, int p, int rowu) {
    return r*rowu + ((((p >> 2) ^ (r & 7)) << 2) | (p & 3));
}
// 16B-granule XOR swizzle (u32 units), row length 16 u32 (GEMM k-tiles)
__device__ __forceinline__ int gsw(int r, int p) {
    return r*16 + ((((p >> 2) ^ ((r >> 1) & 3)) << 2) | (p & 3));
}

// ---------------------------------------------------------------------------
// Generic fp32 -> packed bf16x2 hi/lo plane split. One thread per float4.
// ---------------------------------------------------------------------------
__global__ __launch_bounds__(256) void split_plane(
    const float* __restrict__ src, uint32_t* __restrict__ ph,
    uint32_t* __restrict__ pl)
{
    const size_t i = (size_t)blockIdx.x * 256 + threadIdx.x;
    const float4 v = *(const float4*)(src + i*4);
    uint32_t h0, l0, h1, l1;
    splitbf(v.x, v.y, h0, l0);
    splitbf(v.z, v.w, h1, l1);
    ph[2*i]     = h0;
    ph[2*i + 1] = h1;
    pl[2*i]     = l0;
    pl[2*i + 1] = l1;
}

// ---------------------------------------------------------------------------
// bf16 3-product tensor-core GEMM: C[M,N] = A[M,K] @ W[N,K]^T + bias[N].
// Operands pre-split into packed bf16x2 hi/lo planes (Ku = K/2 u32 per row).
// 128x128 block, k-tile 32 elems (16 u32), 256 threads, double-buffered
// cp.async, warp tile 64x32.
// ---------------------------------------------------------------------------
#define GBUF 8192   // u32 per buffer: AH/AL/BH/BL x 2048

__global__ __launch_bounds__(256, 2) void bf16x3_gemm_nt_bias(
    const uint32_t* __restrict__ Ah, const uint32_t* __restrict__ Al,
    const uint32_t* __restrict__ Bh, const uint32_t* __restrict__ Bl,
    const float* __restrict__ bias, float* __restrict__ C,
    int M, int N, int Ku)
{
    extern __shared__ uint32_t sm[];

    const int tid = threadIdx.x;
    const int bm0 = blockIdx.y * 128;
    const int bn0 = blockIdx.x * 128;
    const int warp = tid >> 5, lane = tid & 31;
    const int wm0 = (warp >> 2) * 64;
    const int wn0 = (warp & 3) * 32;
    const int qr = lane >> 2, qc = lane & 3;

    // cp.async mapping: idx = rep*256 + tid -> row r = idx>>2 (0..127),
    // granule g = idx&3. dst swizzle g^((r>>1)&3); note (r+64) keeps same xor.
    const int lr = tid >> 2;            // 0..63 (rep adds 64)
    const int lg = tid & 3;
    const int d0 = lr*16 + ((lg ^ ((lr >> 1) & 3)) << 2);
    const int d1 = d0 + 64*16;
    const uint32_t* Ag0 = Ah + (size_t)(bm0 + lr) * Ku + lg*4;
    const uint32_t* Ag1 = Ah + (size_t)(bm0 + lr + 64) * Ku + lg*4;
    const uint32_t* Al0 = Al + (size_t)(bm0 + lr) * Ku + lg*4;
    const uint32_t* Al1 = Al + (size_t)(bm0 + lr + 64) * Ku + lg*4;
    const uint32_t* Bg0 = Bh + (size_t)(bn0 + lr) * Ku + lg*4;
    const uint32_t* Bg1 = Bh + (size_t)(bn0 + lr + 64) * Ku + lg*4;
    const uint32_t* Bl0 = Bl + (size_t)(bn0 + lr) * Ku + lg*4;
    const uint32_t* Bl1 = Bl + (size_t)(bn0 + lr + 64) * Ku + lg*4;

    float acc[4][4][4];
    #pragma unroll
    for (int i = 0; i < 4; i++)
        #pragma unroll
        for (int j = 0; j < 4; j++)
            #pragma unroll
            for (int u = 0; u < 4; u++) acc[i][j][u] = 0.f;

    const int nk = Ku / 16;   // 64 k-tiles

    // prologue: buffer 0
    {
        uint32_t* B0 = sm;
        cpasync16u(B0 + d0,          Ag0);
        cpasync16u(B0 + d1,          Ag1);
        cpasync16u(B0 + 2048 + d0,   Al0);
        cpasync16u(B0 + 2048 + d1,   Al1);
        cpasync16u(B0 + 4096 + d0,   Bg0);
        cpasync16u(B0 + 4096 + d1,   Bg1);
        cpasync16u(B0 + 6144 + d0,   Bl0);
        cpasync16u(B0 + 6144 + d1,   Bl1);
    }
    asm volatile("cp.async.commit_group;\n");

    for (int kt = 0; kt < nk; kt++) {
        if (kt + 1 < nk) {
            uint32_t* Bn = sm + ((kt + 1) & 1) * GBUF;
            const int ko = (kt + 1) * 16;
            cpasync16u(Bn + d0,        Ag0 + ko);
            cpasync16u(Bn + d1,        Ag1 + ko);
            cpasync16u(Bn + 2048 + d0, Al0 + ko);
            cpasync16u(Bn + 2048 + d1, Al1 + ko);
            cpasync16u(Bn + 4096 + d0, Bg0 + ko);
            cpasync16u(Bn + 4096 + d1, Bg1 + ko);
            cpasync16u(Bn + 6144 + d0, Bl0 + ko);
            cpasync16u(Bn + 6144 + d1, Bl1 + ko);
            asm volatile("cp.async.commit_group;\n");
            asm volatile("cp.async.wait_group 1;\n");
        } else {
            asm volatile("cp.async.wait_group 0;\n");
        }
        __syncthreads();

        const uint32_t* AH = sm + (kt & 1) * GBUF;
        const uint32_t* AL = AH + 2048;
        const uint32_t* BH = AH + 4096;
        const uint32_t* BL = AH + 6144;

        #pragma unroll
        for (int ch = 0; ch < 2; ch++) {
            const int p0 = ch*8 + qc, p1 = p0 + 4;
            uint32_t ah[4][4], al[4][4];
            #pragma unroll
            for (int im = 0; im < 4; im++) {
                const int r0 = wm0 + im*16 + qr, r1 = r0 + 8;
                ah[im][0] = AH[gsw(r0, p0)];
                ah[im][1] = AH[gsw(r1, p0)];
                ah[im][2] = AH[gsw(r0, p1)];
                ah[im][3] = AH[gsw(r1, p1)];
                al[im][0] = AL[gsw(r0, p0)];
                al[im][1] = AL[gsw(r1, p0)];
                al[im][2] = AL[gsw(r0, p1)];
                al[im][3] = AL[gsw(r1, p1)];
            }
            #pragma unroll
            for (int in = 0; in < 4; in++) {
                const int kr = wn0 + in*8 + qr;
                uint32_t bh[2] = { BH[gsw(kr, p0)], BH[gsw(kr, p1)] };
                uint32_t bl[2] = { BL[gsw(kr, p0)], BL[gsw(kr, p1)] };
                #pragma unroll
                for (int im = 0; im < 4; im++) {
                    mma_bf16(acc[im][in], ah[im], bh);
                    mma_bf16(acc[im][in], al[im], bh);
                    mma_bf16(acc[im][in], ah[im], bl);
                }
            }
        }
        __syncthreads();
    }

    // epilogue: C = acc + bias
    #pragma unroll
    for (int im = 0; im < 4; im++) {
        #pragma unroll
        for (int in = 0; in < 4; in++) {
            const int r0 = bm0 + wm0 + im*16 + qr;
            const int c0 = bn0 + wn0 + in*8 + qc*2;
            const float2 b2 = *(const float2*)(bias + c0);
            float2 v;
            v.x = acc[im][in][0] + b2.x; v.y = acc[im][in][1] + b2.y;
            *(float2*)(C + (size_t)r0 * N + c0) = v;
            v.x = acc[im][in][2] + b2.x; v.y = acc[im][in][3] + b2.y;
            *(float2*)(C + (size_t)(r0 + 8) * N + c0) = v;
        }
    }
}

// ---------------------------------------------------------------------------
// RoPE + RMSNorm for q,k; writes pre-split bf16 hi/lo planes.
// One warp per (m, which, h).
// ---------------------------------------------------------------------------
__global__ __launch_bounds__(256) void rope_rms_split(
    const float* __restrict__ rp, const float* __restrict__ qk_w)
{
    const int w = blockIdx.x * 8 + (threadIdx.x >> 5);
    const int lane = threadIdx.x & 31;
    const int h = w % HH;
    const int t = w / HH;
    const int which = t & 1;          // 0=q, 1=k
    const int m = t >> 1;             // 0..4095
    const int s = m & (SS - 1);
    const int b = m >> 11;

    const float* base = g_qkv + (size_t)m * TRIO + which * DD + h * DH;
    const float* ang = rp + s * (DH/2);

    float r[4];
    float ss = 0.f;
    #pragma unroll
    for (int u = 0; u < 2; u++) {
        const int p = lane + u * 32;
        const float a = ang[p];
        const float c = cosf(a), sn = sinf(a);
        const float x0 = base[2*p], x1 = base[2*p+1];
        const float r0 = x0 * c - x1 * sn;
        const float r1 = x0 * sn + x1 * c;
        r[2*u] = r0; r[2*u+1] = r1;
        ss += r0*r0 + r1*r1;
    }
    #pragma unroll
    for (int o = 16; o > 0; o >>= 1) ss += __shfl_xor_sync(0xffffffffu, ss, o);
    const float inv = rsqrtf(ss * (1.0f / DH) + EPS);

    const float o0 = r[0] * inv * qk_w[2*lane];
    const float o1 = r[1] * inv * qk_w[2*lane + 1];
    const float o2 = r[2] * inv * qk_w[2*(lane+32)];
    const float o3 = r[3] * inv * qk_w[2*(lane+32) + 1];
    uint32_t h0, l0, h1, l1;
    splitbf(o0, o1, h0, l0);
    splitbf(o2, o3, h1, l1);

    const size_t pb = ((size_t)(b*HH + h)*SS + s) * 64;
    uint32_t* ph = which ? g_kh : g_qh;
    uint32_t* pl = which ? g_kl : g_ql;
    ph[pb + lane]      = h0;
    ph[pb + lane + 32] = h1;
    pl[pb + lane]      = l0;
    pl[pb + lane + 32] = l1;
}

// ---------------------------------------------------------------------------
// V split + transpose: g_qkv v -> g_vh/g_vl [b][h][d][s2].
// ---------------------------------------------------------------------------
__global__ __launch_bounds__(256) void v_split_t()
{
    extern __shared__ float vt[];     // [128][129]
    const int sc = blockIdx.x, h = blockIdx.y, b = blockIdx.z;
    const int tid = threadIdx.x;

    #pragma unroll
    for (int rep = 0; rep < 16; rep++) {
        const int idx = rep*256 + tid;
        const int r = idx >> 5, c4 = (idx & 31) * 4;
        const float4 v = *(const float4*)(g_qkv +
            (size_t)(b*SS + sc*128 + r)*TRIO + 2*DD + h*DH + c4);
        vt[r*129 + c4 + 0] = v.x; vt[r*129 + c4 + 1] = v.y;
        vt[r*129 + c4 + 2] = v.z; vt[r*129 + c4 + 3] = v.w;
    }
    __syncthreads();

    #pragma unroll
    for (int rep = 0; rep < 32; rep++) {
        const int idx = rep*256 + tid;
        const int d = idx >> 6, j2 = idx & 63;
        const float x0 = vt[(2*j2)*129 + d];
        const float x1 = vt[(2*j2 + 1)*129 + d];
        uint32_t hi, lo;
        splitbf(x0, x1, hi, lo);
        const size_t o = ((size_t)(b*HH + h)*DH + d)*(SS/2) + sc*64 + j2;
        g_vh[o] = hi;
        g_vl[o] = lo;
    }
}

// ---------------------------------------------------------------------------
// Flash attention v2 (unchanged from R7 pass).
// ---------------------------------------------------------------------------
#define AQH 0
#define AQL 4096
#define AKH 8192
#define AKL 12288
#define AVH 16384
#define AVL 20480
#define APH 24576
#define APL 26624
#define ALRED 28672
#define ASZ ((28672 + 128) * 4)     // 115200 B
#define SHIFTC 11.32f

__global__ __launch_bounds__(256, 2) void flash_attn_v2()
{
    extern __shared__ uint32_t smu[];
    float* smf = reinterpret_cast<float*>(smu);

    const int qb = (int)(gridDim.x - 1 - blockIdx.x);
    const int qm0 = qb * 64;
    const int h = blockIdx.y, b = blockIdx.z;
    const int tid = threadIdx.x;
    const int warp = tid >> 5, lane = tid & 31;
    const int qr = lane >> 2, qc = lane & 3;
    const int half = warp & 1;
    const int wrow = (warp >> 1) * 16;

    const size_t qkbase = (size_t)(b*HH + h) * SS * 64;
    const size_t vbase  = (size_t)(b*HH + h) * DH * (SS/2);
    const float scale = 0.08838834764831845f;

    #pragma unroll
    for (int rep = 0; rep < 4; rep++) {
        const int idx = rep*256 + tid;
        const int r = idx >> 4, g = idx & 15;
        const int dst = r*64 + ((g ^ (r & 7)) << 2);
        const size_t qsrc = qkbase + (size_t)(qm0 + r)*64 + g*4;
        const size_t ksrc = qkbase + (size_t)r*64 + g*4;
        cpasync16u(smu + AQH + dst, g_qh + qsrc);
        cpasync16u(smu + AQL + dst, g_ql + qsrc);
        cpasync16u(smu + AKH + dst, g_kh + ksrc);
        cpasync16u(smu + AKL + dst, g_kl + ksrc);
    }
    asm volatile("cp.async.commit_group;\n");
    asm volatile("cp.async.wait_group 0;\n");
    __syncthreads();

    float lsum0 = 0.f, lsum1 = 0.f;
    float O[8][4];
    #pragma unroll
    for (int n = 0; n < 8; n++)
        #pragma unroll
        for (int u = 0; u < 4; u++) O[n][u] = 0.f;

    const int nt = qb + 1;

    for (int t = 0; t < nt; t++) {
        const int kn0 = t * 64;
        if (t > 0) __syncthreads();

        #pragma unroll
        for (int rep = 0; rep < 4; rep++) {
            const int idx = rep*256 + tid;
            const int d = idx >> 3, g = idx & 7;
            const int dst = d*32 + ((g ^ (d & 7)) << 2);
            const size_t src = vbase + (size_t)d*(SS/2) + (kn0 >> 1) + g*4;
            cpasync16u(smu + AVH + dst, g_vh + src);
            cpasync16u(smu + AVL + dst, g_vl + src);
        }
        asm volatile("cp.async.commit_group;\n");

        asm volatile("cp.async.wait_group 1;\n");
        __syncthreads();

        float Sf[4][4];
        #pragma unroll
        for (int n = 0; n < 4; n++)
            #pragma unroll
            for (int u = 0; u < 4; u++) Sf[n][u] = 0.f;

        #pragma unroll
        for (int ch = 0; ch < 8; ch++) {
            const int p0 = ch*8 + qc, p1 = p0 + 4;
            const int r0 = wrow + qr, r1 = r0 + 8;
            uint32_t ah[4], al[4];
            ah[0] = smu[AQH + xsw(r0, p0, 64)];
            ah[1] = smu[AQH + xsw(r1, p0, 64)];
            ah[2] = smu[AQH + xsw(r0, p1, 64)];
            ah[3] = smu[AQH + xsw(r1, p1, 64)];
            al[0] = smu[AQL + xsw(r0, p0, 64)];
            al[1] = smu[AQL + xsw(r1, p0, 64)];
            al[2] = smu[AQL + xsw(r0, p1, 64)];
            al[3] = smu[AQL + xsw(r1, p1, 64)];
            #pragma unroll
            for (int nf = 0; nf < 4; nf++) {
                const int kr = (half*4 + nf)*8 + qr;
                uint32_t bh[2] = { smu[AKH + xsw(kr, p0, 64)],
                                   smu[AKH + xsw(kr, p1, 64)] };
                uint32_t bl[2] = { smu[AKL + xsw(kr, p0, 64)],
                                   smu[AKL + xsw(kr, p1, 64)] };
                mma_bf16(Sf[nf], ah, bh);
                mma_bf16(Sf[nf], al, bh);
                mma_bf16(Sf[nf], ah, bl);
            }
        }

        const bool maskt = (t == nt - 1);
        const int row0 = qm0 + wrow + qr, row1 = row0 + 8;
        #pragma unroll
        for (int nf = 0; nf < 4; nf++) {
            const int key0 = kn0 + (half*4 + nf)*8 + 2*qc;
            float p00 = __expf(fmaf(Sf[nf][0], scale, -SHIFTC));
            float p01 = __expf(fmaf(Sf[nf][1], scale, -SHIFTC));
            float p10 = __expf(fmaf(Sf[nf][2], scale, -SHIFTC));
            float p11 = __expf(fmaf(Sf[nf][3], scale, -SHIFTC));
            if (maskt) {
                if (key0     > row0) p00 = 0.f;
                if (key0 + 1 > row0) p01 = 0.f;
                if (key0     > row1) p10 = 0.f;
                if (key0 + 1 > row1) p11 = 0.f;
            }
            lsum0 += p00 + p01;
            lsum1 += p10 + p11;
            const int pp = (half*4 + nf)*4 + qc;
            uint32_t hi, lo;
            splitbf(p00, p01, hi, lo);
            smu[APH + xsw(wrow + qr, pp, 32)] = hi;
            smu[APL + xsw(wrow + qr, pp, 32)] = lo;
            splitbf(p10, p11, hi, lo);
            smu[APH + xsw(wrow + qr + 8, pp, 32)] = hi;
            smu[APL + xsw(wrow + qr + 8, pp, 32)] = lo;
        }

        asm volatile("cp.async.wait_group 0;\n");
        __syncthreads();

        if (t + 1 < nt) {
            #pragma unroll
            for (int rep = 0; rep < 4; rep++) {
                const int idx = rep*256 + tid;
                const int r = idx >> 4, g = idx & 15;
                const int dst = r*64 + ((g ^ (r & 7)) << 2);
                const size_t src = qkbase + (size_t)(kn0 + 64 + r)*64 + g*4;
                cpasync16u(smu + AKH + dst, g_kh + src);
                cpasync16u(smu + AKL + dst, g_kl + src);
            }
            asm volatile("cp.async.commit_group;\n");
        }

        #pragma unroll
        for (int ch = 0; ch < 4; ch++) {
            const int p0 = ch*8 + qc, p1 = p0 + 4;
            const int r0 = wrow + qr, r1 = r0 + 8;
            uint32_t ah[4], al[4];
            ah[0] = smu[APH + xsw(r0, p0, 32)];
            ah[1] = smu[APH + xsw(r1, p0, 32)];
            ah[2] = smu[APH + xsw(r0, p1, 32)];
            ah[3] = smu[APH + xsw(r1, p1, 32)];
            al[0] = smu[APL + xsw(r0, p0, 32)];
            al[1] = smu[APL + xsw(r1, p0, 32)];
            al[2] = smu[APL + xsw(r0, p1, 32)];
            al[3] = smu[APL + xsw(r1, p1, 32)];
            #pragma unroll
            for (int nf = 0; nf < 8; nf++) {
                const int dr = (half*8 + nf)*8 + qr;
                uint32_t bh[2] = { smu[AVH + xsw(dr, p0, 32)],
                                   smu[AVH + xsw(dr, p1, 32)] };
                uint32_t bl[2] = { smu[AVL + xsw(dr, p0, 32)],
                                   smu[AVL + xsw(dr, p1, 32)] };
                mma_bf16(O[nf], ah, bh);
                mma_bf16(O[nf], al, bh);
                mma_bf16(O[nf], ah, bl);
            }
        }
    }

    lsum0 += __shfl_xor_sync(0xffffffffu, lsum0, 1);
    lsum0 += __shfl_xor_sync(0xffffffffu, lsum0, 2);
    lsum1 += __shfl_xor_sync(0xffffffffu, lsum1, 1);
    lsum1 += __shfl_xor_sync(0xffffffffu, lsum1, 2);
    __syncthreads();
    if (qc == 0) {
        smf[ALRED + half*64 + wrow + qr]     = lsum0;
        smf[ALRED + half*64 + wrow + qr + 8] = lsum1;
    }
    __syncthreads();
    const float il0 = 1.0f / (smf[ALRED + wrow + qr] + smf[ALRED + 64 + wrow + qr]);
    const float il1 = 1.0f / (smf[ALRED + wrow + qr + 8] + smf[ALRED + 64 + wrow + qr + 8]);

    const size_t gr0 = (size_t)(b*SS + qm0 + wrow + qr);
    #pragma unroll
    for (int nf = 0; nf < 8; nf++) {
        const int col = h*DH + (half*8 + nf)*8 + 2*qc;
        *(float2*)(g_attn + gr0 * DD + col) =
            make_float2(O[nf][0]*il0, O[nf][1]*il0);
        *(float2*)(g_attn + (gr0 + 8) * DD + col) =
            make_float2(O[nf][2]*il1, O[nf][3]*il1);
    }
}

// ---------------------------------------------------------------------------
// RMSNorm over D=2048 + split to bf16 hi/lo planes. One block per row.
// Each thread owns 8 contiguous elems.
// ---------------------------------------------------------------------------
__global__ __launch_bounds__(256) void rmsnorm_split_rows(const float* __restrict__ w)
{
    __shared__ float red[8];
    __shared__ float s_inv;
    const float* p = g_attn + (size_t)blockIdx.x * DD;
    const int tid = threadIdx.x;
    const int base = tid * 8;

    float v[8];
    {
        const float4 a = *(const float4*)(p + base);
        const float4 b = *(const float4*)(p + base + 4);
        v[0]=a.x; v[1]=a.y; v[2]=a.z; v[3]=a.w;
        v[4]=b.x; v[5]=b.y; v[6]=b.z; v[7]=b.w;
    }
    float ss = 0.f;
    #pragma unroll
    for (int k = 0; k < 8; k++) ss += v[k]*v[k];
    #pragma unroll
    for (int o = 16; o > 0; o >>= 1) ss += __shfl_xor_sync(0xffffffffu, ss, o);
    if ((tid & 31) == 0) red[tid >> 5] = ss;
    __syncthreads();
    if (tid == 0) {
        float t = 0.f;
        #pragma unroll
        for (int i = 0; i < 8; i++) t += red[i];
        s_inv = rsqrtf(t * (1.0f / DD) + EPS);
    }
    __syncthreads();
    const float inv = s_inv;
    const size_t ob = (size_t)blockIdx.x * (DD/2) + base/2;
    #pragma unroll
    for (int u = 0; u < 4; u++) {
        const float x0 = v[2*u]   * inv * w[base + 2*u];
        const float x1 = v[2*u+1] * inv * w[base + 2*u + 1];
        uint32_t hi, lo;
        splitbf(x0, x1, hi, lo);
        g_ah[ob + u] = hi;
        g_al[ob + u] = lo;
    }
}

// ---------------------------------------------------------------------------
extern "C" void kernel_launch(void* const* d_in, const int* in_sizes, int n_in,
                              void* d_out, int out_size)
{
    const float* x     = (const float*)d_in[0];
    const float* rp    = (const float*)d_in[1];
    const float* Win   = (const float*)d_in[2];
    const float* b_in  = (const float*)d_in[3];
    const float* Wout  = (const float*)d_in[4];
    const float* b_out = (const float*)d_in[5];
    const float* qk_w  = (const float*)d_in[6];
    const float* out_w = (const float*)d_in[7];
    float* out = (float*)d_out;

    float* qkv;  cudaGetSymbolAddress((void**)&qkv,  g_qkv);
    uint32_t *xh, *xl, *wih, *wil, *woh, *wol, *ah, *al;
    cudaGetSymbolAddress((void**)&xh,  g_xh);
    cudaGetSymbolAddress((void**)&xl,  g_xl);
    cudaGetSymbolAddress((void**)&wih, g_wih);
    cudaGetSymbolAddress((void**)&wil, g_wil);
    cudaGetSymbolAddress((void**)&woh, g_woh);
    cudaGetSymbolAddress((void**)&wol, g_wol);
    cudaGetSymbolAddress((void**)&ah,  g_ah);
    cudaGetSymbolAddress((void**)&al,  g_al);

    const int gemm_smem = 2 * GBUF * (int)sizeof(uint32_t);   // 65536 B
    cudaFuncSetAttribute(bf16x3_gemm_nt_bias,
                         cudaFuncAttributeMaxDynamicSharedMemorySize, gemm_smem);
    const int vsp_smem = 128 * 129 * (int)sizeof(float);      // 66048 B
    cudaFuncSetAttribute(v_split_t,
                         cudaFuncAttributeMaxDynamicSharedMemorySize, vsp_smem);
    cudaFuncSetAttribute(flash_attn_v2,
                         cudaFuncAttributeMaxDynamicSharedMemorySize, ASZ);

    // 0) split inputs into bf16 hi/lo planes
    split_plane<<<(MM*DD)/1024, 256>>>(x, xh, xl);
    split_plane<<<(TRIO*DD)/1024, 256>>>(Win, wih, wil);
    split_plane<<<(DD*DD)/1024, 256>>>(Wout, woh, wol);

    // 1) qkv = x @ Win^T + b_in   [4096, 6144]
    {
        dim3 grid(TRIO / 128, MM / 128);
        bf16x3_gemm_nt_bias<<<grid, 256, gemm_smem>>>(
            xh, xl, wih, wil, b_in, qkv, MM, TRIO, DD/2);
    }
    // 2a) RoPE + RMS on q,k -> split planes
    {
        const int warps = MM * HH * 2;
        rope_rms_split<<<warps / 8, 256>>>(rp, qk_w);
    }
    // 2b) v -> transposed split planes
    {
        dim3 grid(SS / 128, HH, BB);
        v_split_t<<<grid, 256, vsp_smem>>>();
    }
    // 3) flash attention -> g_attn
    {
        dim3 grid(SS / 64, HH, BB);
        flash_attn_v2<<<grid, 256, ASZ>>>();
    }
    // 4) RMSNorm + split -> g_ah/g_al
    rmsnorm_split_rows<<<MM, 256>>>(out_w);
    // 5) out = attn @ Wout^T + b_out
    {
        dim3 grid(DD / 128, MM / 128);
        bf16x3_gemm_nt_bias<<<grid, 256, gemm_smem>>>(
            ah, al, woh, wol, b_out, out, MM, DD, DD/2);
    }
}

// round 12
// speedup vs baseline: 5.2368x; 1.7436x over previous
#include <cuda_runtime.h>
#include <cuda_bf16.h>
#include <cuda_fp16.h>
#include <math.h>
#include <stdint.h>

// Problem constants
#define BB 2
#define SS 2048
#define DD 2048
#define HH 16
#define DH 128
#define MM (BB*SS)          // 4096
#define TRIO (3*DD)         // 6144
#define EPS 1e-6f

// Scratch (device globals; no allocation allowed)
__device__ float g_qkv[(size_t)MM * TRIO];   // 100.7 MB
__device__ float g_attn[(size_t)MM * DD];    // 33.6 MB
// Attention pre-split bf16x2 planes (hi/lo), packed 2 elems per u32.
__device__ uint32_t g_qh[(size_t)BB*HH*SS*64];
__device__ uint32_t g_ql[(size_t)BB*HH*SS*64];
__device__ uint32_t g_kh[(size_t)BB*HH*SS*64];
__device__ uint32_t g_kl[(size_t)BB*HH*SS*64];
__device__ uint32_t g_vh[(size_t)BB*HH*DH*(SS/2)];
__device__ uint32_t g_vl[(size_t)BB*HH*DH*(SS/2)];
// GEMM operand planes: packed fp16x2, single plane
__device__ uint32_t g_xf[(size_t)MM*(DD/2)];      // x
__device__ uint32_t g_wif[(size_t)TRIO*(DD/2)];   // Win
__device__ uint32_t g_wof[(size_t)DD*(DD/2)];     // Wout
__device__ uint32_t g_af[(size_t)MM*(DD/2)];      // rmsnormed attn

// ---------------------------------------------------------------------------
// Helpers
// ---------------------------------------------------------------------------
__device__ __forceinline__ void cpasync16u(uint32_t* s, const uint32_t* g) {
    uint32_t sa = (uint32_t)__cvta_generic_to_shared(s);
    asm volatile("cp.async.cg.shared.global [%0], [%1], 16;" :: "r"(sa), "l"(g));
}
__device__ __forceinline__ void mma_bf16(float c[4], const uint32_t a[4], const uint32_t b[2]) {
    asm volatile(
        "mma.sync.aligned.m16n8k16.row.col.f32.bf16.bf16.f32 "
        "{%0,%1,%2,%3}, {%4,%5,%6,%7}, {%8,%9}, {%0,%1,%2,%3};"
        : "+f"(c[0]), "+f"(c[1]), "+f"(c[2]), "+f"(c[3])
        : "r"(a[0]), "r"(a[1]), "r"(a[2]), "r"(a[3]), "r"(b[0]), "r"(b[1]));
}
__device__ __forceinline__ void mma_f16(float c[4], const uint32_t a[4], const uint32_t b[2]) {
    asm volatile(
        "mma.sync.aligned.m16n8k16.row.col.f32.f16.f16.f32 "
        "{%0,%1,%2,%3}, {%4,%5,%6,%7}, {%8,%9}, {%0,%1,%2,%3};"
        : "+f"(c[0]), "+f"(c[1]), "+f"(c[2]), "+f"(c[3])
        : "r"(a[0]), "r"(a[1]), "r"(a[2]), "r"(a[3]), "r"(b[0]), "r"(b[1]));
}
// split two floats into packed bf16x2 (hi) and packed bf16x2 residual (lo)
__device__ __forceinline__ void splitbf(float x0, float x1, uint32_t& hi, uint32_t& lo) {
    __nv_bfloat162 hp = __floats2bfloat162_rn(x0, x1);
    float r0 = x0 - __bfloat162float(hp.x);
    float r1 = x1 - __bfloat162float(hp.y);
    __nv_bfloat162 lp = __floats2bfloat162_rn(r0, r1);
    hi = *reinterpret_cast<uint32_t*>(&hp);
    lo = *reinterpret_cast<uint32_t*>(&lp);
}
__device__ __forceinline__ uint32_t packf16(float x0, float x1) {
    __half2 hp = __floats2half2_rn(x0, x1);
    return *reinterpret_cast<uint32_t*>(&hp);
}
// 16B-granule XOR swizzle (u32 units), attention tiles (row length rowu)
__device__ __forceinline__ int xsw(int r, int p, int rowu) {
    return r*rowu + ((((p >> 2) ^ (r & 7)) << 2) | (p & 3));
}
// 16B-granule XOR swizzle, GEMM k-tile rows of 32 u32
__device__ __forceinline__ int gsw2(int r, int p) {
    return r*32 + ((((p >> 2) ^ (r & 7)) << 2) | (p & 3));
}

// ---------------------------------------------------------------------------
// fp32 -> packed fp16x2 plane. One thread per float4.
// ---------------------------------------------------------------------------
__global__ __launch_bounds__(256) void split_plane_f16(
    const float* __restrict__ src, uint32_t* __restrict__ pf)
{
    const size_t i = (size_t)blockIdx.x * 256 + threadIdx.x;
    const float4 v = *(const float4*)(src + i*4);
    pf[2*i]     = packf16(v.x, v.y);
    pf[2*i + 1] = packf16(v.z, v.w);
}

// ---------------------------------------------------------------------------
// Single-product fp16 tensor-core GEMM: C[M,N] = A[M,K] @ W[N,K]^T + bias[N].
// Operands packed fp16x2 (Ku = K/2 u32 per row). 128x128 block, k-tile 64
// elems (32 u32), 256 threads, double-buffered cp.async, warp tile 64x32.
// ---------------------------------------------------------------------------
#define GKU 32                 // u32 per row per k-tile
#define GBUF (128*GKU*2)       // A + B per buffer = 8192 u32 (32 KB)

__global__ __launch_bounds__(256, 2) void f16_gemm_nt_bias(
    const uint32_t* __restrict__ A, const uint32_t* __restrict__ B,
    const float* __restrict__ bias, float* __restrict__ C,
    int M, int N, int Ku)
{
    extern __shared__ uint32_t sm[];

    const int tid = threadIdx.x;
    const int bm0 = blockIdx.y * 128;
    const int bn0 = blockIdx.x * 128;
    const int warp = tid >> 5, lane = tid & 31;
    const int wm0 = (warp >> 2) * 64;
    const int wn0 = (warp & 3) * 32;
    const int qr = lane >> 2, qc = lane & 3;

    // cp.async mapping: 8 x 16B per thread per buffer (4 A rows, 4 B rows)
    const int lr = tid >> 3;            // 0..31 (reps add 32/64/96)
    const int lg = tid & 7;             // granule 0..7
    const uint32_t* Agp = A + (size_t)(bm0 + lr) * Ku + lg*4;
    const uint32_t* Bgp = B + (size_t)(bn0 + lr) * Ku + lg*4;
    const size_t rstep = (size_t)32 * Ku;
    int dsts[4];
    #pragma unroll
    for (int rep = 0; rep < 4; rep++) {
        const int r = lr + rep*32;
        dsts[rep] = r*32 + ((lg ^ (r & 7)) << 2);
    }

    float acc[4][4][4];
    #pragma unroll
    for (int i = 0; i < 4; i++)
        #pragma unroll
        for (int j = 0; j < 4; j++)
            #pragma unroll
            for (int u = 0; u < 4; u++) acc[i][j][u] = 0.f;

    const int nk = Ku / GKU;   // 32

    // prologue
    #pragma unroll
    for (int rep = 0; rep < 4; rep++) {
        cpasync16u(sm + dsts[rep],             Agp + rep*rstep);
        cpasync16u(sm + 4096 + dsts[rep],      Bgp + rep*rstep);
    }
    asm volatile("cp.async.commit_group;\n");

    for (int kt = 0; kt < nk; kt++) {
        if (kt + 1 < nk) {
            uint32_t* Bn = sm + ((kt + 1) & 1) * GBUF;
            const int ko = (kt + 1) * GKU;
            #pragma unroll
            for (int rep = 0; rep < 4; rep++) {
                cpasync16u(Bn + dsts[rep],        Agp + ko + rep*rstep);
                cpasync16u(Bn + 4096 + dsts[rep], Bgp + ko + rep*rstep);
            }
            asm volatile("cp.async.commit_group;\n");
            asm volatile("cp.async.wait_group 1;\n");
        } else {
            asm volatile("cp.async.wait_group 0;\n");
        }
        __syncthreads();

        const uint32_t* AS = sm + (kt & 1) * GBUF;
        const uint32_t* BS = AS + 4096;

        #pragma unroll
        for (int ch = 0; ch < 4; ch++) {
            const int p0 = ch*8 + qc, p1 = p0 + 4;
            uint32_t af[4][4];
            #pragma unroll
            for (int im = 0; im < 4; im++) {
                const int r0 = wm0 + im*16 + qr, r1 = r0 + 8;
                af[im][0] = AS[gsw2(r0, p0)];
                af[im][1] = AS[gsw2(r1, p0)];
                af[im][2] = AS[gsw2(r0, p1)];
                af[im][3] = AS[gsw2(r1, p1)];
            }
            #pragma unroll
            for (int in = 0; in < 4; in++) {
                const int kr = wn0 + in*8 + qr;
                uint32_t bf[2] = { BS[gsw2(kr, p0)], BS[gsw2(kr, p1)] };
                #pragma unroll
                for (int im = 0; im < 4; im++)
                    mma_f16(acc[im][in], af[im], bf);
            }
        }
        __syncthreads();
    }

    // epilogue: C = acc + bias
    #pragma unroll
    for (int im = 0; im < 4; im++) {
        #pragma unroll
        for (int in = 0; in < 4; in++) {
            const int r0 = bm0 + wm0 + im*16 + qr;
            const int c0 = bn0 + wn0 + in*8 + qc*2;
            const float2 b2 = *(const float2*)(bias + c0);
            float2 v;
            v.x = acc[im][in][0] + b2.x; v.y = acc[im][in][1] + b2.y;
            *(float2*)(C + (size_t)r0 * N + c0) = v;
            v.x = acc[im][in][2] + b2.x; v.y = acc[im][in][3] + b2.y;
            *(float2*)(C + (size_t)(r0 + 8) * N + c0) = v;
        }
    }
}

// ---------------------------------------------------------------------------
// RoPE + RMSNorm for q,k; writes pre-split bf16 hi/lo planes.
// One warp per (m, which, h).
// ---------------------------------------------------------------------------
__global__ __launch_bounds__(256) void rope_rms_split(
    const float* __restrict__ rp, const float* __restrict__ qk_w)
{
    const int w = blockIdx.x * 8 + (threadIdx.x >> 5);
    const int lane = threadIdx.x & 31;
    const int h = w % HH;
    const int t = w / HH;
    const int which = t & 1;          // 0=q, 1=k
    const int m = t >> 1;             // 0..4095
    const int s = m & (SS - 1);
    const int b = m >> 11;

    const float* base = g_qkv + (size_t)m * TRIO + which * DD + h * DH;
    const float* ang = rp + s * (DH/2);

    float r[4];
    float ss = 0.f;
    #pragma unroll
    for (int u = 0; u < 2; u++) {
        const int p = lane + u * 32;
        const float a = ang[p];
        const float c = cosf(a), sn = sinf(a);
        const float x0 = base[2*p], x1 = base[2*p+1];
        const float r0 = x0 * c - x1 * sn;
        const float r1 = x0 * sn + x1 * c;
        r[2*u] = r0; r[2*u+1] = r1;
        ss += r0*r0 + r1*r1;
    }
    #pragma unroll
    for (int o = 16; o > 0; o >>= 1) ss += __shfl_xor_sync(0xffffffffu, ss, o);
    const float inv = rsqrtf(ss * (1.0f / DH) + EPS);

    const float o0 = r[0] * inv * qk_w[2*lane];
    const float o1 = r[1] * inv * qk_w[2*lane + 1];
    const float o2 = r[2] * inv * qk_w[2*(lane+32)];
    const float o3 = r[3] * inv * qk_w[2*(lane+32) + 1];
    uint32_t h0, l0, h1, l1;
    splitbf(o0, o1, h0, l0);
    splitbf(o2, o3, h1, l1);

    const size_t pb = ((size_t)(b*HH + h)*SS + s) * 64;
    uint32_t* ph = which ? g_kh : g_qh;
    uint32_t* pl = which ? g_kl : g_ql;
    ph[pb + lane]      = h0;
    ph[pb + lane + 32] = h1;
    pl[pb + lane]      = l0;
    pl[pb + lane + 32] = l1;
}

// ---------------------------------------------------------------------------
// V split + transpose: g_qkv v -> g_vh/g_vl [b][h][d][s2].
// ---------------------------------------------------------------------------
__global__ __launch_bounds__(256) void v_split_t()
{
    extern __shared__ float vt[];     // [128][129]
    const int sc = blockIdx.x, h = blockIdx.y, b = blockIdx.z;
    const int tid = threadIdx.x;

    #pragma unroll
    for (int rep = 0; rep < 16; rep++) {
        const int idx = rep*256 + tid;
        const int r = idx >> 5, c4 = (idx & 31) * 4;
        const float4 v = *(const float4*)(g_qkv +
            (size_t)(b*SS + sc*128 + r)*TRIO + 2*DD + h*DH + c4);
        vt[r*129 + c4 + 0] = v.x; vt[r*129 + c4 + 1] = v.y;
        vt[r*129 + c4 + 2] = v.z; vt[r*129 + c4 + 3] = v.w;
    }
    __syncthreads();

    #pragma unroll
    for (int rep = 0; rep < 32; rep++) {
        const int idx = rep*256 + tid;
        const int d = idx >> 6, j2 = idx & 63;
        const float x0 = vt[(2*j2)*129 + d];
        const float x1 = vt[(2*j2 + 1)*129 + d];
        uint32_t hi, lo;
        splitbf(x0, x1, hi, lo);
        const size_t o = ((size_t)(b*HH + h)*DH + d)*(SS/2) + sc*64 + j2;
        g_vh[o] = hi;
        g_vl[o] = lo;
    }
}

// ---------------------------------------------------------------------------
// Flash attention v2 (unchanged; bf16 3-product, static-shift softmax).
// ---------------------------------------------------------------------------
#define AQH 0
#define AQL 4096
#define AKH 8192
#define AKL 12288
#define AVH 16384
#define AVL 20480
#define APH 24576
#define APL 26624
#define ALRED 28672
#define ASZ ((28672 + 128) * 4)     // 115200 B
#define SHIFTC 11.32f

__global__ __launch_bounds__(256, 2) void flash_attn_v2()
{
    extern __shared__ uint32_t smu[];
    float* smf = reinterpret_cast<float*>(smu);

    const int qb = (int)(gridDim.x - 1 - blockIdx.x);
    const int qm0 = qb * 64;
    const int h = blockIdx.y, b = blockIdx.z;
    const int tid = threadIdx.x;
    const int warp = tid >> 5, lane = tid & 31;
    const int qr = lane >> 2, qc = lane & 3;
    const int half = warp & 1;
    const int wrow = (warp >> 1) * 16;

    const size_t qkbase = (size_t)(b*HH + h) * SS * 64;
    const size_t vbase  = (size_t)(b*HH + h) * DH * (SS/2);
    const float scale = 0.08838834764831845f;

    #pragma unroll
    for (int rep = 0; rep < 4; rep++) {
        const int idx = rep*256 + tid;
        const int r = idx >> 4, g = idx & 15;
        const int dst = r*64 + ((g ^ (r & 7)) << 2);
        const size_t qsrc = qkbase + (size_t)(qm0 + r)*64 + g*4;
        const size_t ksrc = qkbase + (size_t)r*64 + g*4;
        cpasync16u(smu + AQH + dst, g_qh + qsrc);
        cpasync16u(smu + AQL + dst, g_ql + qsrc);
        cpasync16u(smu + AKH + dst, g_kh + ksrc);
        cpasync16u(smu + AKL + dst, g_kl + ksrc);
    }
    asm volatile("cp.async.commit_group;\n");
    asm volatile("cp.async.wait_group 0;\n");
    __syncthreads();

    float lsum0 = 0.f, lsum1 = 0.f;
    float O[8][4];
    #pragma unroll
    for (int n = 0; n < 8; n++)
        #pragma unroll
        for (int u = 0; u < 4; u++) O[n][u] = 0.f;

    const int nt = qb + 1;

    for (int t = 0; t < nt; t++) {
        const int kn0 = t * 64;
        if (t > 0) __syncthreads();

        #pragma unroll
        for (int rep = 0; rep < 4; rep++) {
            const int idx = rep*256 + tid;
            const int d = idx >> 3, g = idx & 7;
            const int dst = d*32 + ((g ^ (d & 7)) << 2);
            const size_t src = vbase + (size_t)d*(SS/2) + (kn0 >> 1) + g*4;
            cpasync16u(smu + AVH + dst, g_vh + src);
            cpasync16u(smu + AVL + dst, g_vl + src);
        }
        asm volatile("cp.async.commit_group;\n");

        asm volatile("cp.async.wait_group 1;\n");
        __syncthreads();

        float Sf[4][4];
        #pragma unroll
        for (int n = 0; n < 4; n++)
            #pragma unroll
            for (int u = 0; u < 4; u++) Sf[n][u] = 0.f;

        #pragma unroll
        for (int ch = 0; ch < 8; ch++) {
            const int p0 = ch*8 + qc, p1 = p0 + 4;
            const int r0 = wrow + qr, r1 = r0 + 8;
            uint32_t ah[4], al[4];
            ah[0] = smu[AQH + xsw(r0, p0, 64)];
            ah[1] = smu[AQH + xsw(r1, p0, 64)];
            ah[2] = smu[AQH + xsw(r0, p1, 64)];
            ah[3] = smu[AQH + xsw(r1, p1, 64)];
            al[0] = smu[AQL + xsw(r0, p0, 64)];
            al[1] = smu[AQL + xsw(r1, p0, 64)];
            al[2] = smu[AQL + xsw(r0, p1, 64)];
            al[3] = smu[AQL + xsw(r1, p1, 64)];
            #pragma unroll
            for (int nf = 0; nf < 4; nf++) {
                const int kr = (half*4 + nf)*8 + qr;
                uint32_t bh[2] = { smu[AKH + xsw(kr, p0, 64)],
                                   smu[AKH + xsw(kr, p1, 64)] };
                uint32_t bl[2] = { smu[AKL + xsw(kr, p0, 64)],
                                   smu[AKL + xsw(kr, p1, 64)] };
                mma_bf16(Sf[nf], ah, bh);
                mma_bf16(Sf[nf], al, bh);
                mma_bf16(Sf[nf], ah, bl);
            }
        }

        const bool maskt = (t == nt - 1);
        const int row0 = qm0 + wrow + qr, row1 = row0 + 8;
        #pragma unroll
        for (int nf = 0; nf < 4; nf++) {
            const int key0 = kn0 + (half*4 + nf)*8 + 2*qc;
            float p00 = __expf(fmaf(Sf[nf][0], scale, -SHIFTC));
            float p01 = __expf(fmaf(Sf[nf][1], scale, -SHIFTC));
            float p10 = __expf(fmaf(Sf[nf][2], scale, -SHIFTC));
            float p11 = __expf(fmaf(Sf[nf][3], scale, -SHIFTC));
            if (maskt) {
                if (key0     > row0) p00 = 0.f;
                if (key0 + 1 > row0) p01 = 0.f;
                if (key0     > row1) p10 = 0.f;
                if (key0 + 1 > row1) p11 = 0.f;
            }
            lsum0 += p00 + p01;
            lsum1 += p10 + p11;
            const int pp = (half*4 + nf)*4 + qc;
            uint32_t hi, lo;
            splitbf(p00, p01, hi, lo);
            smu[APH + xsw(wrow + qr, pp, 32)] = hi;
            smu[APL + xsw(wrow + qr, pp, 32)] = lo;
            splitbf(p10, p11, hi, lo);
            smu[APH + xsw(wrow + qr + 8, pp, 32)] = hi;
            smu[APL + xsw(wrow + qr + 8, pp, 32)] = lo;
        }

        asm volatile("cp.async.wait_group 0;\n");
        __syncthreads();

        if (t + 1 < nt) {
            #pragma unroll
            for (int rep = 0; rep < 4; rep++) {
                const int idx = rep*256 + tid;
                const int r = idx >> 4, g = idx & 15;
                const int dst = r*64 + ((g ^ (r & 7)) << 2);
                const size_t src = qkbase + (size_t)(kn0 + 64 + r)*64 + g*4;
                cpasync16u(smu + AKH + dst, g_kh + src);
                cpasync16u(smu + AKL + dst, g_kl + src);
            }
            asm volatile("cp.async.commit_group;\n");
        }

        #pragma unroll
        for (int ch = 0; ch < 4; ch++) {
            const int p0 = ch*8 + qc, p1 = p0 + 4;
            const int r0 = wrow + qr, r1 = r0 + 8;
            uint32_t ah[4], al[4];
            ah[0] = smu[APH + xsw(r0, p0, 32)];
            ah[1] = smu[APH + xsw(r1, p0, 32)];
            ah[2] = smu[APH + xsw(r0, p1, 32)];
            ah[3] = smu[APH + xsw(r1, p1, 32)];
            al[0] = smu[APL + xsw(r0, p0, 32)];
            al[1] = smu[APL + xsw(r1, p0, 32)];
            al[2] = smu[APL + xsw(r0, p1, 32)];
            al[3] = smu[APL + xsw(r1, p1, 32)];
            #pragma unroll
            for (int nf = 0; nf < 8; nf++) {
                const int dr = (half*8 + nf)*8 + qr;
                uint32_t bh[2] = { smu[AVH + xsw(dr, p0, 32)],
                                   smu[AVH + xsw(dr, p1, 32)] };
                uint32_t bl[2] = { smu[AVL + xsw(dr, p0, 32)],
                                   smu[AVL + xsw(dr, p1, 32)] };
                mma_bf16(O[nf], ah, bh);
                mma_bf16(O[nf], al, bh);
                mma_bf16(O[nf], ah, bl);
            }
        }
    }

    lsum0 += __shfl_xor_sync(0xffffffffu, lsum0, 1);
    lsum0 += __shfl_xor_sync(0xffffffffu, lsum0, 2);
    lsum1 += __shfl_xor_sync(0xffffffffu, lsum1, 1);
    lsum1 += __shfl_xor_sync(0xffffffffu, lsum1, 2);
    __syncthreads();
    if (qc == 0) {
        smf[ALRED + half*64 + wrow + qr]     = lsum0;
        smf[ALRED + half*64 + wrow + qr + 8] = lsum1;
    }
    __syncthreads();
    const float il0 = 1.0f / (smf[ALRED + wrow + qr] + smf[ALRED + 64 + wrow + qr]);
    const float il1 = 1.0f / (smf[ALRED + wrow + qr + 8] + smf[ALRED + 64 + wrow + qr + 8]);

    const size_t gr0 = (size_t)(b*SS + qm0 + wrow + qr);
    #pragma unroll
    for (int nf = 0; nf < 8; nf++) {
        const int col = h*DH + (half*8 + nf)*8 + 2*qc;
        *(float2*)(g_attn + gr0 * DD + col) =
            make_float2(O[nf][0]*il0, O[nf][1]*il0);
        *(float2*)(g_attn + (gr0 + 8) * DD + col) =
            make_float2(O[nf][2]*il1, O[nf][3]*il1);
    }
}

// ---------------------------------------------------------------------------
// RMSNorm over D=2048 + pack to fp16 plane. One block per row.
// ---------------------------------------------------------------------------
__global__ __launch_bounds__(256) void rmsnorm_pack_rows(const float* __restrict__ w)
{
    __shared__ float red[8];
    __shared__ float s_inv;
    const float* p = g_attn + (size_t)blockIdx.x * DD;
    const int tid = threadIdx.x;
    const int base = tid * 8;

    float v[8];
    {
        const float4 a = *(const float4*)(p + base);
        const float4 b = *(const float4*)(p + base + 4);
        v[0]=a.x; v[1]=a.y; v[2]=a.z; v[3]=a.w;
        v[4]=b.x; v[5]=b.y; v[6]=b.z; v[7]=b.w;
    }
    float ss = 0.f;
    #pragma unroll
    for (int k = 0; k < 8; k++) ss += v[k]*v[k];
    #pragma unroll
    for (int o = 16; o > 0; o >>= 1) ss += __shfl_xor_sync(0xffffffffu, ss, o);
    if ((tid & 31) == 0) red[tid >> 5] = ss;
    __syncthreads();
    if (tid == 0) {
        float t = 0.f;
        #pragma unroll
        for (int i = 0; i < 8; i++) t += red[i];
        s_inv = rsqrtf(t * (1.0f / DD) + EPS);
    }
    __syncthreads();
    const float inv = s_inv;
    const size_t ob = (size_t)blockIdx.x * (DD/2) + base/2;
    #pragma unroll
    for (int u = 0; u < 4; u++) {
        const float x0 = v[2*u]   * inv * w[base + 2*u];
        const float x1 = v[2*u+1] * inv * w[base + 2*u + 1];
        g_af[ob + u] = packf16(x0, x1);
    }
}

// ---------------------------------------------------------------------------
extern "C" void kernel_launch(void* const* d_in, const int* in_sizes, int n_in,
                              void* d_out, int out_size)
{
    const float* x     = (const float*)d_in[0];
    const float* rp    = (const float*)d_in[1];
    const float* Win   = (const float*)d_in[2];
    const float* b_in  = (const float*)d_in[3];
    const float* Wout  = (const float*)d_in[4];
    const float* b_out = (const float*)d_in[5];
    const float* qk_w  = (const float*)d_in[6];
    const float* out_w = (const float*)d_in[7];
    float* out = (float*)d_out;

    float* qkv;  cudaGetSymbolAddress((void**)&qkv,  g_qkv);
    uint32_t *xf, *wif, *wof, *af;
    cudaGetSymbolAddress((void**)&xf,  g_xf);
    cudaGetSymbolAddress((void**)&wif, g_wif);
    cudaGetSymbolAddress((void**)&wof, g_wof);
    cudaGetSymbolAddress((void**)&af,  g_af);

    const int gemm_smem = 2 * GBUF * (int)sizeof(uint32_t);   // 65536 B
    cudaFuncSetAttribute(f16_gemm_nt_bias,
                         cudaFuncAttributeMaxDynamicSharedMemorySize, gemm_smem);
    const int vsp_smem = 128 * 129 * (int)sizeof(float);      // 66048 B
    cudaFuncSetAttribute(v_split_t,
                         cudaFuncAttributeMaxDynamicSharedMemorySize, vsp_smem);
    cudaFuncSetAttribute(flash_attn_v2,
                         cudaFuncAttributeMaxDynamicSharedMemorySize, ASZ);

    // 0) pack inputs to fp16 planes
    split_plane_f16<<<(MM*DD)/1024, 256>>>(x, xf);
    split_plane_f16<<<(TRIO*DD)/1024, 256>>>(Win, wif);
    split_plane_f16<<<(DD*DD)/1024, 256>>>(Wout, wof);

    // 1) qkv = x @ Win^T + b_in   [4096, 6144]
    {
        dim3 grid(TRIO / 128, MM / 128);
        f16_gemm_nt_bias<<<grid, 256, gemm_smem>>>(
            xf, wif, b_in, qkv, MM, TRIO, DD/2);
    }
    // 2a) RoPE + RMS on q,k -> bf16 hi/lo planes
    {
        const int warps = MM * HH * 2;
        rope_rms_split<<<warps / 8, 256>>>(rp, qk_w);
    }
    // 2b) v -> transposed bf16 hi/lo planes
    {
        dim3 grid(SS / 128, HH, BB);
        v_split_t<<<grid, 256, vsp_smem>>>();
    }
    // 3) flash attention -> g_attn
    {
        dim3 grid(SS / 64, HH, BB);
        flash_attn_v2<<<grid, 256, ASZ>>>();
    }
    // 4) RMSNorm + pack -> g_af
    rmsnorm_pack_rows<<<MM, 256>>>(out_w);
    // 5) out = attn @ Wout^T + b_out
    {
        dim3 grid(DD / 128, MM / 128);
        f16_gemm_nt_bias<<<grid, 256, gemm_smem>>>(
            af, wof, b_out, out, MM, DD, DD/2);
    }
}

// round 13
// speedup vs baseline: 6.5630x; 1.2532x over previous
#include <cuda_runtime.h>
#include <cuda_bf16.h>
#include <cuda_fp16.h>
#include <math.h>
#include <stdint.h>

// Problem constants
#define BB 2
#define SS 2048
#define DD 2048
#define HH 16
#define DH 128
#define MM (BB*SS)          // 4096
#define TRIO (3*DD)         // 6144
#define EPS 1e-6f

// Scratch (device globals; no allocation allowed)
__device__ float g_qkv[(size_t)MM * TRIO];   // 100.7 MB
__device__ float g_attn[(size_t)MM * DD];    // 33.6 MB
// Attention pre-split bf16x2 planes (hi/lo), packed 2 elems per u32.
__device__ uint32_t g_qh[(size_t)BB*HH*SS*64];
__device__ uint32_t g_ql[(size_t)BB*HH*SS*64];
__device__ uint32_t g_kh[(size_t)BB*HH*SS*64];
__device__ uint32_t g_kl[(size_t)BB*HH*SS*64];
__device__ uint32_t g_vh[(size_t)BB*HH*DH*(SS/2)];
__device__ uint32_t g_vl[(size_t)BB*HH*DH*(SS/2)];
// GEMM operand planes: packed fp16x2, single plane
__device__ uint32_t g_xf[(size_t)MM*(DD/2)];      // x
__device__ uint32_t g_wif[(size_t)TRIO*(DD/2)];   // Win
__device__ uint32_t g_wof[(size_t)DD*(DD/2)];     // Wout
__device__ uint32_t g_af[(size_t)MM*(DD/2)];      // rmsnormed attn

// ---------------------------------------------------------------------------
// Helpers
// ---------------------------------------------------------------------------
__device__ __forceinline__ void cpasync16u(uint32_t* s, const uint32_t* g) {
    uint32_t sa = (uint32_t)__cvta_generic_to_shared(s);
    asm volatile("cp.async.cg.shared.global [%0], [%1], 16;" :: "r"(sa), "l"(g));
}
__device__ __forceinline__ void mma_bf16(float c[4], const uint32_t a[4], const uint32_t b[2]) {
    asm volatile(
        "mma.sync.aligned.m16n8k16.row.col.f32.bf16.bf16.f32 "
        "{%0,%1,%2,%3}, {%4,%5,%6,%7}, {%8,%9}, {%0,%1,%2,%3};"
        : "+f"(c[0]), "+f"(c[1]), "+f"(c[2]), "+f"(c[3])
        : "r"(a[0]), "r"(a[1]), "r"(a[2]), "r"(a[3]), "r"(b[0]), "r"(b[1]));
}
__device__ __forceinline__ void mma_f16(float c[4], const uint32_t a[4], const uint32_t b[2]) {
    asm volatile(
        "mma.sync.aligned.m16n8k16.row.col.f32.f16.f16.f32 "
        "{%0,%1,%2,%3}, {%4,%5,%6,%7}, {%8,%9}, {%0,%1,%2,%3};"
        : "+f"(c[0]), "+f"(c[1]), "+f"(c[2]), "+f"(c[3])
        : "r"(a[0]), "r"(a[1]), "r"(a[2]), "r"(a[3]), "r"(b[0]), "r"(b[1]));
}
__device__ __forceinline__ void ldm_x4(uint32_t d[4], uint32_t saddr) {
    asm volatile("ldmatrix.sync.aligned.m8n8.x4.shared.b16 {%0,%1,%2,%3}, [%4];"
        : "=r"(d[0]), "=r"(d[1]), "=r"(d[2]), "=r"(d[3]) : "r"(saddr));
}
// split two floats into packed bf16x2 (hi) and packed bf16x2 residual (lo)
__device__ __forceinline__ void splitbf(float x0, float x1, uint32_t& hi, uint32_t& lo) {
    __nv_bfloat162 hp = __floats2bfloat162_rn(x0, x1);
    float r0 = x0 - __bfloat162float(hp.x);
    float r1 = x1 - __bfloat162float(hp.y);
    __nv_bfloat162 lp = __floats2bfloat162_rn(r0, r1);
    hi = *reinterpret_cast<uint32_t*>(&hp);
    lo = *reinterpret_cast<uint32_t*>(&lp);
}
__device__ __forceinline__ uint32_t packf16(float x0, float x1) {
    __half2 hp = __floats2half2_rn(x0, x1);
    return *reinterpret_cast<uint32_t*>(&hp);
}
// 16B-granule XOR swizzle (u32 units), attention tiles (row length rowu)
__device__ __forceinline__ int xsw(int r, int p, int rowu) {
    return r*rowu + ((((p >> 2) ^ (r & 7)) << 2) | (p & 3));
}

// ---------------------------------------------------------------------------
// fp32 -> packed fp16x2 plane. One thread per float4.
// ---------------------------------------------------------------------------
__global__ __launch_bounds__(256) void split_plane_f16(
    const float* __restrict__ src, uint32_t* __restrict__ pf)
{
    const size_t i = (size_t)blockIdx.x * 256 + threadIdx.x;
    const float4 v = *(const float4*)(src + i*4);
    pf[2*i]     = packf16(v.x, v.y);
    pf[2*i + 1] = packf16(v.z, v.w);
}

// ---------------------------------------------------------------------------
// Single-product fp16 tensor-core GEMM with ldmatrix fragment loads.
// C[M,N] = A[M,K] @ W[N,K]^T + bias[N]. Operands packed fp16x2.
// 128x128 block, k-tile 64 elems (32 u32), 256 threads, warp tile 64x32.
// ---------------------------------------------------------------------------
#define GKU 32                 // u32 per row per k-tile
#define GBUF (128*GKU*2)       // A + B per buffer = 8192 u32 (32 KB)

__global__ __launch_bounds__(256, 2) void f16_gemm_nt_bias(
    const uint32_t* __restrict__ A, const uint32_t* __restrict__ B,
    const float* __restrict__ bias, float* __restrict__ C,
    int M, int N, int Ku)
{
    extern __shared__ uint32_t sm[];
    const uint32_t sbase = (uint32_t)__cvta_generic_to_shared(sm);

    const int tid = threadIdx.x;
    const int bm0 = blockIdx.y * 128;
    const int bn0 = blockIdx.x * 128;
    const int warp = tid >> 5, lane = tid & 31;
    const int wm0 = (warp >> 2) * 64;
    const int wn0 = (warp & 3) * 32;
    const int qr = lane >> 2, qc = lane & 3;
    // ldmatrix per-thread row/granule selectors
    const int lt15 = lane & 15, lt7 = lane & 7;
    const int asel = lane >> 4;           // A-type granule offset
    const int brow = lane >> 4;           // B-type pair-row offset
    const int bsel = (lane >> 3) & 1;     // B-type granule offset

    // cp.async mapping: 8 x 16B per thread per buffer (4 A rows, 4 B rows)
    const int lr = tid >> 3;            // 0..31 (reps add 32/64/96)
    const int lg = tid & 7;             // granule 0..7
    const uint32_t* Agp = A + (size_t)(bm0 + lr) * Ku + lg*4;
    const uint32_t* Bgp = B + (size_t)(bn0 + lr) * Ku + lg*4;
    const size_t rstep = (size_t)32 * Ku;
    int dsts[4];
    #pragma unroll
    for (int rep = 0; rep < 4; rep++) {
        const int r = lr + rep*32;
        dsts[rep] = r*32 + ((lg ^ (r & 7)) << 2);
    }

    float acc[4][4][4];
    #pragma unroll
    for (int i = 0; i < 4; i++)
        #pragma unroll
        for (int j = 0; j < 4; j++)
            #pragma unroll
            for (int u = 0; u < 4; u++) acc[i][j][u] = 0.f;

    const int nk = Ku / GKU;   // 32

    // prologue
    #pragma unroll
    for (int rep = 0; rep < 4; rep++) {
        cpasync16u(sm + dsts[rep],             Agp + rep*rstep);
        cpasync16u(sm + 4096 + dsts[rep],      Bgp + rep*rstep);
    }
    asm volatile("cp.async.commit_group;\n");

    for (int kt = 0; kt < nk; kt++) {
        if (kt + 1 < nk) {
            uint32_t* Bn = sm + ((kt + 1) & 1) * GBUF;
            const int ko = (kt + 1) * GKU;
            #pragma unroll
            for (int rep = 0; rep < 4; rep++) {
                cpasync16u(Bn + dsts[rep],        Agp + ko + rep*rstep);
                cpasync16u(Bn + 4096 + dsts[rep], Bgp + ko + rep*rstep);
            }
            asm volatile("cp.async.commit_group;\n");
            asm volatile("cp.async.wait_group 1;\n");
        } else {
            asm volatile("cp.async.wait_group 0;\n");
        }
        __syncthreads();

        const uint32_t abuf = sbase + ((kt & 1) * GBUF) * 4;
        const uint32_t bbuf = abuf + 4096 * 4;

        #pragma unroll
        for (int ch = 0; ch < 4; ch++) {
            uint32_t af[4][4];
            #pragma unroll
            for (int im = 0; im < 4; im++) {
                const int row = wm0 + im*16 + lt15;
                const int gr  = 2*ch + asel;
                ldm_x4(af[im], abuf + 4*(row*32 + ((gr ^ (row & 7)) << 2)));
            }
            uint32_t bf[2][4];
            #pragma unroll
            for (int ip = 0; ip < 2; ip++) {
                const int nrow = wn0 + (ip*2 + brow)*8 + lt7;
                const int gr = 2*ch + bsel;
                ldm_x4(bf[ip], bbuf + 4*(nrow*32 + ((gr ^ (nrow & 7)) << 2)));
            }
            #pragma unroll
            for (int in = 0; in < 4; in++) {
                uint32_t bb[2] = { bf[in>>1][(in&1)*2], bf[in>>1][(in&1)*2 + 1] };
                #pragma unroll
                for (int im = 0; im < 4; im++)
                    mma_f16(acc[im][in], af[im], bb);
            }
        }
        __syncthreads();
    }

    // epilogue: C = acc + bias
    #pragma unroll
    for (int im = 0; im < 4; im++) {
        #pragma unroll
        for (int in = 0; in < 4; in++) {
            const int r0 = bm0 + wm0 + im*16 + qr;
            const int c0 = bn0 + wn0 + in*8 + qc*2;
            const float2 b2 = *(const float2*)(bias + c0);
            float2 v;
            v.x = acc[im][in][0] + b2.x; v.y = acc[im][in][1] + b2.y;
            *(float2*)(C + (size_t)r0 * N + c0) = v;
            v.x = acc[im][in][2] + b2.x; v.y = acc[im][in][3] + b2.y;
            *(float2*)(C + (size_t)(r0 + 8) * N + c0) = v;
        }
    }
}

// ---------------------------------------------------------------------------
// RoPE + RMSNorm for q,k; writes pre-split bf16 hi/lo planes.
// One warp per (m, which, h).
// ---------------------------------------------------------------------------
__global__ __launch_bounds__(256) void rope_rms_split(
    const float* __restrict__ rp, const float* __restrict__ qk_w)
{
    const int w = blockIdx.x * 8 + (threadIdx.x >> 5);
    const int lane = threadIdx.x & 31;
    const int h = w % HH;
    const int t = w / HH;
    const int which = t & 1;          // 0=q, 1=k
    const int m = t >> 1;             // 0..4095
    const int s = m & (SS - 1);
    const int b = m >> 11;

    const float* base = g_qkv + (size_t)m * TRIO + which * DD + h * DH;
    const float* ang = rp + s * (DH/2);

    float r[4];
    float ss = 0.f;
    #pragma unroll
    for (int u = 0; u < 2; u++) {
        const int p = lane + u * 32;
        const float a = ang[p];
        const float c = cosf(a), sn = sinf(a);
        const float x0 = base[2*p], x1 = base[2*p+1];
        const float r0 = x0 * c - x1 * sn;
        const float r1 = x0 * sn + x1 * c;
        r[2*u] = r0; r[2*u+1] = r1;
        ss += r0*r0 + r1*r1;
    }
    #pragma unroll
    for (int o = 16; o > 0; o >>= 1) ss += __shfl_xor_sync(0xffffffffu, ss, o);
    const float inv = rsqrtf(ss * (1.0f / DH) + EPS);

    const float o0 = r[0] * inv * qk_w[2*lane];
    const float o1 = r[1] * inv * qk_w[2*lane + 1];
    const float o2 = r[2] * inv * qk_w[2*(lane+32)];
    const float o3 = r[3] * inv * qk_w[2*(lane+32) + 1];
    uint32_t h0, l0, h1, l1;
    splitbf(o0, o1, h0, l0);
    splitbf(o2, o3, h1, l1);

    const size_t pb = ((size_t)(b*HH + h)*SS + s) * 64;
    uint32_t* ph = which ? g_kh : g_qh;
    uint32_t* pl = which ? g_kl : g_ql;
    ph[pb + lane]      = h0;
    ph[pb + lane + 32] = h1;
    pl[pb + lane]      = l0;
    pl[pb + lane + 32] = l1;
}

// ---------------------------------------------------------------------------
// V split + transpose: g_qkv v -> g_vh/g_vl [b][h][d][s2].
// ---------------------------------------------------------------------------
__global__ __launch_bounds__(256) void v_split_t()
{
    extern __shared__ float vt[];     // [128][129]
    const int sc = blockIdx.x, h = blockIdx.y, b = blockIdx.z;
    const int tid = threadIdx.x;

    #pragma unroll
    for (int rep = 0; rep < 16; rep++) {
        const int idx = rep*256 + tid;
        const int r = idx >> 5, c4 = (idx & 31) * 4;
        const float4 v = *(const float4*)(g_qkv +
            (size_t)(b*SS + sc*128 + r)*TRIO + 2*DD + h*DH + c4);
        vt[r*129 + c4 + 0] = v.x; vt[r*129 + c4 + 1] = v.y;
        vt[r*129 + c4 + 2] = v.z; vt[r*129 + c4 + 3] = v.w;
    }
    __syncthreads();

    #pragma unroll
    for (int rep = 0; rep < 32; rep++) {
        const int idx = rep*256 + tid;
        const int d = idx >> 6, j2 = idx & 63;
        const float x0 = vt[(2*j2)*129 + d];
        const float x1 = vt[(2*j2 + 1)*129 + d];
        uint32_t hi, lo;
        splitbf(x0, x1, hi, lo);
        const size_t o = ((size_t)(b*HH + h)*DH + d)*(SS/2) + sc*64 + j2;
        g_vh[o] = hi;
        g_vl[o] = lo;
    }
}

// ---------------------------------------------------------------------------
// Flash attention v3: bf16 3-product with ldmatrix fragment loads.
// ---------------------------------------------------------------------------
#define AQH 0
#define AQL 4096
#define AKH 8192
#define AKL 12288
#define AVH 16384
#define AVL 20480
#define APH 24576
#define APL 26624
#define ALRED 28672
#define ASZ ((28672 + 128) * 4)     // 115200 B
#define SHIFTC 11.32f

__global__ __launch_bounds__(256, 2) void flash_attn_v2()
{
    extern __shared__ uint32_t smu[];
    float* smf = reinterpret_cast<float*>(smu);
    const uint32_t sb = (uint32_t)__cvta_generic_to_shared(smu);

    const int qb = (int)(gridDim.x - 1 - blockIdx.x);
    const int qm0 = qb * 64;
    const int h = blockIdx.y, b = blockIdx.z;
    const int tid = threadIdx.x;
    const int warp = tid >> 5, lane = tid & 31;
    const int qr = lane >> 2, qc = lane & 3;
    const int half = warp & 1;
    const int wrow = (warp >> 1) * 16;
    const int lt15 = lane & 15, lt7 = lane & 7;
    const int asel = lane >> 4;
    const int brow = lane >> 4;
    const int bsel = (lane >> 3) & 1;

    const size_t qkbase = (size_t)(b*HH + h) * SS * 64;
    const size_t vbase  = (size_t)(b*HH + h) * DH * (SS/2);
    const float scale = 0.08838834764831845f;

    #pragma unroll
    for (int rep = 0; rep < 4; rep++) {
        const int idx = rep*256 + tid;
        const int r = idx >> 4, g = idx & 15;
        const int dst = r*64 + ((g ^ (r & 7)) << 2);
        const size_t qsrc = qkbase + (size_t)(qm0 + r)*64 + g*4;
        const size_t ksrc = qkbase + (size_t)r*64 + g*4;
        cpasync16u(smu + AQH + dst, g_qh + qsrc);
        cpasync16u(smu + AQL + dst, g_ql + qsrc);
        cpasync16u(smu + AKH + dst, g_kh + ksrc);
        cpasync16u(smu + AKL + dst, g_kl + ksrc);
    }
    asm volatile("cp.async.commit_group;\n");
    asm volatile("cp.async.wait_group 0;\n");
    __syncthreads();

    float lsum0 = 0.f, lsum1 = 0.f;
    float O[8][4];
    #pragma unroll
    for (int n = 0; n < 8; n++)
        #pragma unroll
        for (int u = 0; u < 4; u++) O[n][u] = 0.f;

    const int nt = qb + 1;

    for (int t = 0; t < nt; t++) {
        const int kn0 = t * 64;
        if (t > 0) __syncthreads();

        #pragma unroll
        for (int rep = 0; rep < 4; rep++) {
            const int idx = rep*256 + tid;
            const int d = idx >> 3, g = idx & 7;
            const int dst = d*32 + ((g ^ (d & 7)) << 2);
            const size_t src = vbase + (size_t)d*(SS/2) + (kn0 >> 1) + g*4;
            cpasync16u(smu + AVH + dst, g_vh + src);
            cpasync16u(smu + AVL + dst, g_vl + src);
        }
        asm volatile("cp.async.commit_group;\n");

        asm volatile("cp.async.wait_group 1;\n");
        __syncthreads();

        float Sf[4][4];
        #pragma unroll
        for (int n = 0; n < 4; n++)
            #pragma unroll
            for (int u = 0; u < 4; u++) Sf[n][u] = 0.f;

        // ---- S = Q K^T (bf16 3-product, ldmatrix) ----
        #pragma unroll
        for (int ch = 0; ch < 8; ch++) {
            uint32_t ah[4], al[4];
            {
                const int row = wrow + lt15;
                const int gr = 2*ch + asel;
                const uint32_t off = 4*(row*64 + ((gr ^ (row & 7)) << 2));
                ldm_x4(ah, sb + AQH*4 + off);
                ldm_x4(al, sb + AQL*4 + off);
            }
            uint32_t kh[2][4], kl[2][4];
            #pragma unroll
            for (int ip = 0; ip < 2; ip++) {
                const int kr = (half*4 + ip*2 + brow)*8 + lt7;
                const int gr = 2*ch + bsel;
                const uint32_t off = 4*(kr*64 + ((gr ^ (kr & 7)) << 2));
                ldm_x4(kh[ip], sb + AKH*4 + off);
                ldm_x4(kl[ip], sb + AKL*4 + off);
            }
            #pragma unroll
            for (int nf = 0; nf < 4; nf++) {
                uint32_t bh[2] = { kh[nf>>1][(nf&1)*2], kh[nf>>1][(nf&1)*2 + 1] };
                uint32_t bl[2] = { kl[nf>>1][(nf&1)*2], kl[nf>>1][(nf&1)*2 + 1] };
                mma_bf16(Sf[nf], ah, bh);
                mma_bf16(Sf[nf], al, bh);
                mma_bf16(Sf[nf], ah, bl);
            }
        }

        const bool maskt = (t == nt - 1);
        const int row0 = qm0 + wrow + qr, row1 = row0 + 8;
        #pragma unroll
        for (int nf = 0; nf < 4; nf++) {
            const int key0 = kn0 + (half*4 + nf)*8 + 2*qc;
            float p00 = __expf(fmaf(Sf[nf][0], scale, -SHIFTC));
            float p01 = __expf(fmaf(Sf[nf][1], scale, -SHIFTC));
            float p10 = __expf(fmaf(Sf[nf][2], scale, -SHIFTC));
            float p11 = __expf(fmaf(Sf[nf][3], scale, -SHIFTC));
            if (maskt) {
                if (key0     > row0) p00 = 0.f;
                if (key0 + 1 > row0) p01 = 0.f;
                if (key0     > row1) p10 = 0.f;
                if (key0 + 1 > row1) p11 = 0.f;
            }
            lsum0 += p00 + p01;
            lsum1 += p10 + p11;
            const int pp = (half*4 + nf)*4 + qc;
            uint32_t hi, lo;
            splitbf(p00, p01, hi, lo);
            smu[APH + xsw(wrow + qr, pp, 32)] = hi;
            smu[APL + xsw(wrow + qr, pp, 32)] = lo;
            splitbf(p10, p11, hi, lo);
            smu[APH + xsw(wrow + qr + 8, pp, 32)] = hi;
            smu[APL + xsw(wrow + qr + 8, pp, 32)] = lo;
        }

        asm volatile("cp.async.wait_group 0;\n");
        __syncthreads();

        if (t + 1 < nt) {
            #pragma unroll
            for (int rep = 0; rep < 4; rep++) {
                const int idx = rep*256 + tid;
                const int r = idx >> 4, g = idx & 15;
                const int dst = r*64 + ((g ^ (r & 7)) << 2);
                const size_t src = qkbase + (size_t)(kn0 + 64 + r)*64 + g*4;
                cpasync16u(smu + AKH + dst, g_kh + src);
                cpasync16u(smu + AKL + dst, g_kl + src);
            }
            asm volatile("cp.async.commit_group;\n");
        }

        // ---- O += P V (bf16 3-product, ldmatrix) ----
        #pragma unroll
        for (int ch = 0; ch < 4; ch++) {
            uint32_t ah[4], al[4];
            {
                const int row = wrow + lt15;
                const int gr = 2*ch + asel;
                const uint32_t off = 4*(row*32 + ((gr ^ (row & 7)) << 2));
                ldm_x4(ah, sb + APH*4 + off);
                ldm_x4(al, sb + APL*4 + off);
            }
            uint32_t vh[4][4], vl[4][4];
            #pragma unroll
            for (int ip = 0; ip < 4; ip++) {
                const int dr = (half*8 + ip*2 + brow)*8 + lt7;
                const int gr = 2*ch + bsel;
                const uint32_t off = 4*(dr*32 + ((gr ^ (dr & 7)) << 2));
                ldm_x4(vh[ip], sb + AVH*4 + off);
                ldm_x4(vl[ip], sb + AVL*4 + off);
            }
            #pragma unroll
            for (int nf = 0; nf < 8; nf++) {
                uint32_t bh[2] = { vh[nf>>1][(nf&1)*2], vh[nf>>1][(nf&1)*2 + 1] };
                uint32_t bl[2] = { vl[nf>>1][(nf&1)*2], vl[nf>>1][(nf&1)*2 + 1] };
                mma_bf16(O[nf], ah, bh);
                mma_bf16(O[nf], al, bh);
                mma_bf16(O[nf], ah, bl);
            }
        }
    }

    lsum0 += __shfl_xor_sync(0xffffffffu, lsum0, 1);
    lsum0 += __shfl_xor_sync(0xffffffffu, lsum0, 2);
    lsum1 += __shfl_xor_sync(0xffffffffu, lsum1, 1);
    lsum1 += __shfl_xor_sync(0xffffffffu, lsum1, 2);
    __syncthreads();
    if (qc == 0) {
        smf[ALRED + half*64 + wrow + qr]     = lsum0;
        smf[ALRED + half*64 + wrow + qr + 8] = lsum1;
    }
    __syncthreads();
    const float il0 = 1.0f / (smf[ALRED + wrow + qr] + smf[ALRED + 64 + wrow + qr]);
    const float il1 = 1.0f / (smf[ALRED + wrow + qr + 8] + smf[ALRED + 64 + wrow + qr + 8]);

    const size_t gr0 = (size_t)(b*SS + qm0 + wrow + qr);
    #pragma unroll
    for (int nf = 0; nf < 8; nf++) {
        const int col = h*DH + (half*8 + nf)*8 + 2*qc;
        *(float2*)(g_attn + gr0 * DD + col) =
            make_float2(O[nf][0]*il0, O[nf][1]*il0);
        *(float2*)(g_attn + (gr0 + 8) * DD + col) =
            make_float2(O[nf][2]*il1, O[nf][3]*il1);
    }
}

// ---------------------------------------------------------------------------
// RMSNorm over D=2048 + pack to fp16 plane. One block per row.
// ---------------------------------------------------------------------------
__global__ __launch_bounds__(256) void rmsnorm_pack_rows(const float* __restrict__ w)
{
    __shared__ float red[8];
    __shared__ float s_inv;
    const float* p = g_attn + (size_t)blockIdx.x * DD;
    const int tid = threadIdx.x;
    const int base = tid * 8;

    float v[8];
    {
        const float4 a = *(const float4*)(p + base);
        const float4 b = *(const float4*)(p + base + 4);
        v[0]=a.x; v[1]=a.y; v[2]=a.z; v[3]=a.w;
        v[4]=b.x; v[5]=b.y; v[6]=b.z; v[7]=b.w;
    }
    float ss = 0.f;
    #pragma unroll
    for (int k = 0; k < 8; k++) ss += v[k]*v[k];
    #pragma unroll
    for (int o = 16; o > 0; o >>= 1) ss += __shfl_xor_sync(0xffffffffu, ss, o);
    if ((tid & 31) == 0) red[tid >> 5] = ss;
    __syncthreads();
    if (tid == 0) {
        float t = 0.f;
        #pragma unroll
        for (int i = 0; i < 8; i++) t += red[i];
        s_inv = rsqrtf(t * (1.0f / DD) + EPS);
    }
    __syncthreads();
    const float inv = s_inv;
    const size_t ob = (size_t)blockIdx.x * (DD/2) + base/2;
    #pragma unroll
    for (int u = 0; u < 4; u++) {
        const float x0 = v[2*u]   * inv * w[base + 2*u];
        const float x1 = v[2*u+1] * inv * w[base + 2*u + 1];
        g_af[ob + u] = packf16(x0, x1);
    }
}

// ---------------------------------------------------------------------------
extern "C" void kernel_launch(void* const* d_in, const int* in_sizes, int n_in,
                              void* d_out, int out_size)
{
    const float* x     = (const float*)d_in[0];
    const float* rp    = (const float*)d_in[1];
    const float* Win   = (const float*)d_in[2];
    const float* b_in  = (const float*)d_in[3];
    const float* Wout  = (const float*)d_in[4];
    const float* b_out = (const float*)d_in[5];
    const float* qk_w  = (const float*)d_in[6];
    const float* out_w = (const float*)d_in[7];
    float* out = (float*)d_out;

    float* qkv;  cudaGetSymbolAddress((void**)&qkv,  g_qkv);
    uint32_t *xf, *wif, *wof, *af;
    cudaGetSymbolAddress((void**)&xf,  g_xf);
    cudaGetSymbolAddress((void**)&wif, g_wif);
    cudaGetSymbolAddress((void**)&wof, g_wof);
    cudaGetSymbolAddress((void**)&af,  g_af);

    const int gemm_smem = 2 * GBUF * (int)sizeof(uint32_t);   // 65536 B
    cudaFuncSetAttribute(f16_gemm_nt_bias,
                         cudaFuncAttributeMaxDynamicSharedMemorySize, gemm_smem);
    const int vsp_smem = 128 * 129 * (int)sizeof(float);      // 66048 B
    cudaFuncSetAttribute(v_split_t,
                         cudaFuncAttributeMaxDynamicSharedMemorySize, vsp_smem);
    cudaFuncSetAttribute(flash_attn_v2,
                         cudaFuncAttributeMaxDynamicSharedMemorySize, ASZ);

    // 0) pack inputs to fp16 planes
    split_plane_f16<<<(MM*DD)/1024, 256>>>(x, xf);
    split_plane_f16<<<(TRIO*DD)/1024, 256>>>(Win, wif);
    split_plane_f16<<<(DD*DD)/1024, 256>>>(Wout, wof);

    // 1) qkv = x @ Win^T + b_in   [4096, 6144]
    {
        dim3 grid(TRIO / 128, MM / 128);
        f16_gemm_nt_bias<<<grid, 256, gemm_smem>>>(
            xf, wif, b_in, qkv, MM, TRIO, DD/2);
    }
    // 2a) RoPE + RMS on q,k -> bf16 hi/lo planes
    {
        const int warps = MM * HH * 2;
        rope_rms_split<<<warps / 8, 256>>>(rp, qk_w);
    }
    // 2b) v -> transposed bf16 hi/lo planes
    {
        dim3 grid(SS / 128, HH, BB);
        v_split_t<<<grid, 256, vsp_smem>>>();
    }
    // 3) flash attention -> g_attn
    {
        dim3 grid(SS / 64, HH, BB);
        flash_attn_v2<<<grid, 256, ASZ>>>();
    }
    // 4) RMSNorm + pack -> g_af
    rmsnorm_pack_rows<<<MM, 256>>>(out_w);
    // 5) out = attn @ Wout^T + b_out
    {
        dim3 grid(DD / 128, MM / 128);
        f16_gemm_nt_bias<<<grid, 256, gemm_smem>>>(
            af, wof, b_out, out, MM, DD, DD/2);
    }
}

// round 14
// speedup vs baseline: 7.3955x; 1.1268x over previous
#include <cuda_runtime.h>
#include <cuda_bf16.h>
#include <cuda_fp16.h>
#include <math.h>
#include <stdint.h>

// Problem constants
#define BB 2
#define SS 2048
#define DD 2048
#define HH 16
#define DH 128
#define MM (BB*SS)          // 4096
#define TRIO (3*DD)         // 6144
#define EPS 1e-6f

// Scratch (device globals; no allocation allowed)
__device__ float g_qkv[(size_t)MM * TRIO];   // 100.7 MB
__device__ float g_attn[(size_t)MM * DD];    // 33.6 MB
// Attention q/k pre-split bf16x2 planes (hi/lo), packed 2 elems per u32.
__device__ uint32_t g_qh[(size_t)BB*HH*SS*64];
__device__ uint32_t g_ql[(size_t)BB*HH*SS*64];
__device__ uint32_t g_kh[(size_t)BB*HH*SS*64];
__device__ uint32_t g_kl[(size_t)BB*HH*SS*64];
// V: single fp16x2 plane, transposed [b][h][d][s2]
__device__ uint32_t g_vf[(size_t)BB*HH*DH*(SS/2)];
// GEMM operand planes: packed fp16x2, single plane
__device__ uint32_t g_xf[(size_t)MM*(DD/2)];      // x
__device__ uint32_t g_wif[(size_t)TRIO*(DD/2)];   // Win
__device__ uint32_t g_wof[(size_t)DD*(DD/2)];     // Wout
__device__ uint32_t g_af[(size_t)MM*(DD/2)];      // rmsnormed attn

// ---------------------------------------------------------------------------
// Helpers
// ---------------------------------------------------------------------------
__device__ __forceinline__ void cpasync16u(uint32_t* s, const uint32_t* g) {
    uint32_t sa = (uint32_t)__cvta_generic_to_shared(s);
    asm volatile("cp.async.cg.shared.global [%0], [%1], 16;" :: "r"(sa), "l"(g));
}
__device__ __forceinline__ void mma_bf16(float c[4], const uint32_t a[4], const uint32_t b[2]) {
    asm volatile(
        "mma.sync.aligned.m16n8k16.row.col.f32.bf16.bf16.f32 "
        "{%0,%1,%2,%3}, {%4,%5,%6,%7}, {%8,%9}, {%0,%1,%2,%3};"
        : "+f"(c[0]), "+f"(c[1]), "+f"(c[2]), "+f"(c[3])
        : "r"(a[0]), "r"(a[1]), "r"(a[2]), "r"(a[3]), "r"(b[0]), "r"(b[1]));
}
__device__ __forceinline__ void mma_f16(float c[4], const uint32_t a[4], const uint32_t b[2]) {
    asm volatile(
        "mma.sync.aligned.m16n8k16.row.col.f32.f16.f16.f32 "
        "{%0,%1,%2,%3}, {%4,%5,%6,%7}, {%8,%9}, {%0,%1,%2,%3};"
        : "+f"(c[0]), "+f"(c[1]), "+f"(c[2]), "+f"(c[3])
        : "r"(a[0]), "r"(a[1]), "r"(a[2]), "r"(a[3]), "r"(b[0]), "r"(b[1]));
}
__device__ __forceinline__ void ldm_x4(uint32_t d[4], uint32_t saddr) {
    asm volatile("ldmatrix.sync.aligned.m8n8.x4.shared.b16 {%0,%1,%2,%3}, [%4];"
        : "=r"(d[0]), "=r"(d[1]), "=r"(d[2]), "=r"(d[3]) : "r"(saddr));
}
// split two floats into packed bf16x2 (hi) and packed bf16x2 residual (lo)
__device__ __forceinline__ void splitbf(float x0, float x1, uint32_t& hi, uint32_t& lo) {
    __nv_bfloat162 hp = __floats2bfloat162_rn(x0, x1);
    float r0 = x0 - __bfloat162float(hp.x);
    float r1 = x1 - __bfloat162float(hp.y);
    __nv_bfloat162 lp = __floats2bfloat162_rn(r0, r1);
    hi = *reinterpret_cast<uint32_t*>(&hp);
    lo = *reinterpret_cast<uint32_t*>(&lp);
}
__device__ __forceinline__ uint32_t packf16(float x0, float x1) {
    __half2 hp = __floats2half2_rn(x0, x1);
    return *reinterpret_cast<uint32_t*>(&hp);
}
// 16B-granule XOR swizzle (u32 units), row length rowu
__device__ __forceinline__ int xsw(int r, int p, int rowu) {
    return r*rowu + ((((p >> 2) ^ (r & 7)) << 2) | (p & 3));
}

// ---------------------------------------------------------------------------
// fp32 -> packed fp16x2 plane. One thread per float4.
// ---------------------------------------------------------------------------
__global__ __launch_bounds__(256) void split_plane_f16(
    const float* __restrict__ src, uint32_t* __restrict__ pf)
{
    const size_t i = (size_t)blockIdx.x * 256 + threadIdx.x;
    const float4 v = *(const float4*)(src + i*4);
    pf[2*i]     = packf16(v.x, v.y);
    pf[2*i + 1] = packf16(v.z, v.w);
}

// ---------------------------------------------------------------------------
// Single-product fp16 tensor-core GEMM with ldmatrix fragment loads.
// ---------------------------------------------------------------------------
#define GKU 32                 // u32 per row per k-tile
#define GBUF (128*GKU*2)       // A + B per buffer = 8192 u32 (32 KB)

__global__ __launch_bounds__(256, 2) void f16_gemm_nt_bias(
    const uint32_t* __restrict__ A, const uint32_t* __restrict__ B,
    const float* __restrict__ bias, float* __restrict__ C,
    int M, int N, int Ku)
{
    extern __shared__ uint32_t sm[];
    const uint32_t sbase = (uint32_t)__cvta_generic_to_shared(sm);

    const int tid = threadIdx.x;
    const int bm0 = blockIdx.y * 128;
    const int bn0 = blockIdx.x * 128;
    const int warp = tid >> 5, lane = tid & 31;
    const int wm0 = (warp >> 2) * 64;
    const int wn0 = (warp & 3) * 32;
    const int qr = lane >> 2, qc = lane & 3;
    const int lt15 = lane & 15, lt7 = lane & 7;
    const int asel = lane >> 4;
    const int brow = lane >> 4;
    const int bsel = (lane >> 3) & 1;

    const int lr = tid >> 3;
    const int lg = tid & 7;
    const uint32_t* Agp = A + (size_t)(bm0 + lr) * Ku + lg*4;
    const uint32_t* Bgp = B + (size_t)(bn0 + lr) * Ku + lg*4;
    const size_t rstep = (size_t)32 * Ku;
    int dsts[4];
    #pragma unroll
    for (int rep = 0; rep < 4; rep++) {
        const int r = lr + rep*32;
        dsts[rep] = r*32 + ((lg ^ (r & 7)) << 2);
    }

    float acc[4][4][4];
    #pragma unroll
    for (int i = 0; i < 4; i++)
        #pragma unroll
        for (int j = 0; j < 4; j++)
            #pragma unroll
            for (int u = 0; u < 4; u++) acc[i][j][u] = 0.f;

    const int nk = Ku / GKU;

    #pragma unroll
    for (int rep = 0; rep < 4; rep++) {
        cpasync16u(sm + dsts[rep],             Agp + rep*rstep);
        cpasync16u(sm + 4096 + dsts[rep],      Bgp + rep*rstep);
    }
    asm volatile("cp.async.commit_group;\n");

    for (int kt = 0; kt < nk; kt++) {
        if (kt + 1 < nk) {
            uint32_t* Bn = sm + ((kt + 1) & 1) * GBUF;
            const int ko = (kt + 1) * GKU;
            #pragma unroll
            for (int rep = 0; rep < 4; rep++) {
                cpasync16u(Bn + dsts[rep],        Agp + ko + rep*rstep);
                cpasync16u(Bn + 4096 + dsts[rep], Bgp + ko + rep*rstep);
            }
            asm volatile("cp.async.commit_group;\n");
            asm volatile("cp.async.wait_group 1;\n");
        } else {
            asm volatile("cp.async.wait_group 0;\n");
        }
        __syncthreads();

        const uint32_t abuf = sbase + ((kt & 1) * GBUF) * 4;
        const uint32_t bbuf = abuf + 4096 * 4;

        #pragma unroll
        for (int ch = 0; ch < 4; ch++) {
            uint32_t af[4][4];
            #pragma unroll
            for (int im = 0; im < 4; im++) {
                const int row = wm0 + im*16 + lt15;
                const int gr  = 2*ch + asel;
                ldm_x4(af[im], abuf + 4*(row*32 + ((gr ^ (row & 7)) << 2)));
            }
            uint32_t bf[2][4];
            #pragma unroll
            for (int ip = 0; ip < 2; ip++) {
                const int nrow = wn0 + (ip*2 + brow)*8 + lt7;
                const int gr = 2*ch + bsel;
                ldm_x4(bf[ip], bbuf + 4*(nrow*32 + ((gr ^ (nrow & 7)) << 2)));
            }
            #pragma unroll
            for (int in = 0; in < 4; in++) {
                uint32_t bb[2] = { bf[in>>1][(in&1)*2], bf[in>>1][(in&1)*2 + 1] };
                #pragma unroll
                for (int im = 0; im < 4; im++)
                    mma_f16(acc[im][in], af[im], bb);
            }
        }
        __syncthreads();
    }

    #pragma unroll
    for (int im = 0; im < 4; im++) {
        #pragma unroll
        for (int in = 0; in < 4; in++) {
            const int r0 = bm0 + wm0 + im*16 + qr;
            const int c0 = bn0 + wn0 + in*8 + qc*2;
            const float2 b2 = *(const float2*)(bias + c0);
            float2 v;
            v.x = acc[im][in][0] + b2.x; v.y = acc[im][in][1] + b2.y;
            *(float2*)(C + (size_t)r0 * N + c0) = v;
            v.x = acc[im][in][2] + b2.x; v.y = acc[im][in][3] + b2.y;
            *(float2*)(C + (size_t)(r0 + 8) * N + c0) = v;
        }
    }
}

// ---------------------------------------------------------------------------
// RoPE + RMSNorm for q,k; writes pre-split bf16 hi/lo planes.
// ---------------------------------------------------------------------------
__global__ __launch_bounds__(256) void rope_rms_split(
    const float* __restrict__ rp, const float* __restrict__ qk_w)
{
    const int w = blockIdx.x * 8 + (threadIdx.x >> 5);
    const int lane = threadIdx.x & 31;
    const int h = w % HH;
    const int t = w / HH;
    const int which = t & 1;
    const int m = t >> 1;
    const int s = m & (SS - 1);
    const int b = m >> 11;

    const float* base = g_qkv + (size_t)m * TRIO + which * DD + h * DH;
    const float* ang = rp + s * (DH/2);

    float r[4];
    float ss = 0.f;
    #pragma unroll
    for (int u = 0; u < 2; u++) {
        const int p = lane + u * 32;
        const float a = ang[p];
        const float c = cosf(a), sn = sinf(a);
        const float x0 = base[2*p], x1 = base[2*p+1];
        const float r0 = x0 * c - x1 * sn;
        const float r1 = x0 * sn + x1 * c;
        r[2*u] = r0; r[2*u+1] = r1;
        ss += r0*r0 + r1*r1;
    }
    #pragma unroll
    for (int o = 16; o > 0; o >>= 1) ss += __shfl_xor_sync(0xffffffffu, ss, o);
    const float inv = rsqrtf(ss * (1.0f / DH) + EPS);

    const float o0 = r[0] * inv * qk_w[2*lane];
    const float o1 = r[1] * inv * qk_w[2*lane + 1];
    const float o2 = r[2] * inv * qk_w[2*(lane+32)];
    const float o3 = r[3] * inv * qk_w[2*(lane+32) + 1];
    uint32_t h0, l0, h1, l1;
    splitbf(o0, o1, h0, l0);
    splitbf(o2, o3, h1, l1);

    const size_t pb = ((size_t)(b*HH + h)*SS + s) * 64;
    uint32_t* ph = which ? g_kh : g_qh;
    uint32_t* pl = which ? g_kl : g_ql;
    ph[pb + lane]      = h0;
    ph[pb + lane + 32] = h1;
    pl[pb + lane]      = l0;
    pl[pb + lane + 32] = l1;
}

// ---------------------------------------------------------------------------
// V pack + transpose: g_qkv v -> g_vf fp16 plane [b][h][d][s2].
// ---------------------------------------------------------------------------
__global__ __launch_bounds__(256) void v_pack_t()
{
    extern __shared__ float vt[];     // [128][129]
    const int sc = blockIdx.x, h = blockIdx.y, b = blockIdx.z;
    const int tid = threadIdx.x;

    #pragma unroll
    for (int rep = 0; rep < 16; rep++) {
        const int idx = rep*256 + tid;
        const int r = idx >> 5, c4 = (idx & 31) * 4;
        const float4 v = *(const float4*)(g_qkv +
            (size_t)(b*SS + sc*128 + r)*TRIO + 2*DD + h*DH + c4);
        vt[r*129 + c4 + 0] = v.x; vt[r*129 + c4 + 1] = v.y;
        vt[r*129 + c4 + 2] = v.z; vt[r*129 + c4 + 3] = v.w;
    }
    __syncthreads();

    #pragma unroll
    for (int rep = 0; rep < 32; rep++) {
        const int idx = rep*256 + tid;
        const int d = idx >> 6, j2 = idx & 63;
        const float x0 = vt[(2*j2)*129 + d];
        const float x1 = vt[(2*j2 + 1)*129 + d];
        const size_t o = ((size_t)(b*HH + h)*DH + d)*(SS/2) + sc*64 + j2;
        g_vf[o] = packf16(x0, x1);
    }
}

// ---------------------------------------------------------------------------
// Flash attention v4: S = bf16 3-product (ldmatrix), PV = fp16 1-product.
// ---------------------------------------------------------------------------
#define AQH 0
#define AQL 4096
#define AKH 8192
#define AKL 12288
#define AVH 16384               // 4096 u32 (128 d x 32)
#define APH 20480               // 2048 u32 (64 rows x 32)
#define ALRED 22528
#define ASZ ((22528 + 128) * 4) // 90624 B
#define SHIFTC 11.32f

__global__ __launch_bounds__(256, 2) void flash_attn_v2()
{
    extern __shared__ uint32_t smu[];
    float* smf = reinterpret_cast<float*>(smu);
    const uint32_t sb = (uint32_t)__cvta_generic_to_shared(smu);

    const int qb = (int)(gridDim.x - 1 - blockIdx.x);
    const int qm0 = qb * 64;
    const int h = blockIdx.y, b = blockIdx.z;
    const int tid = threadIdx.x;
    const int warp = tid >> 5, lane = tid & 31;
    const int qr = lane >> 2, qc = lane & 3;
    const int half = warp & 1;
    const int wrow = (warp >> 1) * 16;
    const int lt15 = lane & 15, lt7 = lane & 7;
    const int asel = lane >> 4;
    const int brow = lane >> 4;
    const int bsel = (lane >> 3) & 1;

    const size_t qkbase = (size_t)(b*HH + h) * SS * 64;
    const size_t vbase  = (size_t)(b*HH + h) * DH * (SS/2);
    const float scale = 0.08838834764831845f;

    #pragma unroll
    for (int rep = 0; rep < 4; rep++) {
        const int idx = rep*256 + tid;
        const int r = idx >> 4, g = idx & 15;
        const int dst = r*64 + ((g ^ (r & 7)) << 2);
        const size_t qsrc = qkbase + (size_t)(qm0 + r)*64 + g*4;
        const size_t ksrc = qkbase + (size_t)r*64 + g*4;
        cpasync16u(smu + AQH + dst, g_qh + qsrc);
        cpasync16u(smu + AQL + dst, g_ql + qsrc);
        cpasync16u(smu + AKH + dst, g_kh + ksrc);
        cpasync16u(smu + AKL + dst, g_kl + ksrc);
    }
    asm volatile("cp.async.commit_group;\n");
    asm volatile("cp.async.wait_group 0;\n");
    __syncthreads();

    float lsum0 = 0.f, lsum1 = 0.f;
    float O[8][4];
    #pragma unroll
    for (int n = 0; n < 8; n++)
        #pragma unroll
        for (int u = 0; u < 4; u++) O[n][u] = 0.f;

    const int nt = qb + 1;

    for (int t = 0; t < nt; t++) {
        const int kn0 = t * 64;
        if (t > 0) __syncthreads();

        // ---- issue V_t (single fp16 plane) ----
        #pragma unroll
        for (int rep = 0; rep < 4; rep++) {
            const int idx = rep*256 + tid;
            const int d = idx >> 3, g = idx & 7;
            const int dst = d*32 + ((g ^ (d & 7)) << 2);
            const size_t src = vbase + (size_t)d*(SS/2) + (kn0 >> 1) + g*4;
            cpasync16u(smu + AVH + dst, g_vf + src);
        }
        asm volatile("cp.async.commit_group;\n");

        asm volatile("cp.async.wait_group 1;\n");
        __syncthreads();

        float Sf[4][4];
        #pragma unroll
        for (int n = 0; n < 4; n++)
            #pragma unroll
            for (int u = 0; u < 4; u++) Sf[n][u] = 0.f;

        // ---- S = Q K^T (bf16 3-product, ldmatrix) ----
        #pragma unroll
        for (int ch = 0; ch < 8; ch++) {
            uint32_t ah[4], al[4];
            {
                const int row = wrow + lt15;
                const int gr = 2*ch + asel;
                const uint32_t off = 4*(row*64 + ((gr ^ (row & 7)) << 2));
                ldm_x4(ah, sb + AQH*4 + off);
                ldm_x4(al, sb + AQL*4 + off);
            }
            uint32_t kh[2][4], kl[2][4];
            #pragma unroll
            for (int ip = 0; ip < 2; ip++) {
                const int kr = (half*4 + ip*2 + brow)*8 + lt7;
                const int gr = 2*ch + bsel;
                const uint32_t off = 4*(kr*64 + ((gr ^ (kr & 7)) << 2));
                ldm_x4(kh[ip], sb + AKH*4 + off);
                ldm_x4(kl[ip], sb + AKL*4 + off);
            }
            #pragma unroll
            for (int nf = 0; nf < 4; nf++) {
                uint32_t bh[2] = { kh[nf>>1][(nf&1)*2], kh[nf>>1][(nf&1)*2 + 1] };
                uint32_t bl[2] = { kl[nf>>1][(nf&1)*2], kl[nf>>1][(nf&1)*2 + 1] };
                mma_bf16(Sf[nf], ah, bh);
                mma_bf16(Sf[nf], al, bh);
                mma_bf16(Sf[nf], ah, bl);
            }
        }

        const bool maskt = (t == nt - 1);
        const int row0 = qm0 + wrow + qr, row1 = row0 + 8;
        #pragma unroll
        for (int nf = 0; nf < 4; nf++) {
            const int key0 = kn0 + (half*4 + nf)*8 + 2*qc;
            float p00 = __expf(fmaf(Sf[nf][0], scale, -SHIFTC));
            float p01 = __expf(fmaf(Sf[nf][1], scale, -SHIFTC));
            float p10 = __expf(fmaf(Sf[nf][2], scale, -SHIFTC));
            float p11 = __expf(fmaf(Sf[nf][3], scale, -SHIFTC));
            if (maskt) {
                if (key0     > row0) p00 = 0.f;
                if (key0 + 1 > row0) p01 = 0.f;
                if (key0     > row1) p10 = 0.f;
                if (key0 + 1 > row1) p11 = 0.f;
            }
            lsum0 += p00 + p01;
            lsum1 += p10 + p11;
            const int pp = (half*4 + nf)*4 + qc;
            smu[APH + xsw(wrow + qr, pp, 32)]     = packf16(p00, p01);
            smu[APH + xsw(wrow + qr + 8, pp, 32)] = packf16(p10, p11);
        }

        asm volatile("cp.async.wait_group 0;\n");
        __syncthreads();

        if (t + 1 < nt) {
            #pragma unroll
            for (int rep = 0; rep < 4; rep++) {
                const int idx = rep*256 + tid;
                const int r = idx >> 4, g = idx & 15;
                const int dst = r*64 + ((g ^ (r & 7)) << 2);
                const size_t src = qkbase + (size_t)(kn0 + 64 + r)*64 + g*4;
                cpasync16u(smu + AKH + dst, g_kh + src);
                cpasync16u(smu + AKL + dst, g_kl + src);
            }
            asm volatile("cp.async.commit_group;\n");
        }

        // ---- O += P V (fp16 single product, ldmatrix) ----
        #pragma unroll
        for (int ch = 0; ch < 4; ch++) {
            uint32_t ah[4];
            {
                const int row = wrow + lt15;
                const int gr = 2*ch + asel;
                ldm_x4(ah, sb + APH*4 + 4*(row*32 + ((gr ^ (row & 7)) << 2)));
            }
            uint32_t vh[4][4];
            #pragma unroll
            for (int ip = 0; ip < 4; ip++) {
                const int dr = (half*8 + ip*2 + brow)*8 + lt7;
                const int gr = 2*ch + bsel;
                ldm_x4(vh[ip], sb + AVH*4 + 4*(dr*32 + ((gr ^ (dr & 7)) << 2)));
            }
            #pragma unroll
            for (int nf = 0; nf < 8; nf++) {
                uint32_t bb[2] = { vh[nf>>1][(nf&1)*2], vh[nf>>1][(nf&1)*2 + 1] };
                mma_f16(O[nf], ah, bb);
            }
        }
    }

    lsum0 += __shfl_xor_sync(0xffffffffu, lsum0, 1);
    lsum0 += __shfl_xor_sync(0xffffffffu, lsum0, 2);
    lsum1 += __shfl_xor_sync(0xffffffffu, lsum1, 1);
    lsum1 += __shfl_xor_sync(0xffffffffu, lsum1, 2);
    __syncthreads();
    if (qc == 0) {
        smf[ALRED + half*64 + wrow + qr]     = lsum0;
        smf[ALRED + half*64 + wrow + qr + 8] = lsum1;
    }
    __syncthreads();
    const float il0 = 1.0f / (smf[ALRED + wrow + qr] + smf[ALRED + 64 + wrow + qr]);
    const float il1 = 1.0f / (smf[ALRED + wrow + qr + 8] + smf[ALRED + 64 + wrow + qr + 8]);

    const size_t gr0 = (size_t)(b*SS + qm0 + wrow + qr);
    #pragma unroll
    for (int nf = 0; nf < 8; nf++) {
        const int col = h*DH + (half*8 + nf)*8 + 2*qc;
        *(float2*)(g_attn + gr0 * DD + col) =
            make_float2(O[nf][0]*il0, O[nf][1]*il0);
        *(float2*)(g_attn + (gr0 + 8) * DD + col) =
            make_float2(O[nf][2]*il1, O[nf][3]*il1);
    }
}

// ---------------------------------------------------------------------------
// RMSNorm over D=2048 + pack to fp16 plane. One block per row.
// ---------------------------------------------------------------------------
__global__ __launch_bounds__(256) void rmsnorm_pack_rows(const float* __restrict__ w)
{
    __shared__ float red[8];
    __shared__ float s_inv;
    const float* p = g_attn + (size_t)blockIdx.x * DD;
    const int tid = threadIdx.x;
    const int base = tid * 8;

    float v[8];
    {
        const float4 a = *(const float4*)(p + base);
        const float4 b = *(const float4*)(p + base + 4);
        v[0]=a.x; v[1]=a.y; v[2]=a.z; v[3]=a.w;
        v[4]=b.x; v[5]=b.y; v[6]=b.z; v[7]=b.w;
    }
    float ss = 0.f;
    #pragma unroll
    for (int k = 0; k < 8; k++) ss += v[k]*v[k];
    #pragma unroll
    for (int o = 16; o > 0; o >>= 1) ss += __shfl_xor_sync(0xffffffffu, ss, o);
    if ((tid & 31) == 0) red[tid >> 5] = ss;
    __syncthreads();
    if (tid == 0) {
        float t = 0.f;
        #pragma unroll
        for (int i = 0; i < 8; i++) t += red[i];
        s_inv = rsqrtf(t * (1.0f / DD) + EPS);
    }
    __syncthreads();
    const float inv = s_inv;
    const size_t ob = (size_t)blockIdx.x * (DD/2) + base/2;
    #pragma unroll
    for (int u = 0; u < 4; u++) {
        const float x0 = v[2*u]   * inv * w[base + 2*u];
        const float x1 = v[2*u+1] * inv * w[base + 2*u + 1];
        g_af[ob + u] = packf16(x0, x1);
    }
}

// ---------------------------------------------------------------------------
extern "C" void kernel_launch(void* const* d_in, const int* in_sizes, int n_in,
                              void* d_out, int out_size)
{
    const float* x     = (const float*)d_in[0];
    const float* rp    = (const float*)d_in[1];
    const float* Win   = (const float*)d_in[2];
    const float* b_in  = (const float*)d_in[3];
    const float* Wout  = (const float*)d_in[4];
    const float* b_out = (const float*)d_in[5];
    const float* qk_w  = (const float*)d_in[6];
    const float* out_w = (const float*)d_in[7];
    float* out = (float*)d_out;

    float* qkv;  cudaGetSymbolAddress((void**)&qkv,  g_qkv);
    uint32_t *xf, *wif, *wof, *af;
    cudaGetSymbolAddress((void**)&xf,  g_xf);
    cudaGetSymbolAddress((void**)&wif, g_wif);
    cudaGetSymbolAddress((void**)&wof, g_wof);
    cudaGetSymbolAddress((void**)&af,  g_af);

    const int gemm_smem = 2 * GBUF * (int)sizeof(uint32_t);   // 65536 B
    cudaFuncSetAttribute(f16_gemm_nt_bias,
                         cudaFuncAttributeMaxDynamicSharedMemorySize, gemm_smem);
    const int vsp_smem = 128 * 129 * (int)sizeof(float);      // 66048 B
    cudaFuncSetAttribute(v_pack_t,
                         cudaFuncAttributeMaxDynamicSharedMemorySize, vsp_smem);
    cudaFuncSetAttribute(flash_attn_v2,
                         cudaFuncAttributeMaxDynamicSharedMemorySize, ASZ);

    // 0) pack inputs to fp16 planes
    split_plane_f16<<<(MM*DD)/1024, 256>>>(x, xf);
    split_plane_f16<<<(TRIO*DD)/1024, 256>>>(Win, wif);
    split_plane_f16<<<(DD*DD)/1024, 256>>>(Wout, wof);

    // 1) qkv = x @ Win^T + b_in   [4096, 6144]
    {
        dim3 grid(TRIO / 128, MM / 128);
        f16_gemm_nt_bias<<<grid, 256, gemm_smem>>>(
            xf, wif, b_in, qkv, MM, TRIO, DD/2);
    }
    // 2a) RoPE + RMS on q,k -> bf16 hi/lo planes
    {
        const int warps = MM * HH * 2;
        rope_rms_split<<<warps / 8, 256>>>(rp, qk_w);
    }
    // 2b) v -> transposed fp16 plane
    {
        dim3 grid(SS / 128, HH, BB);
        v_pack_t<<<grid, 256, vsp_smem>>>();
    }
    // 3) flash attention -> g_attn
    {
        dim3 grid(SS / 64, HH, BB);
        flash_attn_v2<<<grid, 256, ASZ>>>();
    }
    // 4) RMSNorm + pack -> g_af
    rmsnorm_pack_rows<<<MM, 256>>>(out_w);
    // 5) out = attn @ Wout^T + b_out
    {
        dim3 grid(DD / 128, MM / 128);
        f16_gemm_nt_bias<<<grid, 256, gemm_smem>>>(
            af, wof, b_out, out, MM, DD, DD/2);
    }
}

// round 15
// speedup vs baseline: 7.6529x; 1.0348x over previous
#include <cuda_runtime.h>
#include <cuda_bf16.h>
#include <cuda_fp16.h>
#include <math.h>
#include <stdint.h>

// Problem constants
#define BB 2
#define SS 2048
#define DD 2048
#define HH 16
#define DH 128
#define MM (BB*SS)          // 4096
#define TRIO (3*DD)         // 6144
#define EPS 1e-6f

// Scratch (device globals; no allocation allowed)
__device__ float g_attn[(size_t)MM * DD];    // 33.6 MB
// Attention q/k pre-split bf16x2 planes (hi/lo), packed 2 elems per u32.
__device__ uint32_t g_qh[(size_t)BB*HH*SS*64];
__device__ uint32_t g_ql[(size_t)BB*HH*SS*64];
__device__ uint32_t g_kh[(size_t)BB*HH*SS*64];
__device__ uint32_t g_kl[(size_t)BB*HH*SS*64];
// V: single fp16x2 plane, transposed [b][h][d][s2]
__device__ uint32_t g_vf[(size_t)BB*HH*DH*(SS/2)];
// GEMM operand planes: packed fp16x2, single plane
__device__ uint32_t g_xf[(size_t)MM*(DD/2)];      // x
__device__ uint32_t g_wif[(size_t)TRIO*(DD/2)];   // Win
__device__ uint32_t g_wof[(size_t)DD*(DD/2)];     // Wout
__device__ uint32_t g_af[(size_t)MM*(DD/2)];      // rmsnormed attn

// ---------------------------------------------------------------------------
// Helpers
// ---------------------------------------------------------------------------
__device__ __forceinline__ void cpasync16u(uint32_t* s, const uint32_t* g) {
    uint32_t sa = (uint32_t)__cvta_generic_to_shared(s);
    asm volatile("cp.async.cg.shared.global [%0], [%1], 16;" :: "r"(sa), "l"(g));
}
__device__ __forceinline__ void mma_bf16(float c[4], const uint32_t a[4], const uint32_t b[2]) {
    asm volatile(
        "mma.sync.aligned.m16n8k16.row.col.f32.bf16.bf16.f32 "
        "{%0,%1,%2,%3}, {%4,%5,%6,%7}, {%8,%9}, {%0,%1,%2,%3};"
        : "+f"(c[0]), "+f"(c[1]), "+f"(c[2]), "+f"(c[3])
        : "r"(a[0]), "r"(a[1]), "r"(a[2]), "r"(a[3]), "r"(b[0]), "r"(b[1]));
}
__device__ __forceinline__ void mma_f16(float c[4], const uint32_t a[4], const uint32_t b[2]) {
    asm volatile(
        "mma.sync.aligned.m16n8k16.row.col.f32.f16.f16.f32 "
        "{%0,%1,%2,%3}, {%4,%5,%6,%7}, {%8,%9}, {%0,%1,%2,%3};"
        : "+f"(c[0]), "+f"(c[1]), "+f"(c[2]), "+f"(c[3])
        : "r"(a[0]), "r"(a[1]), "r"(a[2]), "r"(a[3]), "r"(b[0]), "r"(b[1]));
}
__device__ __forceinline__ void ldm_x4(uint32_t d[4], uint32_t saddr) {
    asm volatile("ldmatrix.sync.aligned.m8n8.x4.shared.b16 {%0,%1,%2,%3}, [%4];"
        : "=r"(d[0]), "=r"(d[1]), "=r"(d[2]), "=r"(d[3]) : "r"(saddr));
}
// split two floats into packed bf16x2 (hi) and packed bf16x2 residual (lo)
__device__ __forceinline__ void splitbf(float x0, float x1, uint32_t& hi, uint32_t& lo) {
    __nv_bfloat162 hp = __floats2bfloat162_rn(x0, x1);
    float r0 = x0 - __bfloat162float(hp.x);
    float r1 = x1 - __bfloat162float(hp.y);
    __nv_bfloat162 lp = __floats2bfloat162_rn(r0, r1);
    hi = *reinterpret_cast<uint32_t*>(&hp);
    lo = *reinterpret_cast<uint32_t*>(&lp);
}
__device__ __forceinline__ uint32_t packf16(float x0, float x1) {
    __half2 hp = __floats2half2_rn(x0, x1);
    return *reinterpret_cast<uint32_t*>(&hp);
}
// 16B-granule XOR swizzle (u32 units), row length rowu
__device__ __forceinline__ int xsw(int r, int p, int rowu) {
    return r*rowu + ((((p >> 2) ^ (r & 7)) << 2) | (p & 3));
}

// ---------------------------------------------------------------------------
// fp32 -> packed fp16x2 plane. One thread per float4.
// ---------------------------------------------------------------------------
__global__ __launch_bounds__(256) void split_plane_f16(
    const float* __restrict__ src, uint32_t* __restrict__ pf)
{
    const size_t i = (size_t)blockIdx.x * 256 + threadIdx.x;
    const float4 v = *(const float4*)(src + i*4);
    pf[2*i]     = packf16(v.x, v.y);
    pf[2*i + 1] = packf16(v.z, v.w);
}

#define GKU 32                 // u32 per row per k-tile
#define GBUF (128*GKU*2)       // A + B per buffer = 8192 u32 (32 KB)

// ---------------------------------------------------------------------------
// QKV GEMM with FUSED epilogue: RoPE + RMSNorm + bf16 split for q/k heads,
// fp16 pack + transpose for v heads. N-tile 128 == one (which, head).
// ---------------------------------------------------------------------------
__global__ __launch_bounds__(256, 2) void f16_gemm_qkv_fused(
    const uint32_t* __restrict__ A, const uint32_t* __restrict__ B,
    const float* __restrict__ bias,
    const float* __restrict__ rp, const float* __restrict__ qk_w)
{
    extern __shared__ uint32_t sm[];
    const uint32_t sbase = (uint32_t)__cvta_generic_to_shared(sm);
    const int Ku = DD/2;

    const int tid = threadIdx.x;
    const int bm0 = blockIdx.y * 128;
    const int bn0 = blockIdx.x * 128;
    const int warp = tid >> 5, lane = tid & 31;
    const int wm0 = (warp >> 2) * 64;
    const int wn0 = (warp & 3) * 32;
    const int qr = lane >> 2, qc = lane & 3;
    const int lt15 = lane & 15, lt7 = lane & 7;
    const int asel = lane >> 4;
    const int brow = lane >> 4;
    const int bsel = (lane >> 3) & 1;

    const int lr = tid >> 3;
    const int lg = tid & 7;
    const uint32_t* Agp = A + (size_t)(bm0 + lr) * Ku + lg*4;
    const uint32_t* Bgp = B + (size_t)(bn0 + lr) * Ku + lg*4;
    const size_t rstep = (size_t)32 * Ku;
    int dsts[4];
    #pragma unroll
    for (int rep = 0; rep < 4; rep++) {
        const int r = lr + rep*32;
        dsts[rep] = r*32 + ((lg ^ (r & 7)) << 2);
    }

    float acc[4][4][4];
    #pragma unroll
    for (int i = 0; i < 4; i++)
        #pragma unroll
        for (int j = 0; j < 4; j++)
            #pragma unroll
            for (int u = 0; u < 4; u++) acc[i][j][u] = 0.f;

    const int nk = Ku / GKU;

    #pragma unroll
    for (int rep = 0; rep < 4; rep++) {
        cpasync16u(sm + dsts[rep],             Agp + rep*rstep);
        cpasync16u(sm + 4096 + dsts[rep],      Bgp + rep*rstep);
    }
    asm volatile("cp.async.commit_group;\n");

    for (int kt = 0; kt < nk; kt++) {
        if (kt + 1 < nk) {
            uint32_t* Bn = sm + ((kt + 1) & 1) * GBUF;
            const int ko = (kt + 1) * GKU;
            #pragma unroll
            for (int rep = 0; rep < 4; rep++) {
                cpasync16u(Bn + dsts[rep],        Agp + ko + rep*rstep);
                cpasync16u(Bn + 4096 + dsts[rep], Bgp + ko + rep*rstep);
            }
            asm volatile("cp.async.commit_group;\n");
            asm volatile("cp.async.wait_group 1;\n");
        } else {
            asm volatile("cp.async.wait_group 0;\n");
        }
        __syncthreads();

        const uint32_t abuf = sbase + ((kt & 1) * GBUF) * 4;
        const uint32_t bbuf = abuf + 4096 * 4;

        #pragma unroll
        for (int ch = 0; ch < 4; ch++) {
            uint32_t af[4][4];
            #pragma unroll
            for (int im = 0; im < 4; im++) {
                const int row = wm0 + im*16 + lt15;
                const int gr  = 2*ch + asel;
                ldm_x4(af[im], abuf + 4*(row*32 + ((gr ^ (row & 7)) << 2)));
            }
            uint32_t bf[2][4];
            #pragma unroll
            for (int ip = 0; ip < 2; ip++) {
                const int nrow = wn0 + (ip*2 + brow)*8 + lt7;
                const int gr = 2*ch + bsel;
                ldm_x4(bf[ip], bbuf + 4*(nrow*32 + ((gr ^ (nrow & 7)) << 2)));
            }
            #pragma unroll
            for (int in = 0; in < 4; in++) {
                uint32_t bb[2] = { bf[in>>1][(in&1)*2], bf[in>>1][(in&1)*2 + 1] };
                #pragma unroll
                for (int im = 0; im < 4; im++)
                    mma_f16(acc[im][in], af[im], bb);
            }
        }
        __syncthreads();
    }

    // ------------------- fused epilogue -------------------
    const int which = bn0 >> 11;          // 0=q, 1=k, 2=v
    const int hh = (bn0 >> 7) & 15;
    const int bb2 = bm0 >> 11;
    const int s0 = bm0 & (SS - 1);

    if (which < 2) {
        float* buf = (float*)sm;          // [4][128] row sums
        float ssum[4][2];
        #pragma unroll
        for (int im = 0; im < 4; im++) {
            #pragma unroll
            for (int rr = 0; rr < 2; rr++) {
                const int rl = wm0 + im*16 + qr + rr*8;
                const int s = s0 + rl;
                float a2 = 0.f;
                #pragma unroll
                for (int in = 0; in < 4; in++) {
                    const int c0 = wn0 + in*8 + qc*2;
                    const float ang = rp[s*(DH/2) + (c0 >> 1)];
                    const float cs = cosf(ang), sn = sinf(ang);
                    const float x0 = acc[im][in][rr*2+0] + bias[bn0 + c0];
                    const float x1 = acc[im][in][rr*2+1] + bias[bn0 + c0 + 1];
                    const float y0 = x0*cs - x1*sn;
                    const float y1 = x0*sn + x1*cs;
                    acc[im][in][rr*2+0] = y0;
                    acc[im][in][rr*2+1] = y1;
                    a2 += y0*y0 + y1*y1;
                }
                ssum[im][rr] = a2;
            }
        }
        #pragma unroll
        for (int im = 0; im < 4; im++)
            #pragma unroll
            for (int rr = 0; rr < 2; rr++) {
                float v = ssum[im][rr];
                v += __shfl_xor_sync(0xffffffffu, v, 1);
                v += __shfl_xor_sync(0xffffffffu, v, 2);
                ssum[im][rr] = v;
            }
        const int wn_idx = warp & 3;
        if (qc == 0) {
            #pragma unroll
            for (int im = 0; im < 4; im++)
                #pragma unroll
                for (int rr = 0; rr < 2; rr++)
                    buf[wn_idx*128 + wm0 + im*16 + qr + rr*8] = ssum[im][rr];
        }
        __syncthreads();

        uint32_t* ph = which ? g_kh : g_qh;
        uint32_t* pl = which ? g_kl : g_ql;
        const size_t pbase = (size_t)(bb2*HH + hh) * SS * 64;
        #pragma unroll
        for (int im = 0; im < 4; im++) {
            #pragma unroll
            for (int rr = 0; rr < 2; rr++) {
                const int rl = wm0 + im*16 + qr + rr*8;
                const float tot = buf[rl] + buf[128 + rl] + buf[256 + rl] + buf[384 + rl];
                const float inv = rsqrtf(tot * (1.0f/DH) + EPS);
                const size_t rowb = pbase + (size_t)(s0 + rl) * 64;
                #pragma unroll
                for (int in = 0; in < 4; in++) {
                    const int c0 = wn0 + in*8 + qc*2;
                    const float o0 = acc[im][in][rr*2+0] * inv * qk_w[c0];
                    const float o1 = acc[im][in][rr*2+1] * inv * qk_w[c0+1];
                    uint32_t hi, lo;
                    splitbf(o0, o1, hi, lo);
                    ph[rowb + (c0 >> 1)] = hi;
                    pl[rowb + (c0 >> 1)] = lo;
                }
            }
        }
    } else {
        __half* vh = (__half*)g_vf;
        const size_t vb = (size_t)(bb2*HH + hh) * DH * SS;
        #pragma unroll
        for (int im = 0; im < 4; im++) {
            #pragma unroll
            for (int in = 0; in < 4; in++) {
                const int c0 = wn0 + in*8 + qc*2;
                #pragma unroll
                for (int rr = 0; rr < 2; rr++) {
                    const int s = s0 + wm0 + im*16 + qr + rr*8;
                    const float o0 = acc[im][in][rr*2+0] + bias[bn0 + c0];
                    const float o1 = acc[im][in][rr*2+1] + bias[bn0 + c0 + 1];
                    vh[vb + (size_t)c0*SS + s]       = __float2half_rn(o0);
                    vh[vb + (size_t)(c0+1)*SS + s]   = __float2half_rn(o1);
                }
            }
        }
    }
}

// ---------------------------------------------------------------------------
// Plain single-product fp16 GEMM (out-projection): C = A @ W^T + bias.
// ---------------------------------------------------------------------------
__global__ __launch_bounds__(256, 2) void f16_gemm_nt_bias(
    const uint32_t* __restrict__ A, const uint32_t* __restrict__ B,
    const float* __restrict__ bias, float* __restrict__ C,
    int M, int N, int Ku)
{
    extern __shared__ uint32_t sm[];
    const uint32_t sbase = (uint32_t)__cvta_generic_to_shared(sm);

    const int tid = threadIdx.x;
    const int bm0 = blockIdx.y * 128;
    const int bn0 = blockIdx.x * 128;
    const int warp = tid >> 5, lane = tid & 31;
    const int wm0 = (warp >> 2) * 64;
    const int wn0 = (warp & 3) * 32;
    const int qr = lane >> 2, qc = lane & 3;
    const int lt15 = lane & 15, lt7 = lane & 7;
    const int asel = lane >> 4;
    const int brow = lane >> 4;
    const int bsel = (lane >> 3) & 1;

    const int lr = tid >> 3;
    const int lg = tid & 7;
    const uint32_t* Agp = A + (size_t)(bm0 + lr) * Ku + lg*4;
    const uint32_t* Bgp = B + (size_t)(bn0 + lr) * Ku + lg*4;
    const size_t rstep = (size_t)32 * Ku;
    int dsts[4];
    #pragma unroll
    for (int rep = 0; rep < 4; rep++) {
        const int r = lr + rep*32;
        dsts[rep] = r*32 + ((lg ^ (r & 7)) << 2);
    }

    float acc[4][4][4];
    #pragma unroll
    for (int i = 0; i < 4; i++)
        #pragma unroll
        for (int j = 0; j < 4; j++)
            #pragma unroll
            for (int u = 0; u < 4; u++) acc[i][j][u] = 0.f;

    const int nk = Ku / GKU;

    #pragma unroll
    for (int rep = 0; rep < 4; rep++) {
        cpasync16u(sm + dsts[rep],             Agp + rep*rstep);
        cpasync16u(sm + 4096 + dsts[rep],      Bgp + rep*rstep);
    }
    asm volatile("cp.async.commit_group;\n");

    for (int kt = 0; kt < nk; kt++) {
        if (kt + 1 < nk) {
            uint32_t* Bn = sm + ((kt + 1) & 1) * GBUF;
            const int ko = (kt + 1) * GKU;
            #pragma unroll
            for (int rep = 0; rep < 4; rep++) {
                cpasync16u(Bn + dsts[rep],        Agp + ko + rep*rstep);
                cpasync16u(Bn + 4096 + dsts[rep], Bgp + ko + rep*rstep);
            }
            asm volatile("cp.async.commit_group;\n");
            asm volatile("cp.async.wait_group 1;\n");
        } else {
            asm volatile("cp.async.wait_group 0;\n");
        }
        __syncthreads();

        const uint32_t abuf = sbase + ((kt & 1) * GBUF) * 4;
        const uint32_t bbuf = abuf + 4096 * 4;

        #pragma unroll
        for (int ch = 0; ch < 4; ch++) {
            uint32_t af[4][4];
            #pragma unroll
            for (int im = 0; im < 4; im++) {
                const int row = wm0 + im*16 + lt15;
                const int gr  = 2*ch + asel;
                ldm_x4(af[im], abuf + 4*(row*32 + ((gr ^ (row & 7)) << 2)));
            }
            uint32_t bf[2][4];
            #pragma unroll
            for (int ip = 0; ip < 2; ip++) {
                const int nrow = wn0 + (ip*2 + brow)*8 + lt7;
                const int gr = 2*ch + bsel;
                ldm_x4(bf[ip], bbuf + 4*(nrow*32 + ((gr ^ (nrow & 7)) << 2)));
            }
            #pragma unroll
            for (int in = 0; in < 4; in++) {
                uint32_t bb[2] = { bf[in>>1][(in&1)*2], bf[in>>1][(in&1)*2 + 1] };
                #pragma unroll
                for (int im = 0; im < 4; im++)
                    mma_f16(acc[im][in], af[im], bb);
            }
        }
        __syncthreads();
    }

    #pragma unroll
    for (int im = 0; im < 4; im++) {
        #pragma unroll
        for (int in = 0; in < 4; in++) {
            const int r0 = bm0 + wm0 + im*16 + qr;
            const int c0 = bn0 + wn0 + in*8 + qc*2;
            const float2 b2 = *(const float2*)(bias + c0);
            float2 v;
            v.x = acc[im][in][0] + b2.x; v.y = acc[im][in][1] + b2.y;
            *(float2*)(C + (size_t)r0 * N + c0) = v;
            v.x = acc[im][in][2] + b2.x; v.y = acc[im][in][3] + b2.y;
            *(float2*)(C + (size_t)(r0 + 8) * N + c0) = v;
        }
    }
}

// ---------------------------------------------------------------------------
// Flash attention v4: S = bf16 3-product (ldmatrix), PV = fp16 1-product.
// ---------------------------------------------------------------------------
#define AQH 0
#define AQL 4096
#define AKH 8192
#define AKL 12288
#define AVH 16384               // 4096 u32 (128 d x 32)
#define APH 20480               // 2048 u32 (64 rows x 32)
#define ALRED 22528
#define ASZ ((22528 + 128) * 4) // 90624 B
#define SHIFTC 11.32f

__global__ __launch_bounds__(256, 2) void flash_attn_v2()
{
    extern __shared__ uint32_t smu[];
    float* smf = reinterpret_cast<float*>(smu);
    const uint32_t sb = (uint32_t)__cvta_generic_to_shared(smu);

    const int qb = (int)(gridDim.x - 1 - blockIdx.x);
    const int qm0 = qb * 64;
    const int h = blockIdx.y, b = blockIdx.z;
    const int tid = threadIdx.x;
    const int warp = tid >> 5, lane = tid & 31;
    const int qr = lane >> 2, qc = lane & 3;
    const int half = warp & 1;
    const int wrow = (warp >> 1) * 16;
    const int lt15 = lane & 15, lt7 = lane & 7;
    const int asel = lane >> 4;
    const int brow = lane >> 4;
    const int bsel = (lane >> 3) & 1;

    const size_t qkbase = (size_t)(b*HH + h) * SS * 64;
    const size_t vbase  = (size_t)(b*HH + h) * DH * (SS/2);
    const float scale = 0.08838834764831845f;

    #pragma unroll
    for (int rep = 0; rep < 4; rep++) {
        const int idx = rep*256 + tid;
        const int r = idx >> 4, g = idx & 15;
        const int dst = r*64 + ((g ^ (r & 7)) << 2);
        const size_t qsrc = qkbase + (size_t)(qm0 + r)*64 + g*4;
        const size_t ksrc = qkbase + (size_t)r*64 + g*4;
        cpasync16u(smu + AQH + dst, g_qh + qsrc);
        cpasync16u(smu + AQL + dst, g_ql + qsrc);
        cpasync16u(smu + AKH + dst, g_kh + ksrc);
        cpasync16u(smu + AKL + dst, g_kl + ksrc);
    }
    asm volatile("cp.async.commit_group;\n");
    asm volatile("cp.async.wait_group 0;\n");
    __syncthreads();

    float lsum0 = 0.f, lsum1 = 0.f;
    float O[8][4];
    #pragma unroll
    for (int n = 0; n < 8; n++)
        #pragma unroll
        for (int u = 0; u < 4; u++) O[n][u] = 0.f;

    const int nt = qb + 1;

    for (int t = 0; t < nt; t++) {
        const int kn0 = t * 64;
        if (t > 0) __syncthreads();

        #pragma unroll
        for (int rep = 0; rep < 4; rep++) {
            const int idx = rep*256 + tid;
            const int d = idx >> 3, g = idx & 7;
            const int dst = d*32 + ((g ^ (d & 7)) << 2);
            const size_t src = vbase + (size_t)d*(SS/2) + (kn0 >> 1) + g*4;
            cpasync16u(smu + AVH + dst, g_vf + src);
        }
        asm volatile("cp.async.commit_group;\n");

        asm volatile("cp.async.wait_group 1;\n");
        __syncthreads();

        float Sf[4][4];
        #pragma unroll
        for (int n = 0; n < 4; n++)
            #pragma unroll
            for (int u = 0; u < 4; u++) Sf[n][u] = 0.f;

        #pragma unroll
        for (int ch = 0; ch < 8; ch++) {
            uint32_t ah[4], al[4];
            {
                const int row = wrow + lt15;
                const int gr = 2*ch + asel;
                const uint32_t off = 4*(row*64 + ((gr ^ (row & 7)) << 2));
                ldm_x4(ah, sb + AQH*4 + off);
                ldm_x4(al, sb + AQL*4 + off);
            }
            uint32_t kh[2][4], kl[2][4];
            #pragma unroll
            for (int ip = 0; ip < 2; ip++) {
                const int kr = (half*4 + ip*2 + brow)*8 + lt7;
                const int gr = 2*ch + bsel;
                const uint32_t off = 4*(kr*64 + ((gr ^ (kr & 7)) << 2));
                ldm_x4(kh[ip], sb + AKH*4 + off);
                ldm_x4(kl[ip], sb + AKL*4 + off);
            }
            #pragma unroll
            for (int nf = 0; nf < 4; nf++) {
                uint32_t bh[2] = { kh[nf>>1][(nf&1)*2], kh[nf>>1][(nf&1)*2 + 1] };
                uint32_t bl[2] = { kl[nf>>1][(nf&1)*2], kl[nf>>1][(nf&1)*2 + 1] };
                mma_bf16(Sf[nf], ah, bh);
                mma_bf16(Sf[nf], al, bh);
                mma_bf16(Sf[nf], ah, bl);
            }
        }

        const bool maskt = (t == nt - 1);
        const int row0 = qm0 + wrow + qr, row1 = row0 + 8;
        #pragma unroll
        for (int nf = 0; nf < 4; nf++) {
            const int key0 = kn0 + (half*4 + nf)*8 + 2*qc;
            float p00 = __expf(fmaf(Sf[nf][0], scale, -SHIFTC));
            float p01 = __expf(fmaf(Sf[nf][1], scale, -SHIFTC));
            float p10 = __expf(fmaf(Sf[nf][2], scale, -SHIFTC));
            float p11 = __expf(fmaf(Sf[nf][3], scale, -SHIFTC));
            if (maskt) {
                if (key0     > row0) p00 = 0.f;
                if (key0 + 1 > row0) p01 = 0.f;
                if (key0     > row1) p10 = 0.f;
                if (key0 + 1 > row1) p11 = 0.f;
            }
            lsum0 += p00 + p01;
            lsum1 += p10 + p11;
            const int pp = (half*4 + nf)*4 + qc;
            smu[APH + xsw(wrow + qr, pp, 32)]     = packf16(p00, p01);
            smu[APH + xsw(wrow + qr + 8, pp, 32)] = packf16(p10, p11);
        }

        asm volatile("cp.async.wait_group 0;\n");
        __syncthreads();

        if (t + 1 < nt) {
            #pragma unroll
            for (int rep = 0; rep < 4; rep++) {
                const int idx = rep*256 + tid;
                const int r = idx >> 4, g = idx & 15;
                const int dst = r*64 + ((g ^ (r & 7)) << 2);
                const size_t src = qkbase + (size_t)(kn0 + 64 + r)*64 + g*4;
                cpasync16u(smu + AKH + dst, g_kh + src);
                cpasync16u(smu + AKL + dst, g_kl + src);
            }
            asm volatile("cp.async.commit_group;\n");
        }

        #pragma unroll
        for (int ch = 0; ch < 4; ch++) {
            uint32_t ah[4];
            {
                const int row = wrow + lt15;
                const int gr = 2*ch + asel;
                ldm_x4(ah, sb + APH*4 + 4*(row*32 + ((gr ^ (row & 7)) << 2)));
            }
            uint32_t vh[4][4];
            #pragma unroll
            for (int ip = 0; ip < 4; ip++) {
                const int dr = (half*8 + ip*2 + brow)*8 + lt7;
                const int gr = 2*ch + bsel;
                ldm_x4(vh[ip], sb + AVH*4 + 4*(dr*32 + ((gr ^ (dr & 7)) << 2)));
            }
            #pragma unroll
            for (int nf = 0; nf < 8; nf++) {
                uint32_t bb[2] = { vh[nf>>1][(nf&1)*2], vh[nf>>1][(nf&1)*2 + 1] };
                mma_f16(O[nf], ah, bb);
            }
        }
    }

    lsum0 += __shfl_xor_sync(0xffffffffu, lsum0, 1);
    lsum0 += __shfl_xor_sync(0xffffffffu, lsum0, 2);
    lsum1 += __shfl_xor_sync(0xffffffffu, lsum1, 1);
    lsum1 += __shfl_xor_sync(0xffffffffu, lsum1, 2);
    __syncthreads();
    if (qc == 0) {
        smf[ALRED + half*64 + wrow + qr]     = lsum0;
        smf[ALRED + half*64 + wrow + qr + 8] = lsum1;
    }
    __syncthreads();
    const float il0 = 1.0f / (smf[ALRED + wrow + qr] + smf[ALRED + 64 + wrow + qr]);
    const float il1 = 1.0f / (smf[ALRED + wrow + qr + 8] + smf[ALRED + 64 + wrow + qr + 8]);

    const size_t gr0 = (size_t)(b*SS + qm0 + wrow + qr);
    #pragma unroll
    for (int nf = 0; nf < 8; nf++) {
        const int col = h*DH + (half*8 + nf)*8 + 2*qc;
        *(float2*)(g_attn + gr0 * DD + col) =
            make_float2(O[nf][0]*il0, O[nf][1]*il0);
        *(float2*)(g_attn + (gr0 + 8) * DD + col) =
            make_float2(O[nf][2]*il1, O[nf][3]*il1);
    }
}

// ---------------------------------------------------------------------------
// RMSNorm over D=2048 + pack to fp16 plane. One block per row.
// ---------------------------------------------------------------------------
__global__ __launch_bounds__(256) void rmsnorm_pack_rows(const float* __restrict__ w)
{
    __shared__ float red[8];
    __shared__ float s_inv;
    const float* p = g_attn + (size_t)blockIdx.x * DD;
    const int tid = threadIdx.x;
    const int base = tid * 8;

    float v[8];
    {
        const float4 a = *(const float4*)(p + base);
        const float4 b = *(const float4*)(p + base + 4);
        v[0]=a.x; v[1]=a.y; v[2]=a.z; v[3]=a.w;
        v[4]=b.x; v[5]=b.y; v[6]=b.z; v[7]=b.w;
    }
    float ss = 0.f;
    #pragma unroll
    for (int k = 0; k < 8; k++) ss += v[k]*v[k];
    #pragma unroll
    for (int o = 16; o > 0; o >>= 1) ss += __shfl_xor_sync(0xffffffffu, ss, o);
    if ((tid & 31) == 0) red[tid >> 5] = ss;
    __syncthreads();
    if (tid == 0) {
        float t = 0.f;
        #pragma unroll
        for (int i = 0; i < 8; i++) t += red[i];
        s_inv = rsqrtf(t * (1.0f / DD) + EPS);
    }
    __syncthreads();
    const float inv = s_inv;
    const size_t ob = (size_t)blockIdx.x * (DD/2) + base/2;
    #pragma unroll
    for (int u = 0; u < 4; u++) {
        const float x0 = v[2*u]   * inv * w[base + 2*u];
        const float x1 = v[2*u+1] * inv * w[base + 2*u + 1];
        g_af[ob + u] = packf16(x0, x1);
    }
}

// ---------------------------------------------------------------------------
extern "C" void kernel_launch(void* const* d_in, const int* in_sizes, int n_in,
                              void* d_out, int out_size)
{
    const float* x     = (const float*)d_in[0];
    const float* rp    = (const float*)d_in[1];
    const float* Win   = (const float*)d_in[2];
    const float* b_in  = (const float*)d_in[3];
    const float* Wout  = (const float*)d_in[4];
    const float* b_out = (const float*)d_in[5];
    const float* qk_w  = (const float*)d_in[6];
    const float* out_w = (const float*)d_in[7];
    float* out = (float*)d_out;

    uint32_t *xf, *wif, *wof, *af;
    cudaGetSymbolAddress((void**)&xf,  g_xf);
    cudaGetSymbolAddress((void**)&wif, g_wif);
    cudaGetSymbolAddress((void**)&wof, g_wof);
    cudaGetSymbolAddress((void**)&af,  g_af);

    const int gemm_smem = 2 * GBUF * (int)sizeof(uint32_t);   // 65536 B
    cudaFuncSetAttribute(f16_gemm_qkv_fused,
                         cudaFuncAttributeMaxDynamicSharedMemorySize, gemm_smem);
    cudaFuncSetAttribute(f16_gemm_nt_bias,
                         cudaFuncAttributeMaxDynamicSharedMemorySize, gemm_smem);
    cudaFuncSetAttribute(flash_attn_v2,
                         cudaFuncAttributeMaxDynamicSharedMemorySize, ASZ);

    // 0) pack inputs to fp16 planes
    split_plane_f16<<<(MM*DD)/1024, 256>>>(x, xf);
    split_plane_f16<<<(TRIO*DD)/1024, 256>>>(Win, wif);
    split_plane_f16<<<(DD*DD)/1024, 256>>>(Wout, wof);

    // 1) fused: qkv = x @ Win^T + b_in, then rope+rms+split (q,k) / pack (v)
    {
        dim3 grid(TRIO / 128, MM / 128);
        f16_gemm_qkv_fused<<<grid, 256, gemm_smem>>>(xf, wif, b_in, rp, qk_w);
    }
    // 2) flash attention -> g_attn
    {
        dim3 grid(SS / 64, HH, BB);
        flash_attn_v2<<<grid, 256, ASZ>>>();
    }
    // 3) RMSNorm + pack -> g_af
    rmsnorm_pack_rows<<<MM, 256>>>(out_w);
    // 4) out = attn @ Wout^T + b_out
    {
        dim3 grid(DD / 128, MM / 128);
        f16_gemm_nt_bias<<<grid, 256, gemm_smem>>>(
            af, wof, b_out, out, MM, DD, DD/2);
    }
}